// round 1
// baseline (speedup 1.0000x reference)
#include <cuda_runtime.h>
#include <math.h>

#define NATOMS 16384
#define NMOL   512
#define HDIM   128
#define GDIM   50
#define LINT   3
#define CUTOFF 6.0f

// Scratch (allocation-free): 4 x 8MB
__device__ float g_h  [NATOMS * HDIM];
__device__ float g_hx [NATOMS * HDIM];
__device__ float g_agg[NATOMS * HDIM];
__device__ float g_tmp[NATOMS * HDIM];

__device__ __forceinline__ float sspf(float x) {
    // shifted softplus: log(1+exp(x)) - log(2)
    const float LN2 = 0.6931471805599453f;
    if (x > 20.f) return x - LN2;
    return __logf(1.f + __expf(x)) - LN2;
}

// ---------------------------------------------------------------------------
// h[i] = emb[z[i]]
// ---------------------------------------------------------------------------
__global__ void k_embed(const int* __restrict__ z, const float* __restrict__ emb) {
    int i = blockIdx.x * blockDim.x + threadIdx.x;
    if (i < NATOMS * HDIM) {
        int a = i >> 7, f = i & 127;
        g_h[i] = emb[z[a] * HDIM + f];
    }
}

__global__ void k_zero_agg() {
    int i = blockIdx.x * blockDim.x + threadIdx.x;
    if (i < NATOMS * HDIM) g_agg[i] = 0.f;
}

__global__ void k_zero_out(float* out) {
    int i = blockIdx.x * blockDim.x + threadIdx.x;
    if (i < NMOL) out[i] = 0.f;
}

// ---------------------------------------------------------------------------
// Generic 128x128 node GEMM: y(row,:) = [ADDTO? y +] act(x(row,:) @ W + b)
// Warp-per-row, W resident in SMEM (64KB dynamic), x row staged in SMEM.
// ---------------------------------------------------------------------------
template<bool ACT, bool ADDTO>
__global__ __launch_bounds__(256) void k_gemm128(
    const float* __restrict__ x, const float* __restrict__ W,
    const float* __restrict__ b, float* __restrict__ y, int nrows)
{
    extern __shared__ float sm[];
    float* Ws = sm;            // 128*128
    float* xs = sm + 16384;    // 8*128

    int tid = threadIdx.x;
    for (int i = tid; i < 16384; i += 256) Ws[i] = W[i];
    __syncthreads();

    int warp = tid >> 5, lane = tid & 31, f0 = lane * 4;
    float b0 = b ? b[f0]     : 0.f;
    float b1 = b ? b[f0 + 1] : 0.f;
    float b2 = b ? b[f0 + 2] : 0.f;
    float b3 = b ? b[f0 + 3] : 0.f;
    float* xrow = xs + warp * 128;

    for (int row = blockIdx.x * 8 + warp; row < nrows; row += gridDim.x * 8) {
        ((float4*)xrow)[lane] = ((const float4*)(x + (long)row * 128))[lane];
        __syncwarp();
        float a0 = b0, a1 = b1, a2 = b2, a3 = b3;
        #pragma unroll 8
        for (int k = 0; k < 128; k++) {
            float xv = xrow[k];
            float4 wv = ((const float4*)(Ws + k * 128))[lane];
            a0 += xv * wv.x; a1 += xv * wv.y; a2 += xv * wv.z; a3 += xv * wv.w;
        }
        if (ACT) { a0 = sspf(a0); a1 = sspf(a1); a2 = sspf(a2); a3 = sspf(a3); }
        float4 o = make_float4(a0, a1, a2, a3);
        float4* yp = (float4*)(y + (long)row * 128) + lane;
        if (ADDTO) { float4 p = *yp; o.x += p.x; o.y += p.y; o.z += p.z; o.w += p.w; }
        *yp = o;
        __syncwarp();
    }
}

// ---------------------------------------------------------------------------
// Edge kernel: for each edge e
//   d   = |pos[src]-pos[dst]|
//   ea  = exp(coeff*(d - offs)^2)            [50]
//   t1  = ssp(ea @ w1 + b1)                  [128]
//   w   = (t1 @ w2 + b2) * 0.5*(cos(pi d/6)+1)
//   agg[dst] += hx[src] * w                  (atomicAdd)
// Warp processes ET=4 edges at a time to amortize SMEM weight loads.
// ---------------------------------------------------------------------------
#define EW 16   // warps per block
#define ET 4    // edges per warp per iteration

__global__ __launch_bounds__(EW * 32) void k_edge(
    const float* __restrict__ pos, const int* __restrict__ src, const int* __restrict__ dst,
    const float* __restrict__ w1, const float* __restrict__ b1,
    const float* __restrict__ w2, const float* __restrict__ b2, int E)
{
    extern __shared__ float sm[];
    float* w1s = sm;                         // 50*128   = 6400
    float* w2s = sm + GDIM * HDIM;           // 128*128  = 16384
    float* wsc = w2s + HDIM * HDIM;          // per-warp scratch: ET*52 + ET*128 = 720

    int tid = threadIdx.x;
    for (int i = tid; i < GDIM * HDIM; i += EW * 32) w1s[i] = w1[i];
    for (int i = tid; i < HDIM * HDIM; i += EW * 32) w2s[i] = w2[i];
    __syncthreads();

    int warp = tid >> 5, lane = tid & 31, f0 = lane * 4;
    float* ea = wsc + warp * 720;            // [ET][52]
    float* t1 = ea + ET * 52;                // [ET][128]

    float bb1x = b1[f0], bb1y = b1[f0+1], bb1z = b1[f0+2], bb1w = b1[f0+3];
    float bb2x = b2[f0], bb2y = b2[f0+1], bb2z = b2[f0+2], bb2w = b2[f0+3];

    const float step  = CUTOFF / (GDIM - 1);
    const float coeff = -0.5f / (step * step);
    const float PIOC  = 3.14159265358979f / CUTOFF;

    for (long base = (long)(blockIdx.x * EW + warp) * ET; base < E;
         base += (long)gridDim.x * EW * ET)
    {
        int  sidx[ET], tidx[ET];
        float dd[ET];
        bool  val[ET];
        #pragma unroll
        for (int j = 0; j < ET; j++) {
            long e = base + j;
            val[j] = (e < E);
            int ee = val[j] ? (int)e : 0;
            sidx[j] = src[ee]; tidx[j] = dst[ee];
            float dx = pos[3*sidx[j]]   - pos[3*tidx[j]];
            float dy = pos[3*sidx[j]+1] - pos[3*tidx[j]+1];
            float dz = pos[3*sidx[j]+2] - pos[3*tidx[j]+2];
            dd[j] = sqrtf(dx*dx + dy*dy + dz*dz);
            for (int g = lane; g < GDIM; g += 32) {
                float u = dd[j] - g * step;
                ea[j*52 + g] = __expf(coeff * u * u);
            }
        }
        __syncwarp();

        // GEMM1: [ET,50] x [50,128]
        float a[ET][4];
        #pragma unroll
        for (int j = 0; j < ET; j++) { a[j][0]=bb1x; a[j][1]=bb1y; a[j][2]=bb1z; a[j][3]=bb1w; }
        for (int g = 0; g < GDIM; g++) {
            float4 wv = *((const float4*)(w1s + g * HDIM) + lane);
            #pragma unroll
            for (int j = 0; j < ET; j++) {
                float xv = ea[j*52 + g];
                a[j][0] += xv * wv.x; a[j][1] += xv * wv.y;
                a[j][2] += xv * wv.z; a[j][3] += xv * wv.w;
            }
        }
        #pragma unroll
        for (int j = 0; j < ET; j++) {
            ((float4*)(t1 + j*128))[lane] =
                make_float4(sspf(a[j][0]), sspf(a[j][1]), sspf(a[j][2]), sspf(a[j][3]));
        }
        __syncwarp();

        // GEMM2: [ET,128] x [128,128]
        float c[ET][4];
        #pragma unroll
        for (int j = 0; j < ET; j++) { c[j][0]=bb2x; c[j][1]=bb2y; c[j][2]=bb2z; c[j][3]=bb2w; }
        #pragma unroll 4
        for (int k = 0; k < HDIM; k++) {
            float4 wv = *((const float4*)(w2s + k * HDIM) + lane);
            #pragma unroll
            for (int j = 0; j < ET; j++) {
                float xv = t1[j*128 + k];
                c[j][0] += xv * wv.x; c[j][1] += xv * wv.y;
                c[j][2] += xv * wv.z; c[j][3] += xv * wv.w;
            }
        }

        #pragma unroll
        for (int j = 0; j < ET; j++) {
            if (!val[j]) continue;
            float cc = 0.5f * (cosf(dd[j] * PIOC) + 1.f);
            float4 hxv = *((const float4*)(g_hx + (long)sidx[j] * HDIM) + lane);
            float* ap = g_agg + (long)tidx[j] * HDIM + f0;
            atomicAdd(ap + 0, c[j][0] * cc * hxv.x);
            atomicAdd(ap + 1, c[j][1] * cc * hxv.y);
            atomicAdd(ap + 2, c[j][2] * cc * hxv.z);
            atomicAdd(ap + 3, c[j][3] * cc * hxv.w);
        }
        __syncwarp();
    }
}

// ---------------------------------------------------------------------------
// Output head: per atom  v = ssp(h @ out1_w + out1_b) @ out2_w + out2_b
// then atomicAdd into out[batch[atom]].
// ---------------------------------------------------------------------------
__global__ __launch_bounds__(256) void k_out(
    const float* __restrict__ out1_w, const float* __restrict__ out1_b,
    const float* __restrict__ out2_w, const float* __restrict__ out2_b,
    const int* __restrict__ batch, float* __restrict__ out)
{
    __shared__ float W1[128 * 64];
    __shared__ float w2s[64];
    __shared__ float xs[8][128];

    int tid = threadIdx.x;
    for (int i = tid; i < 128 * 64; i += 256) W1[i] = out1_w[i];
    if (tid < 64) w2s[tid] = out2_w[tid];
    __syncthreads();

    int warp = tid >> 5, lane = tid & 31;
    float ob0 = out1_b[lane], ob1 = out1_b[lane + 32];
    float b2v = out2_b[0];

    for (int row = blockIdx.x * 8 + warp; row < NATOMS; row += gridDim.x * 8) {
        ((float4*)xs[warp])[lane] = ((const float4*)(g_h + (long)row * 128))[lane];
        __syncwarp();
        float a0 = ob0, a1 = ob1;
        #pragma unroll 8
        for (int k = 0; k < 128; k++) {
            float xv = xs[warp][k];
            a0 += xv * W1[k * 64 + lane];
            a1 += xv * W1[k * 64 + lane + 32];
        }
        float v = sspf(a0) * w2s[lane] + sspf(a1) * w2s[lane + 32];
        #pragma unroll
        for (int off = 16; off; off >>= 1) v += __shfl_down_sync(0xffffffffu, v, off);
        if (lane == 0) atomicAdd(&out[batch[row]], v + b2v);
        __syncwarp();
    }
}

// ---------------------------------------------------------------------------
extern "C" void kernel_launch(void* const* d_in, const int* in_sizes, int n_in,
                              void* d_out, int out_size)
{
    const int*   z       = (const int*)  d_in[0];
    const float* pos     = (const float*)d_in[1];
    const int*   batch   = (const int*)  d_in[2];
    const int*   ei      = (const int*)  d_in[3];
    const float* emb     = (const float*)d_in[4];
    const float* mlp_w1  = (const float*)d_in[5];
    const float* mlp_b1  = (const float*)d_in[6];
    const float* mlp_w2  = (const float*)d_in[7];
    const float* mlp_b2  = (const float*)d_in[8];
    const float* cf1_w   = (const float*)d_in[9];
    const float* cf2_w   = (const float*)d_in[10];
    const float* cf2_b   = (const float*)d_in[11];
    const float* lin_w   = (const float*)d_in[12];
    const float* lin_b   = (const float*)d_in[13];
    const float* out1_w  = (const float*)d_in[14];
    const float* out1_b  = (const float*)d_in[15];
    const float* out2_w  = (const float*)d_in[16];
    const float* out2_b  = (const float*)d_in[17];

    int E = in_sizes[3] / 2;
    const int* src = ei;
    const int* dst = ei + E;

    const int EDGE_SMEM = (GDIM*HDIM + HDIM*HDIM + EW*720) * 4;   // 137216 B
    const int GEMM_SMEM = (16384 + 8*128) * 4;                    // 69632 B
    cudaFuncSetAttribute(k_edge, cudaFuncAttributeMaxDynamicSharedMemorySize, EDGE_SMEM);
    cudaFuncSetAttribute(k_gemm128<false,false>, cudaFuncAttributeMaxDynamicSharedMemorySize, GEMM_SMEM);
    cudaFuncSetAttribute(k_gemm128<true ,false>, cudaFuncAttributeMaxDynamicSharedMemorySize, GEMM_SMEM);
    cudaFuncSetAttribute(k_gemm128<false,true >, cudaFuncAttributeMaxDynamicSharedMemorySize, GEMM_SMEM);

    float *ph, *phx, *pagg, *ptmp;
    cudaGetSymbolAddress((void**)&ph,   g_h);
    cudaGetSymbolAddress((void**)&phx,  g_hx);
    cudaGetSymbolAddress((void**)&pagg, g_agg);
    cudaGetSymbolAddress((void**)&ptmp, g_tmp);

    float* out = (float*)d_out;

    k_embed<<<(NATOMS*HDIM + 255)/256, 256>>>(z, emb);

    for (int l = 0; l < LINT; l++) {
        // hx = h @ cf1_w[l]
        k_gemm128<false,false><<<456, 256, GEMM_SMEM>>>(
            ph, cf1_w + (long)l*HDIM*HDIM, nullptr, phx, NATOMS);
        // agg = 0
        k_zero_agg<<<(NATOMS*HDIM + 255)/256, 256>>>();
        // edge message passing
        k_edge<<<152, EW*32, EDGE_SMEM>>>(
            pos, src, dst,
            mlp_w1 + (long)l*GDIM*HDIM, mlp_b1 + (long)l*HDIM,
            mlp_w2 + (long)l*HDIM*HDIM, mlp_b2 + (long)l*HDIM, E);
        // tmp = ssp(agg @ cf2_w[l] + cf2_b[l])
        k_gemm128<true,false><<<456, 256, GEMM_SMEM>>>(
            pagg, cf2_w + (long)l*HDIM*HDIM, cf2_b + (long)l*HDIM, ptmp, NATOMS);
        // h += tmp @ lin_w[l] + lin_b[l]
        k_gemm128<false,true><<<456, 256, GEMM_SMEM>>>(
            ptmp, lin_w + (long)l*HDIM*HDIM, lin_b + (long)l*HDIM, ph, NATOMS);
    }

    k_zero_out<<<1, 512>>>(out);
    k_out<<<256, 256>>>(out1_w, out1_b, out2_w, out2_b, batch, out);
}

// round 2
// speedup vs baseline: 1.1732x; 1.1732x over previous
#include <cuda_runtime.h>
#include <math.h>

#define NATOMS 16384
#define NMOL   512
#define HDIM   128
#define GDIM   50
#define LINT   3
#define CUTOFF 6.0f

typedef unsigned long long ull;

// Scratch (allocation-free): 4 x 8MB
__device__ float g_h  [NATOMS * HDIM];
__device__ float g_hx [NATOMS * HDIM];
__device__ float g_agg[NATOMS * HDIM];
__device__ float g_tmp[NATOMS * HDIM];

__device__ __forceinline__ float sspf(float x) {
    const float LN2 = 0.6931471805599453f;
    if (x > 20.f) return x - LN2;
    return __logf(1.f + __expf(x)) - LN2;
}

// packed f32x2 fma (Blackwell FFMA2): per-element IEEE fma on 2 packed fp32
__device__ __forceinline__ ull ffma2(ull a, ull b, ull c) {
    ull d;
    asm("fma.rn.f32x2 %0, %1, %2, %3;" : "=l"(d) : "l"(a), "l"(b), "l"(c));
    return d;
}
__device__ __forceinline__ float fcomb(ull a) {   // lo + hi
    float lo = __int_as_float((int)(a & 0xffffffffULL));
    float hi = __int_as_float((int)(a >> 32));
    return lo + hi;
}

// ---------------------------------------------------------------------------
__global__ void k_embed(const int* __restrict__ z, const float* __restrict__ emb) {
    int i = blockIdx.x * blockDim.x + threadIdx.x;
    if (i < NATOMS * HDIM) {
        int a = i >> 7, f = i & 127;
        g_h[i] = emb[z[a] * HDIM + f];
    }
}
__global__ void k_zero_agg() {
    int i = blockIdx.x * blockDim.x + threadIdx.x;
    if (i < NATOMS * HDIM) g_agg[i] = 0.f;
}
__global__ void k_zero_out(float* out) {
    int i = blockIdx.x * blockDim.x + threadIdx.x;
    if (i < NMOL) out[i] = 0.f;
}

// ---------------------------------------------------------------------------
// Node GEMM 128x128 via f32x2, 8 rows per warp, interleaved-pair weights.
// Lane owns columns {2*lane, 2*lane+1, 64+2*lane, 64+2*lane+1}.
// ---------------------------------------------------------------------------
template<bool ACT, bool ADDTO>
__global__ __launch_bounds__(256, 1) void k_gemmx(
    const float* __restrict__ x, const float* __restrict__ W,
    const float* __restrict__ b, float* __restrict__ y, int nrows)
{
    extern __shared__ float sm[];
    float* Wi = sm;            // 16384 floats, interleaved (k,k+1) pairs per column
    float* xs = sm + 16384;    // 8 warps * 8 rows * 128

    int tid = threadIdx.x;
    // Wi[(p*128 + c)*2 + {0,1}] = W[2p][c], W[2p+1][c]
    for (int i = tid; i < 64 * 128; i += 256) {
        int p = i >> 7, c = i & 127;
        Wi[2 * i]     = W[(2 * p) * 128 + c];
        Wi[2 * i + 1] = W[(2 * p + 1) * 128 + c];
    }
    __syncthreads();

    int warp = tid >> 5, lane = tid & 31;
    int cA = 2 * lane, cB = 64 + 2 * lane;
    float bA0 = b ? b[cA]     : 0.f;
    float bA1 = b ? b[cA + 1] : 0.f;
    float bB0 = b ? b[cB]     : 0.f;
    float bB1 = b ? b[cB + 1] : 0.f;
    float* xw = xs + warp * 1024;

    for (int base = blockIdx.x * 64 + warp * 8; base < nrows; base += gridDim.x * 64) {
        #pragma unroll
        for (int r = 0; r < 8; r++)
            ((float4*)(xw + r * 128))[lane] = ((const float4*)(x + (long)(base + r) * 128))[lane];
        __syncwarp();

        ull acc[8][4];
        #pragma unroll
        for (int r = 0; r < 8; r++) { acc[r][0]=0; acc[r][1]=0; acc[r][2]=0; acc[r][3]=0; }

        #pragma unroll 4
        for (int p = 0; p < 64; p++) {
            ulonglong2 wA = *(const ulonglong2*)(Wi + p * 256 + 4 * lane);
            ulonglong2 wB = *(const ulonglong2*)(Wi + p * 256 + 128 + 4 * lane);
            #pragma unroll
            for (int r = 0; r < 8; r++) {
                ull xv = *(const ull*)(xw + r * 128 + 2 * p);
                acc[r][0] = ffma2(xv, wA.x, acc[r][0]);
                acc[r][1] = ffma2(xv, wA.y, acc[r][1]);
                acc[r][2] = ffma2(xv, wB.x, acc[r][2]);
                acc[r][3] = ffma2(xv, wB.y, acc[r][3]);
            }
        }

        #pragma unroll
        for (int r = 0; r < 8; r++) {
            float v0 = fcomb(acc[r][0]) + bA0;
            float v1 = fcomb(acc[r][1]) + bA1;
            float v2 = fcomb(acc[r][2]) + bB0;
            float v3 = fcomb(acc[r][3]) + bB1;
            if (ACT) { v0 = sspf(v0); v1 = sspf(v1); v2 = sspf(v2); v3 = sspf(v3); }
            float* yp = y + (long)(base + r) * 128;
            if (ADDTO) {
                float2 pa = *(float2*)(yp + cA); v0 += pa.x; v1 += pa.y;
                float2 pb = *(float2*)(yp + cB); v2 += pb.x; v3 += pb.y;
            }
            *(float2*)(yp + cA) = make_float2(v0, v1);
            *(float2*)(yp + cB) = make_float2(v2, v3);
        }
        __syncwarp();
    }
}

// ---------------------------------------------------------------------------
// Edge kernel: filter MLP (f32x2, ET=8 edges/warp) + gather/scatter message.
// ---------------------------------------------------------------------------
#define EW 16   // warps per block
#define ET 8    // edges per warp per iteration

__global__ __launch_bounds__(EW * 32, 1) void k_edge(
    const float* __restrict__ pos, const int* __restrict__ src, const int* __restrict__ dst,
    const float* __restrict__ w1, const float* __restrict__ b1,
    const float* __restrict__ w2, const float* __restrict__ b2, int E)
{
    extern __shared__ float sm[];
    float* w1i = sm;                     // 25 pairs * 128 * 2 = 6400
    float* w2i = sm + 6400;              // 64 pairs * 128 * 2 = 16384
    float* wsc = sm + 6400 + 16384;      // per-warp: ea 8*52 + t1 8*128 = 1440

    int tid = threadIdx.x;
    for (int i = tid; i < 25 * 128; i += EW * 32) {
        int p = i >> 7, c = i & 127;
        w1i[2 * i]     = w1[(2 * p) * 128 + c];
        w1i[2 * i + 1] = w1[(2 * p + 1) * 128 + c];
    }
    for (int i = tid; i < 64 * 128; i += EW * 32) {
        int p = i >> 7, c = i & 127;
        w2i[2 * i]     = w2[(2 * p) * 128 + c];
        w2i[2 * i + 1] = w2[(2 * p + 1) * 128 + c];
    }
    __syncthreads();

    int warp = tid >> 5, lane = tid & 31;
    int cA = 2 * lane, cB = 64 + 2 * lane;
    float* ea = wsc + warp * 1440;       // [8][52]
    float* t1 = ea + ET * 52;            // [8][128]

    float b1A0 = b1[cA], b1A1 = b1[cA + 1], b1B0 = b1[cB], b1B1 = b1[cB + 1];
    float b2A0 = b2[cA], b2A1 = b2[cA + 1], b2B0 = b2[cB], b2B1 = b2[cB + 1];

    const float step  = CUTOFF / (GDIM - 1);
    const float coeff = -0.5f / (step * step);
    const float PIOC  = 3.14159265358979f / CUTOFF;

    for (long base = (long)(blockIdx.x * EW + warp) * ET; base < E;
         base += (long)gridDim.x * EW * ET)
    {
        int  sidx[ET], tidx[ET];
        float dd[ET];
        bool  val[ET];
        #pragma unroll
        for (int j = 0; j < ET; j++) {
            long e = base + j;
            val[j] = (e < E);
            int ee = val[j] ? (int)e : 0;
            sidx[j] = src[ee]; tidx[j] = dst[ee];
            float dx = pos[3*sidx[j]]   - pos[3*tidx[j]];
            float dy = pos[3*sidx[j]+1] - pos[3*tidx[j]+1];
            float dz = pos[3*sidx[j]+2] - pos[3*tidx[j]+2];
            dd[j] = sqrtf(dx*dx + dy*dy + dz*dz);
            for (int g = lane; g < GDIM; g += 32) {
                float u = dd[j] - g * step;
                ea[j * 52 + g] = __expf(coeff * u * u);
            }
        }
        __syncwarp();

        // GEMM1: [8,50] x [50,128], f32x2 over 25 k-pairs
        ull a[ET][4];
        #pragma unroll
        for (int j = 0; j < ET; j++) { a[j][0]=0; a[j][1]=0; a[j][2]=0; a[j][3]=0; }
        #pragma unroll 5
        for (int p = 0; p < 25; p++) {
            ulonglong2 wA = *(const ulonglong2*)(w1i + p * 256 + 4 * lane);
            ulonglong2 wB = *(const ulonglong2*)(w1i + p * 256 + 128 + 4 * lane);
            #pragma unroll
            for (int j = 0; j < ET; j++) {
                ull xv = *(const ull*)(ea + j * 52 + 2 * p);
                a[j][0] = ffma2(xv, wA.x, a[j][0]);
                a[j][1] = ffma2(xv, wA.y, a[j][1]);
                a[j][2] = ffma2(xv, wB.x, a[j][2]);
                a[j][3] = ffma2(xv, wB.y, a[j][3]);
            }
        }
        #pragma unroll
        for (int j = 0; j < ET; j++) {
            *(float2*)(t1 + j * 128 + cA) =
                make_float2(sspf(fcomb(a[j][0]) + b1A0), sspf(fcomb(a[j][1]) + b1A1));
            *(float2*)(t1 + j * 128 + cB) =
                make_float2(sspf(fcomb(a[j][2]) + b1B0), sspf(fcomb(a[j][3]) + b1B1));
        }
        __syncwarp();

        // GEMM2: [8,128] x [128,128], f32x2 over 64 k-pairs
        ull c[ET][4];
        #pragma unroll
        for (int j = 0; j < ET; j++) { c[j][0]=0; c[j][1]=0; c[j][2]=0; c[j][3]=0; }
        #pragma unroll 4
        for (int p = 0; p < 64; p++) {
            ulonglong2 wA = *(const ulonglong2*)(w2i + p * 256 + 4 * lane);
            ulonglong2 wB = *(const ulonglong2*)(w2i + p * 256 + 128 + 4 * lane);
            #pragma unroll
            for (int j = 0; j < ET; j++) {
                ull xv = *(const ull*)(t1 + j * 128 + 2 * p);
                c[j][0] = ffma2(xv, wA.x, c[j][0]);
                c[j][1] = ffma2(xv, wA.y, c[j][1]);
                c[j][2] = ffma2(xv, wB.x, c[j][2]);
                c[j][3] = ffma2(xv, wB.y, c[j][3]);
            }
        }

        // epilogue: cutoff * W * hx[src], scatter-add to agg[dst]
        #pragma unroll
        for (int j = 0; j < ET; j++) {
            if (!val[j]) continue;
            float cc = 0.5f * (cosf(dd[j] * PIOC) + 1.f);
            const float* hp = g_hx + (long)sidx[j] * HDIM;
            float2 hA = *(const float2*)(hp + cA);
            float2 hB = *(const float2*)(hp + cB);
            float* ap = g_agg + (long)tidx[j] * HDIM;
            atomicAdd(ap + cA,     (fcomb(c[j][0]) + b2A0) * cc * hA.x);
            atomicAdd(ap + cA + 1, (fcomb(c[j][1]) + b2A1) * cc * hA.y);
            atomicAdd(ap + cB,     (fcomb(c[j][2]) + b2B0) * cc * hB.x);
            atomicAdd(ap + cB + 1, (fcomb(c[j][3]) + b2B1) * cc * hB.y);
        }
        __syncwarp();
    }
}

// ---------------------------------------------------------------------------
// Output head
// ---------------------------------------------------------------------------
__global__ __launch_bounds__(256) void k_out(
    const float* __restrict__ out1_w, const float* __restrict__ out1_b,
    const float* __restrict__ out2_w, const float* __restrict__ out2_b,
    const int* __restrict__ batch, float* __restrict__ out)
{
    __shared__ float W1[128 * 64];
    __shared__ float w2s[64];
    __shared__ float xs[8][128];

    int tid = threadIdx.x;
    for (int i = tid; i < 128 * 64; i += 256) W1[i] = out1_w[i];
    if (tid < 64) w2s[tid] = out2_w[tid];
    __syncthreads();

    int warp = tid >> 5, lane = tid & 31;
    float ob0 = out1_b[lane], ob1 = out1_b[lane + 32];
    float b2v = out2_b[0];

    for (int row = blockIdx.x * 8 + warp; row < NATOMS; row += gridDim.x * 8) {
        ((float4*)xs[warp])[lane] = ((const float4*)(g_h + (long)row * 128))[lane];
        __syncwarp();
        float a0 = ob0, a1 = ob1;
        #pragma unroll 8
        for (int k = 0; k < 128; k++) {
            float xv = xs[warp][k];
            a0 += xv * W1[k * 64 + lane];
            a1 += xv * W1[k * 64 + lane + 32];
        }
        float v = sspf(a0) * w2s[lane] + sspf(a1) * w2s[lane + 32];
        #pragma unroll
        for (int off = 16; off; off >>= 1) v += __shfl_down_sync(0xffffffffu, v, off);
        if (lane == 0) atomicAdd(&out[batch[row]], v + b2v);
        __syncwarp();
    }
}

// ---------------------------------------------------------------------------
extern "C" void kernel_launch(void* const* d_in, const int* in_sizes, int n_in,
                              void* d_out, int out_size)
{
    const int*   z       = (const int*)  d_in[0];
    const float* pos     = (const float*)d_in[1];
    const int*   batch   = (const int*)  d_in[2];
    const int*   ei      = (const int*)  d_in[3];
    const float* emb     = (const float*)d_in[4];
    const float* mlp_w1  = (const float*)d_in[5];
    const float* mlp_b1  = (const float*)d_in[6];
    const float* mlp_w2  = (const float*)d_in[7];
    const float* mlp_b2  = (const float*)d_in[8];
    const float* cf1_w   = (const float*)d_in[9];
    const float* cf2_w   = (const float*)d_in[10];
    const float* cf2_b   = (const float*)d_in[11];
    const float* lin_w   = (const float*)d_in[12];
    const float* lin_b   = (const float*)d_in[13];
    const float* out1_w  = (const float*)d_in[14];
    const float* out1_b  = (const float*)d_in[15];
    const float* out2_w  = (const float*)d_in[16];
    const float* out2_b  = (const float*)d_in[17];

    int E = in_sizes[3] / 2;
    const int* src = ei;
    const int* dst = ei + E;

    const int EDGE_SMEM = (6400 + 16384 + EW * 1440) * 4;  // 183296 B
    const int GEMM_SMEM = (16384 + 8 * 1024) * 4;          // 98304 B
    cudaFuncSetAttribute(k_edge, cudaFuncAttributeMaxDynamicSharedMemorySize, EDGE_SMEM);
    cudaFuncSetAttribute(k_gemmx<false,false>, cudaFuncAttributeMaxDynamicSharedMemorySize, GEMM_SMEM);
    cudaFuncSetAttribute(k_gemmx<true ,false>, cudaFuncAttributeMaxDynamicSharedMemorySize, GEMM_SMEM);
    cudaFuncSetAttribute(k_gemmx<false,true >, cudaFuncAttributeMaxDynamicSharedMemorySize, GEMM_SMEM);

    float *ph, *phx, *pagg, *ptmp;
    cudaGetSymbolAddress((void**)&ph,   g_h);
    cudaGetSymbolAddress((void**)&phx,  g_hx);
    cudaGetSymbolAddress((void**)&pagg, g_agg);
    cudaGetSymbolAddress((void**)&ptmp, g_tmp);

    float* out = (float*)d_out;

    k_embed<<<(NATOMS*HDIM + 255)/256, 256>>>(z, emb);

    for (int l = 0; l < LINT; l++) {
        k_gemmx<false,false><<<256, 256, GEMM_SMEM>>>(
            ph, cf1_w + (long)l*HDIM*HDIM, nullptr, phx, NATOMS);
        k_zero_agg<<<(NATOMS*HDIM + 255)/256, 256>>>();
        k_edge<<<152, EW*32, EDGE_SMEM>>>(
            pos, src, dst,
            mlp_w1 + (long)l*GDIM*HDIM, mlp_b1 + (long)l*HDIM,
            mlp_w2 + (long)l*HDIM*HDIM, mlp_b2 + (long)l*HDIM, E);
        k_gemmx<true,false><<<256, 256, GEMM_SMEM>>>(
            pagg, cf2_w + (long)l*HDIM*HDIM, cf2_b + (long)l*HDIM, ptmp, NATOMS);
        k_gemmx<false,true><<<256, 256, GEMM_SMEM>>>(
            ptmp, lin_w + (long)l*HDIM*HDIM, lin_b + (long)l*HDIM, ph, NATOMS);
    }

    k_zero_out<<<1, 512>>>(out);
    k_out<<<256, 256>>>(out1_w, out1_b, out2_w, out2_b, batch, out);
}

// round 4
// speedup vs baseline: 1.4725x; 1.2551x over previous
#include <cuda_runtime.h>
#include <cuda_bf16.h>
#include <math.h>
#include <stdint.h>

#define NATOMS 16384
#define NMOL   512
#define APM    32
#define HDIM   128
#define GDIM   50
#define LINT   3
#define CUTOFF 6.0f

typedef unsigned long long ull;

// Scratch (allocation-free)
__device__ float g_h  [NATOMS * HDIM];
__device__ float g_hx [NATOMS * HDIM];
__device__ float g_agg[NATOMS * HDIM];
__device__ float g_tmp[NATOMS * HDIM];
__device__ int   g_moff[NMOL + 1];

__device__ __forceinline__ float sspf(float x) {
    const float LN2 = 0.6931471805599453f;
    if (x > 20.f) return x - LN2;
    return __logf(1.f + __expf(x)) - LN2;
}
__device__ __forceinline__ ull ffma2(ull a, ull b, ull c) {
    ull d;
    asm("fma.rn.f32x2 %0, %1, %2, %3;" : "=l"(d) : "l"(a), "l"(b), "l"(c));
    return d;
}
__device__ __forceinline__ float fcomb(ull a) {
    float lo = __int_as_float((int)(a & 0xffffffffULL));
    float hi = __int_as_float((int)(a >> 32));
    return lo + hi;
}
// bf16 hi/lo split of a float pair, packed low-half = first element
__device__ __forceinline__ void split2(float v0, float v1, uint32_t& hi, uint32_t& lo) {
    __nv_bfloat16 h0 = __float2bfloat16(v0), h1 = __float2bfloat16(v1);
    __nv_bfloat16 l0 = __float2bfloat16(v0 - __bfloat162float(h0));
    __nv_bfloat16 l1 = __float2bfloat16(v1 - __bfloat162float(h1));
    hi = (uint32_t)__bfloat16_as_ushort(h0) | ((uint32_t)__bfloat16_as_ushort(h1) << 16);
    lo = (uint32_t)__bfloat16_as_ushort(l0) | ((uint32_t)__bfloat16_as_ushort(l1) << 16);
}
__device__ __forceinline__ void mma16816(float* d,
    uint32_t a0, uint32_t a1, uint32_t a2, uint32_t a3, uint32_t b0, uint32_t b1) {
    asm volatile(
        "mma.sync.aligned.m16n8k16.row.col.f32.bf16.bf16.f32 "
        "{%0,%1,%2,%3}, {%4,%5,%6,%7}, {%8,%9}, {%0,%1,%2,%3};"
        : "+f"(d[0]), "+f"(d[1]), "+f"(d[2]), "+f"(d[3])
        : "r"(a0), "r"(a1), "r"(a2), "r"(a3), "r"(b0), "r"(b1));
}
__device__ __forceinline__ void eaf(float d, float gofs, float step, float coeff,
                                    uint32_t& hi, uint32_t& lo) {
    float u0 = d - gofs, u1 = d - gofs - step;
    float e0 = __expf(coeff * u0 * u0);
    float e1 = __expf(coeff * u1 * u1);
    split2(e0, e1, hi, lo);
}

// ---------------------------------------------------------------------------
__global__ void k_embed(const int* __restrict__ z, const float* __restrict__ emb) {
    int i = blockIdx.x * blockDim.x + threadIdx.x;
    if (i < NATOMS * HDIM) {
        int a = i >> 7, f = i & 127;
        g_h[i] = emb[z[a] * HDIM + f];
    }
}
__global__ void k_zero_out(float* out) {
    int i = blockIdx.x * blockDim.x + threadIdx.x;
    if (i < NMOL) out[i] = 0.f;
}
// per-molecule edge offsets (edges sorted by src ascending)
__global__ void k_moff(const int* __restrict__ src, int E) {
    int m = blockIdx.x * blockDim.x + threadIdx.x;
    if (m > NMOL) return;
    int target = m * APM;
    int lo = 0, hi = E;
    while (lo < hi) { int mid = (lo + hi) >> 1; if (src[mid] < target) lo = mid + 1; else hi = mid; }
    g_moff[m] = lo;
}

// ---------------------------------------------------------------------------
// Node GEMM 128x128 via f32x2 (unchanged from R2)
// ---------------------------------------------------------------------------
template<bool ACT, bool ADDTO>
__global__ __launch_bounds__(256, 1) void k_gemmx(
    const float* __restrict__ x, const float* __restrict__ W,
    const float* __restrict__ b, float* __restrict__ y, int nrows)
{
    extern __shared__ float sm[];
    float* Wi = sm;
    float* xs = sm + 16384;

    int tid = threadIdx.x;
    for (int i = tid; i < 64 * 128; i += 256) {
        int p = i >> 7, c = i & 127;
        Wi[2 * i]     = W[(2 * p) * 128 + c];
        Wi[2 * i + 1] = W[(2 * p + 1) * 128 + c];
    }
    __syncthreads();

    int warp = tid >> 5, lane = tid & 31;
    int cA = 2 * lane, cB = 64 + 2 * lane;
    float bA0 = b ? b[cA] : 0.f, bA1 = b ? b[cA + 1] : 0.f;
    float bB0 = b ? b[cB] : 0.f, bB1 = b ? b[cB + 1] : 0.f;
    float* xw = xs + warp * 1024;

    for (int base = blockIdx.x * 64 + warp * 8; base < nrows; base += gridDim.x * 64) {
        #pragma unroll
        for (int r = 0; r < 8; r++)
            ((float4*)(xw + r * 128))[lane] = ((const float4*)(x + (long)(base + r) * 128))[lane];
        __syncwarp();

        ull acc[8][4];
        #pragma unroll
        for (int r = 0; r < 8; r++) { acc[r][0]=0; acc[r][1]=0; acc[r][2]=0; acc[r][3]=0; }

        #pragma unroll 4
        for (int p = 0; p < 64; p++) {
            ulonglong2 wA = *(const ulonglong2*)(Wi + p * 256 + 4 * lane);
            ulonglong2 wB = *(const ulonglong2*)(Wi + p * 256 + 128 + 4 * lane);
            #pragma unroll
            for (int r = 0; r < 8; r++) {
                ull xv = *(const ull*)(xw + r * 128 + 2 * p);
                acc[r][0] = ffma2(xv, wA.x, acc[r][0]);
                acc[r][1] = ffma2(xv, wA.y, acc[r][1]);
                acc[r][2] = ffma2(xv, wB.x, acc[r][2]);
                acc[r][3] = ffma2(xv, wB.y, acc[r][3]);
            }
        }

        #pragma unroll
        for (int r = 0; r < 8; r++) {
            float v0 = fcomb(acc[r][0]) + bA0;
            float v1 = fcomb(acc[r][1]) + bA1;
            float v2 = fcomb(acc[r][2]) + bB0;
            float v3 = fcomb(acc[r][3]) + bB1;
            if (ACT) { v0 = sspf(v0); v1 = sspf(v1); v2 = sspf(v2); v3 = sspf(v3); }
            float* yp = y + (long)(base + r) * 128;
            if (ADDTO) {
                float2 pa = *(float2*)(yp + cA); v0 += pa.x; v1 += pa.y;
                float2 pb = *(float2*)(yp + cB); v2 += pb.x; v3 += pb.y;
            }
            *(float2*)(yp + cA) = make_float2(v0, v1);
            *(float2*)(yp + cB) = make_float2(v2, v3);
        }
        __syncwarp();
    }
}

// ---------------------------------------------------------------------------
// HMMA edge kernel: persistent CTA per molecule set; 256 threads = 8 warps,
// each tile = 128 edges; warp w owns edge-rows 16w..16w+15 across all 128 cols.
// GEMM1/GEMM2 in 3-pass split-bf16; t1 stays in registers (D-frag == A-frag).
// Aggregation: agg[src] += W ⊙ hx[dst] (valid by graph/W symmetry), segmented
// reduction over the src-sorted tile through SMEM, agg held in registers.
// ---------------------------------------------------------------------------
#define B1S 68
#define B2S 132
#define SBS 136
#define HXS 132
#define OB1  0
#define OB2  8704
#define OSB  25600
#define OHX  43008
#define OSD  47232
#define OCC  47360
#define ODL  47488
#define OSL  47616
#define OCN  47744
#define OSB1 47792
#define OSB2 47920
#define OPS  48048
#define SMW  48160
#define EDGE_SMEM_BYTES (SMW * 4)

__global__ __launch_bounds__(256, 1)
void k_edge_mma(const float* __restrict__ pos,
                const int* __restrict__ src, const int* __restrict__ dst,
                const float* __restrict__ w1, const float* __restrict__ b1,
                const float* __restrict__ w2, const float* __restrict__ b2)
{
    extern __shared__ float sm[];
    uint32_t* B1u = (uint32_t*)(sm + OB1);
    uint32_t* B2u = (uint32_t*)(sm + OB2);
    float* sbuf = sm + OSB;
    float* hxs  = sm + OHX;
    float* sd   = sm + OSD;
    float* scc  = sm + OCC;
    int*   sdl  = (int*)(sm + ODL);
    int*   ssl  = (int*)(sm + OSL);
    int*   scnt = (int*)(sm + OCN);
    float* sb1  = sm + OSB1;
    float* sb2  = sm + OSB2;
    float* ps   = sm + OPS;

    const int tid = threadIdx.x, wid = tid >> 5, lane = tid & 31;
    const int qr = lane >> 2, qc = lane & 3;

    // ---- stage weights coalesced into sbuf, then build split-bf16 B tiles ----
    for (int i = tid; i < GDIM * 128; i += 256) sbuf[i] = w1[i];
    __syncthreads();
    for (int i = tid; i < 128 * 32; i += 256) {
        int kp = i >> 7, n = i & 127, k = kp * 2;
        float v0 = (k < GDIM)     ? sbuf[k * 128 + n]       : 0.f;
        float v1 = (k + 1 < GDIM) ? sbuf[(k + 1) * 128 + n] : 0.f;
        uint32_t h, l; split2(v0, v1, h, l);
        B1u[n * B1S + kp] = h;
        B1u[n * B1S + 32 + kp] = l;
    }
    __syncthreads();
    for (int i = tid; i < 128 * 128; i += 256) sbuf[i] = w2[i];
    __syncthreads();
    for (int i = tid; i < 128 * 64; i += 256) {
        int kp = i >> 7, n = i & 127, k = kp * 2;
        float v0 = sbuf[k * 128 + n], v1 = sbuf[(k + 1) * 128 + n];
        uint32_t h, l; split2(v0, v1, h, l);
        B2u[n * B2S + kp] = h;
        B2u[n * B2S + 64 + kp] = l;
    }
    if (tid < 128) { sb1[tid] = b1[tid]; sb2[tid] = b2[tid]; }
    __syncthreads();

    const float step  = CUTOFF / (GDIM - 1);
    const float coeff = -0.5f / (step * step);
    const float PIOC  = 3.14159265358979f / CUTOFF;
    const int a_own = tid >> 3, c_own = (tid & 7) * 16;
    const int r0 = wid * 16 + qr;

    for (int m = blockIdx.x; m < NMOL; m += gridDim.x) {
        int e0 = g_moff[m], e1 = g_moff[m + 1];
        for (int i = tid; i < APM * 128; i += 256) {
            int a = i >> 7, c = i & 127;
            hxs[a * HXS + c] = g_hx[(long)(m * APM + a) * 128 + c];
        }
        if (tid < 96) ps[tid] = pos[m * 96 + tid];
        float4 agg0 = make_float4(0,0,0,0), agg1 = agg0, agg2 = agg0, agg3 = agg0;
        __syncthreads();

        for (int t0 = e0; t0 < e1; t0 += 128) {
            if (tid < 128) {
                int e = t0 + tid;
                float d = 0.f, cc = 0.f;
                int di = 0, sl = APM;
                if (e < e1) {
                    int s = src[e] - m * APM;
                    di = dst[e] - m * APM;
                    float dx = ps[3*s]   - ps[3*di];
                    float dy = ps[3*s+1] - ps[3*di+1];
                    float dz = ps[3*s+2] - ps[3*di+2];
                    d = sqrtf(dx*dx + dy*dy + dz*dz);
                    cc = 0.5f * (cosf(d * PIOC) + 1.f);
                    sl = s;
                }
                sd[tid] = d; scc[tid] = cc; sdl[tid] = di; ssl[tid] = sl;
            }
            __syncthreads();
            if (tid < APM) {
                int c = 0;
                for (int r = 0; r < 128; r++) c += (ssl[r] <= tid) ? 1 : 0;
                scnt[tid + 1] = c;
                if (tid == 0) scnt[0] = 0;
            }

            float dv0 = sd[r0], dv1 = sd[r0 + 8];

            // ---- GEMM1: D1 = split-bf16( ea[128x64] x W1[64x128] ) ----
            float acc1[16][4];
            #pragma unroll
            for (int nb = 0; nb < 16; nb++) {
                acc1[nb][0] = 0.f; acc1[nb][1] = 0.f; acc1[nb][2] = 0.f; acc1[nb][3] = 0.f;
            }
            #pragma unroll
            for (int ks = 0; ks < 4; ks++) {
                float g0 = (float)(ks * 16 + 2 * qc) * step;
                uint32_t aH[4], aL[4];
                eaf(dv0, g0,             step, coeff, aH[0], aL[0]);
                eaf(dv1, g0,             step, coeff, aH[1], aL[1]);
                eaf(dv0, g0 + 8.f*step,  step, coeff, aH[2], aL[2]);
                eaf(dv1, g0 + 8.f*step,  step, coeff, aH[3], aL[3]);
                #pragma unroll
                for (int nb = 0; nb < 16; nb++) {
                    int noff = (nb * 8 + qr) * B1S + ks * 8 + qc;
                    uint32_t bh0 = B1u[noff], bh1 = B1u[noff + 4];
                    mma16816(acc1[nb], aH[0], aH[1], aH[2], aH[3], bh0, bh1);
                    mma16816(acc1[nb], aL[0], aL[1], aL[2], aL[3], bh0, bh1);
                    uint32_t bl0 = B1u[noff + 32], bl1 = B1u[noff + 36];
                    mma16816(acc1[nb], aH[0], aH[1], aH[2], aH[3], bl0, bl1);
                }
            }

            // ---- activation + split; t1 stays in registers as A-fragments ----
            uint32_t tAh[16], tBh[16], tAl[16], tBl[16];
            #pragma unroll
            for (int nb = 0; nb < 16; nb++) {
                int c = nb * 8 + 2 * qc;
                float bx = sb1[c], by = sb1[c + 1];
                float v0 = sspf(acc1[nb][0] + bx);
                float v1 = sspf(acc1[nb][1] + by);
                float v2 = sspf(acc1[nb][2] + bx);
                float v3 = sspf(acc1[nb][3] + by);
                split2(v0, v1, tAh[nb], tAl[nb]);
                split2(v2, v3, tBh[nb], tBl[nb]);
            }

            // ---- GEMM2: D2 = split-bf16( t1[128x128] x W2[128x128] ) ----
            float acc2[16][4];
            #pragma unroll
            for (int nb = 0; nb < 16; nb++) {
                acc2[nb][0] = 0.f; acc2[nb][1] = 0.f; acc2[nb][2] = 0.f; acc2[nb][3] = 0.f;
            }
            #pragma unroll
            for (int ks = 0; ks < 8; ks++) {
                #pragma unroll
                for (int nb = 0; nb < 16; nb++) {
                    int noff = (nb * 8 + qr) * B2S + ks * 8 + qc;
                    uint32_t bh0 = B2u[noff], bh1 = B2u[noff + 4];
                    mma16816(acc2[nb], tAh[2*ks], tBh[2*ks], tAh[2*ks+1], tBh[2*ks+1], bh0, bh1);
                    mma16816(acc2[nb], tAl[2*ks], tBl[2*ks], tAl[2*ks+1], tBl[2*ks+1], bh0, bh1);
                    uint32_t bl0 = B2u[noff + 64], bl1 = B2u[noff + 68];
                    mma16816(acc2[nb], tAh[2*ks], tBh[2*ks], tAh[2*ks+1], tBh[2*ks+1], bl0, bl1);
                }
            }

            // ---- msg = (D2 + b2) * cc * hx[dst]  -> sbuf ----
            float cc0 = scc[r0], cc1 = scc[r0 + 8];
            int dl0 = sdl[r0], dl1 = sdl[r0 + 8];
            #pragma unroll
            for (int nb = 0; nb < 16; nb++) {
                int c = nb * 8 + 2 * qc;
                float bx = sb2[c], by = sb2[c + 1];
                float2 h0 = *(float2*)&hxs[dl0 * HXS + c];
                float2 h1 = *(float2*)&hxs[dl1 * HXS + c];
                *(float2*)&sbuf[r0 * SBS + c] =
                    make_float2((acc2[nb][0] + bx) * cc0 * h0.x,
                                (acc2[nb][1] + by) * cc0 * h0.y);
                *(float2*)&sbuf[(r0 + 8) * SBS + c] =
                    make_float2((acc2[nb][2] + bx) * cc1 * h1.x,
                                (acc2[nb][3] + by) * cc1 * h1.y);
            }
            __syncthreads();

            // ---- segmented reduce over src-sorted rows into register agg ----
            int rs = scnt[a_own], re = scnt[a_own + 1];
            for (int r = rs; r < re; r++) {
                const float4* p = (const float4*)&sbuf[r * SBS + c_own];
                float4 x0 = p[0], x1 = p[1], x2 = p[2], x3 = p[3];
                agg0.x += x0.x; agg0.y += x0.y; agg0.z += x0.z; agg0.w += x0.w;
                agg1.x += x1.x; agg1.y += x1.y; agg1.z += x1.z; agg1.w += x1.w;
                agg2.x += x2.x; agg2.y += x2.y; agg2.z += x2.z; agg2.w += x2.w;
                agg3.x += x3.x; agg3.y += x3.y; agg3.z += x3.z; agg3.w += x3.w;
            }
            __syncthreads();
        }

        float* ap = g_agg + (long)(m * APM + a_own) * 128 + c_own;
        ((float4*)ap)[0] = agg0;
        ((float4*)ap)[1] = agg1;
        ((float4*)ap)[2] = agg2;
        ((float4*)ap)[3] = agg3;
        __syncthreads();
    }
}

// ---------------------------------------------------------------------------
__global__ __launch_bounds__(256) void k_out(
    const float* __restrict__ out1_w, const float* __restrict__ out1_b,
    const float* __restrict__ out2_w, const float* __restrict__ out2_b,
    const int* __restrict__ batch, float* __restrict__ out)
{
    __shared__ float W1[128 * 64];
    __shared__ float w2s[64];
    __shared__ float xs[8][128];

    int tid = threadIdx.x;
    for (int i = tid; i < 128 * 64; i += 256) W1[i] = out1_w[i];
    if (tid < 64) w2s[tid] = out2_w[tid];
    __syncthreads();

    int warp = tid >> 5, lane = tid & 31;
    float ob0 = out1_b[lane], ob1 = out1_b[lane + 32];
    float b2v = out2_b[0];

    for (int row = blockIdx.x * 8 + warp; row < NATOMS; row += gridDim.x * 8) {
        ((float4*)xs[warp])[lane] = ((const float4*)(g_h + (long)row * 128))[lane];
        __syncwarp();
        float a0 = ob0, a1 = ob1;
        #pragma unroll 8
        for (int k = 0; k < 128; k++) {
            float xv = xs[warp][k];
            a0 += xv * W1[k * 64 + lane];
            a1 += xv * W1[k * 64 + lane + 32];
        }
        float v = sspf(a0) * w2s[lane] + sspf(a1) * w2s[lane + 32];
        #pragma unroll
        for (int off = 16; off; off >>= 1) v += __shfl_down_sync(0xffffffffu, v, off);
        if (lane == 0) atomicAdd(&out[batch[row]], v + b2v);
        __syncwarp();
    }
}

// ---------------------------------------------------------------------------
extern "C" void kernel_launch(void* const* d_in, const int* in_sizes, int n_in,
                              void* d_out, int out_size)
{
    const int*   z       = (const int*)  d_in[0];
    const float* pos     = (const float*)d_in[1];
    const int*   batch   = (const int*)  d_in[2];
    const int*   ei      = (const int*)  d_in[3];
    const float* emb     = (const float*)d_in[4];
    const float* mlp_w1  = (const float*)d_in[5];
    const float* mlp_b1  = (const float*)d_in[6];
    const float* mlp_w2  = (const float*)d_in[7];
    const float* mlp_b2  = (const float*)d_in[8];
    const float* cf1_w   = (const float*)d_in[9];
    const float* cf2_w   = (const float*)d_in[10];
    const float* cf2_b   = (const float*)d_in[11];
    const float* lin_w   = (const float*)d_in[12];
    const float* lin_b   = (const float*)d_in[13];
    const float* out1_w  = (const float*)d_in[14];
    const float* out1_b  = (const float*)d_in[15];
    const float* out2_w  = (const float*)d_in[16];
    const float* out2_b  = (const float*)d_in[17];

    int E = in_sizes[3] / 2;
    const int* src = ei;
    const int* dst = ei + E;

    const int GEMM_SMEM = (16384 + 8 * 1024) * 4;
    cudaFuncSetAttribute(k_edge_mma, cudaFuncAttributeMaxDynamicSharedMemorySize, EDGE_SMEM_BYTES);
    cudaFuncSetAttribute(k_gemmx<false,false>, cudaFuncAttributeMaxDynamicSharedMemorySize, GEMM_SMEM);
    cudaFuncSetAttribute(k_gemmx<true ,false>, cudaFuncAttributeMaxDynamicSharedMemorySize, GEMM_SMEM);
    cudaFuncSetAttribute(k_gemmx<false,true >, cudaFuncAttributeMaxDynamicSharedMemorySize, GEMM_SMEM);

    float *ph, *phx, *pagg, *ptmp;
    cudaGetSymbolAddress((void**)&ph,   g_h);
    cudaGetSymbolAddress((void**)&phx,  g_hx);
    cudaGetSymbolAddress((void**)&pagg, g_agg);
    cudaGetSymbolAddress((void**)&ptmp, g_tmp);

    float* out = (float*)d_out;

    k_moff<<<3, 256>>>(src, E);
    k_embed<<<(NATOMS*HDIM + 255)/256, 256>>>(z, emb);

    for (int l = 0; l < LINT; l++) {
        k_gemmx<false,false><<<256, 256, GEMM_SMEM>>>(
            ph, cf1_w + (long)l*HDIM*HDIM, nullptr, phx, NATOMS);
        k_edge_mma<<<148, 256, EDGE_SMEM_BYTES>>>(
            pos, src, dst,
            mlp_w1 + (long)l*GDIM*HDIM, mlp_b1 + (long)l*HDIM,
            mlp_w2 + (long)l*HDIM*HDIM, mlp_b2 + (long)l*HDIM);
        k_gemmx<true,false><<<256, 256, GEMM_SMEM>>>(
            pagg, cf2_w + (long)l*HDIM*HDIM, cf2_b + (long)l*HDIM, ptmp, NATOMS);
        k_gemmx<false,true><<<256, 256, GEMM_SMEM>>>(
            ptmp, lin_w + (long)l*HDIM*HDIM, lin_b + (long)l*HDIM, ph, NATOMS);
    }

    k_zero_out<<<1, 512>>>(out);
    k_out<<<256, 256>>>(out1_w, out1_b, out2_w, out2_b, batch, out);
}

// round 5
// speedup vs baseline: 1.7168x; 1.1659x over previous
#include <cuda_runtime.h>
#include <cuda_bf16.h>
#include <math.h>
#include <stdint.h>

#define NATOMS 16384
#define NMOL   512
#define APM    32
#define HDIM   128
#define GDIM   50
#define LINT   3
#define CUTOFF 6.0f

typedef unsigned long long ull;

// Scratch (allocation-free)
__device__ float g_h  [NATOMS * HDIM];
__device__ float g_hx [NATOMS * HDIM];
__device__ float g_agg[NATOMS * HDIM];
__device__ float g_tmp[NATOMS * HDIM];
__device__ int   g_moff[NMOL + 1];
__device__ int   g_ucnt[NMOL];
__device__ unsigned g_upak[NMOL * 512];
__device__ int   g_ioff[NMOL * 4 * 33];
__device__ int   g_joff[NMOL * 4 * 33];
__device__ int   g_jperm[NMOL * 512];

__device__ __forceinline__ float sspf(float x) {
    const float LN2 = 0.6931471805599453f;
    if (x > 20.f) return x - LN2;
    return __logf(1.f + __expf(x)) - LN2;
}
__device__ __forceinline__ ull ffma2(ull a, ull b, ull c) {
    ull d;
    asm("fma.rn.f32x2 %0, %1, %2, %3;" : "=l"(d) : "l"(a), "l"(b), "l"(c));
    return d;
}
__device__ __forceinline__ float fcomb(ull a) {
    float lo = __int_as_float((int)(a & 0xffffffffULL));
    float hi = __int_as_float((int)(a >> 32));
    return lo + hi;
}
__device__ __forceinline__ void split2(float v0, float v1, uint32_t& hi, uint32_t& lo) {
    __nv_bfloat16 h0 = __float2bfloat16(v0), h1 = __float2bfloat16(v1);
    __nv_bfloat16 l0 = __float2bfloat16(v0 - __bfloat162float(h0));
    __nv_bfloat16 l1 = __float2bfloat16(v1 - __bfloat162float(h1));
    hi = (uint32_t)__bfloat16_as_ushort(h0) | ((uint32_t)__bfloat16_as_ushort(h1) << 16);
    lo = (uint32_t)__bfloat16_as_ushort(l0) | ((uint32_t)__bfloat16_as_ushort(l1) << 16);
}
__device__ __forceinline__ void mma16816(float* d,
    uint32_t a0, uint32_t a1, uint32_t a2, uint32_t a3, uint32_t b0, uint32_t b1) {
    asm volatile(
        "mma.sync.aligned.m16n8k16.row.col.f32.bf16.bf16.f32 "
        "{%0,%1,%2,%3}, {%4,%5,%6,%7}, {%8,%9}, {%0,%1,%2,%3};"
        : "+f"(d[0]), "+f"(d[1]), "+f"(d[2]), "+f"(d[3])
        : "r"(a0), "r"(a1), "r"(a2), "r"(a3), "r"(b0), "r"(b1));
}
__device__ __forceinline__ void eaf(float d, float gofs, float step, float coeff,
                                    uint32_t& hi, uint32_t& lo) {
    float u0 = d - gofs, u1 = d - gofs - step;
    float e0 = __expf(coeff * u0 * u0);
    float e1 = __expf(coeff * u1 * u1);
    split2(e0, e1, hi, lo);
}

// ---------------------------------------------------------------------------
__global__ void k_embed(const int* __restrict__ z, const float* __restrict__ emb) {
    int i = blockIdx.x * blockDim.x + threadIdx.x;
    if (i < NATOMS * HDIM) {
        int a = i >> 7, f = i & 127;
        g_h[i] = emb[z[a] * HDIM + f];
    }
}
__global__ void k_zero_out(float* out) {
    int i = blockIdx.x * blockDim.x + threadIdx.x;
    if (i < NMOL) out[i] = 0.f;
}
__global__ void k_moff(const int* __restrict__ src, int E) {
    int m = blockIdx.x * blockDim.x + threadIdx.x;
    if (m > NMOL) return;
    int target = m * APM;
    int lo = 0, hi = E;
    while (lo < hi) { int mid = (lo + hi) >> 1; if (src[mid] < target) lo = mid + 1; else hi = mid; }
    g_moff[m] = lo;
}

// ---------------------------------------------------------------------------
// Prepass: per molecule, compact undirected edges (dst>src) preserving order,
// then per 128-row tile: i-side segment offsets (i is sorted) and j-side
// stable counting-sort permutation + offsets. Fully deterministic.
// ---------------------------------------------------------------------------
__global__ __launch_bounds__(128) void k_prep(const int* __restrict__ src,
                                              const int* __restrict__ dst) {
    __shared__ unsigned spak[128];
    __shared__ int scnt2[33];
    __shared__ int snu;
    int m = blockIdx.x;
    int tid = threadIdx.x, lane = tid & 31, wid = tid >> 5;
    int e0 = g_moff[m], e1 = g_moff[m + 1];

    if (wid == 0) {
        int cnt = 0;
        for (int base = e0; base < e1; base += 32) {
            int e = base + lane;
            bool p = false; unsigned pk = 0;
            if (e < e1) {
                int s = src[e] - m * APM, d2 = dst[e] - m * APM;
                if (d2 > s) { p = true; pk = (unsigned)((s << 8) | d2); }
            }
            unsigned msk = __ballot_sync(0xffffffffu, p);
            if (p) g_upak[m * 512 + cnt + __popc(msk & ((1u << lane) - 1))] = pk;
            cnt += __popc(msk);
        }
        if (lane == 0) { g_ucnt[m] = cnt; snu = cnt; }
    }
    __syncthreads();
    int nu = snu;
    int nt = (nu + 127) / 128;

    for (int t = 0; t < nt; t++) {
        int nr = nu - t * 128; if (nr > 128) nr = 128;
        if (tid < 128) spak[tid] = (tid < nr) ? g_upak[m * 512 + t * 128 + tid] : 0xffffffffu;
        __syncthreads();
        if (wid == 0) {   // i-side offsets (i sorted ascending)
            int a = lane, c = 0;
            for (int r = 0; r < nr; r++) c += ((int)(spak[r] >> 8) < a) ? 1 : 0;
            g_ioff[(m * 4 + t) * 33 + a] = c;
            if (lane == 0) g_ioff[(m * 4 + t) * 33 + 32] = nr;
        }
        if (wid == 1) {   // j-side counts -> exclusive scan
            int a = lane, c = 0;
            for (int r = 0; r < nr; r++) c += ((int)(spak[r] & 255) == a) ? 1 : 0;
            int x = c;
            #pragma unroll
            for (int o = 1; o < 32; o <<= 1) {
                int y = __shfl_up_sync(0xffffffffu, x, o);
                if (lane >= o) x += y;
            }
            int excl = x - c;
            g_joff[(m * 4 + t) * 33 + a] = excl;
            scnt2[a] = excl;
            if (lane == 31) g_joff[(m * 4 + t) * 33 + 32] = excl + c;
        }
        __syncthreads();
        if (tid == 0) {   // stable fill of j permutation
            for (int r = 0; r < nr; r++) {
                int j = (int)(spak[r] & 255);
                g_jperm[m * 512 + t * 128 + scnt2[j]] = r;
                scnt2[j]++;
            }
        }
        __syncthreads();
    }
}

// ---------------------------------------------------------------------------
// Node GEMM 128x128 via f32x2 (unchanged)
// ---------------------------------------------------------------------------
template<bool ACT, bool ADDTO>
__global__ __launch_bounds__(256, 1) void k_gemmx(
    const float* __restrict__ x, const float* __restrict__ W,
    const float* __restrict__ b, float* __restrict__ y, int nrows)
{
    extern __shared__ float sm[];
    float* Wi = sm;
    float* xs = sm + 16384;

    int tid = threadIdx.x;
    for (int i = tid; i < 64 * 128; i += 256) {
        int p = i >> 7, c = i & 127;
        Wi[2 * i]     = W[(2 * p) * 128 + c];
        Wi[2 * i + 1] = W[(2 * p + 1) * 128 + c];
    }
    __syncthreads();

    int warp = tid >> 5, lane = tid & 31;
    int cA = 2 * lane, cB = 64 + 2 * lane;
    float bA0 = b ? b[cA] : 0.f, bA1 = b ? b[cA + 1] : 0.f;
    float bB0 = b ? b[cB] : 0.f, bB1 = b ? b[cB + 1] : 0.f;
    float* xw = xs + warp * 1024;

    for (int base = blockIdx.x * 64 + warp * 8; base < nrows; base += gridDim.x * 64) {
        #pragma unroll
        for (int r = 0; r < 8; r++)
            ((float4*)(xw + r * 128))[lane] = ((const float4*)(x + (long)(base + r) * 128))[lane];
        __syncwarp();

        ull acc[8][4];
        #pragma unroll
        for (int r = 0; r < 8; r++) { acc[r][0]=0; acc[r][1]=0; acc[r][2]=0; acc[r][3]=0; }

        #pragma unroll 4
        for (int p = 0; p < 64; p++) {
            ulonglong2 wA = *(const ulonglong2*)(Wi + p * 256 + 4 * lane);
            ulonglong2 wB = *(const ulonglong2*)(Wi + p * 256 + 128 + 4 * lane);
            #pragma unroll
            for (int r = 0; r < 8; r++) {
                ull xv = *(const ull*)(xw + r * 128 + 2 * p);
                acc[r][0] = ffma2(xv, wA.x, acc[r][0]);
                acc[r][1] = ffma2(xv, wA.y, acc[r][1]);
                acc[r][2] = ffma2(xv, wB.x, acc[r][2]);
                acc[r][3] = ffma2(xv, wB.y, acc[r][3]);
            }
        }

        #pragma unroll
        for (int r = 0; r < 8; r++) {
            float v0 = fcomb(acc[r][0]) + bA0;
            float v1 = fcomb(acc[r][1]) + bA1;
            float v2 = fcomb(acc[r][2]) + bB0;
            float v3 = fcomb(acc[r][3]) + bB1;
            if (ACT) { v0 = sspf(v0); v1 = sspf(v1); v2 = sspf(v2); v3 = sspf(v3); }
            float* yp = y + (long)(base + r) * 128;
            if (ADDTO) {
                float2 pa = *(float2*)(yp + cA); v0 += pa.x; v1 += pa.y;
                float2 pb = *(float2*)(yp + cB); v2 += pb.x; v3 += pb.y;
            }
            *(float2*)(yp + cA) = make_float2(v0, v1);
            *(float2*)(yp + cB) = make_float2(v2, v3);
        }
        __syncwarp();
    }
}

// ---------------------------------------------------------------------------
// HMMA edge kernel on UNDIRECTED edges (W symmetric in direction):
// per 128-pair tile compute W once, then both-direction segmented reduction.
// ---------------------------------------------------------------------------
#define B1S 68
#define B2S 132
#define SBS 136
#define HXS 132
#define OB1  0
#define OB2  8704
#define OSB  25600
#define OHX  43008
#define OSD  47232
#define OCC  47360
#define OIL  47488
#define OJL  47616
#define OIO  47744
#define OJO  47778
#define OJP  47812
#define OSB1 47940
#define OSB2 48068
#define OPS  48196
#define SMW  48292
#define EDGE_SMEM_BYTES (SMW * 4)

__global__ __launch_bounds__(256, 1)
void k_edge_mma(const float* __restrict__ pos,
                const float* __restrict__ w1, const float* __restrict__ b1,
                const float* __restrict__ w2, const float* __restrict__ b2)
{
    extern __shared__ float sm[];
    uint32_t* B1u = (uint32_t*)(sm + OB1);
    uint32_t* B2u = (uint32_t*)(sm + OB2);
    float* sbuf = sm + OSB;
    float* hxs  = sm + OHX;
    float* sd   = sm + OSD;
    float* scc  = sm + OCC;
    int*   sil  = (int*)(sm + OIL);
    int*   sjl  = (int*)(sm + OJL);
    int*   siof = (int*)(sm + OIO);
    int*   sjof = (int*)(sm + OJO);
    int*   sjp  = (int*)(sm + OJP);
    float* sb1  = sm + OSB1;
    float* sb2  = sm + OSB2;
    float* ps   = sm + OPS;

    const int tid = threadIdx.x, wid = tid >> 5, lane = tid & 31;
    const int qr = lane >> 2, qc = lane & 3;

    // ---- build split-bf16 B tiles (stage via sbuf for coalescing) ----
    for (int i = tid; i < GDIM * 128; i += 256) sbuf[i] = w1[i];
    __syncthreads();
    for (int i = tid; i < 128 * 32; i += 256) {
        int kp = i >> 7, n = i & 127, k = kp * 2;
        float v0 = (k < GDIM)     ? sbuf[k * 128 + n]       : 0.f;
        float v1 = (k + 1 < GDIM) ? sbuf[(k + 1) * 128 + n] : 0.f;
        uint32_t h, l; split2(v0, v1, h, l);
        B1u[n * B1S + kp] = h;
        B1u[n * B1S + 32 + kp] = l;
    }
    __syncthreads();
    for (int i = tid; i < 128 * 128; i += 256) sbuf[i] = w2[i];
    __syncthreads();
    for (int i = tid; i < 128 * 64; i += 256) {
        int kp = i >> 7, n = i & 127, k = kp * 2;
        float v0 = sbuf[k * 128 + n], v1 = sbuf[(k + 1) * 128 + n];
        uint32_t h, l; split2(v0, v1, h, l);
        B2u[n * B2S + kp] = h;
        B2u[n * B2S + 64 + kp] = l;
    }
    if (tid < 128) { sb1[tid] = b1[tid]; sb2[tid] = b2[tid]; }
    __syncthreads();

    const float step  = CUTOFF / (GDIM - 1);
    const float coeff = -0.5f / (step * step);
    const float PIOC  = 3.14159265358979f / CUTOFF;
    const int a_own = tid >> 3, c_own = (tid & 7) * 16;
    const int r0 = wid * 16 + qr;

    for (int m = blockIdx.x; m < NMOL; m += gridDim.x) {
        int nu = g_ucnt[m];
        int nt = (nu + 127) / 128;
        for (int i = tid; i < APM * 128; i += 256) {
            int a = i >> 7, c = i & 127;
            hxs[a * HXS + c] = g_hx[(long)(m * APM + a) * 128 + c];
        }
        if (tid < 96) ps[tid] = pos[m * 96 + tid];
        float4 agg0 = make_float4(0,0,0,0), agg1 = agg0, agg2 = agg0, agg3 = agg0;
        __syncthreads();

        for (int t = 0; t < nt; t++) {
            if (tid < 128) {
                int k = t * 128 + tid;
                float d = 0.f, cc = 0.f; int il = 0, jl = 0;
                if (k < nu) {
                    unsigned pk = g_upak[m * 512 + k];
                    il = (int)(pk >> 8); jl = (int)(pk & 255);
                    float dx = ps[3*il]   - ps[3*jl];
                    float dy = ps[3*il+1] - ps[3*jl+1];
                    float dz = ps[3*il+2] - ps[3*jl+2];
                    d = sqrtf(dx*dx + dy*dy + dz*dz);
                    cc = 0.5f * (cosf(d * PIOC) + 1.f);
                }
                sd[tid] = d; scc[tid] = cc; sil[tid] = il; sjl[tid] = jl;
                sjp[tid] = g_jperm[m * 512 + t * 128 + tid];
            }
            if (tid >= 128 && tid < 161) siof[tid - 128] = g_ioff[(m * 4 + t) * 33 + tid - 128];
            if (tid >= 192 && tid < 225) sjof[tid - 192] = g_joff[(m * 4 + t) * 33 + tid - 192];
            __syncthreads();

            float dv0 = sd[r0], dv1 = sd[r0 + 8];

            // ---- ea A-fragments (computed once) ----
            uint32_t aH[4][4], aL[4][4];
            #pragma unroll
            for (int ks = 0; ks < 4; ks++) {
                float g0 = (float)(ks * 16 + 2 * qc) * step;
                eaf(dv0, g0,            step, coeff, aH[ks][0], aL[ks][0]);
                eaf(dv1, g0,            step, coeff, aH[ks][1], aL[ks][1]);
                eaf(dv0, g0 + 8.f*step, step, coeff, aH[ks][2], aL[ks][2]);
                eaf(dv1, g0 + 8.f*step, step, coeff, aH[ks][3], aL[ks][3]);
            }

            // ---- GEMM1 (per-nb acc, activation immediately) ----
            uint32_t tAh[16], tBh[16], tAl[16], tBl[16];
            #pragma unroll
            for (int nb = 0; nb < 16; nb++) {
                float acc[4] = {0.f, 0.f, 0.f, 0.f};
                #pragma unroll
                for (int ks = 0; ks < 4; ks++) {
                    int noff = (nb * 8 + qr) * B1S + ks * 8 + qc;
                    uint32_t bh0 = B1u[noff], bh1 = B1u[noff + 4];
                    mma16816(acc, aH[ks][0], aH[ks][1], aH[ks][2], aH[ks][3], bh0, bh1);
                    mma16816(acc, aL[ks][0], aL[ks][1], aL[ks][2], aL[ks][3], bh0, bh1);
                    uint32_t bl0 = B1u[noff + 32], bl1 = B1u[noff + 36];
                    mma16816(acc, aH[ks][0], aH[ks][1], aH[ks][2], aH[ks][3], bl0, bl1);
                }
                int c = nb * 8 + 2 * qc;
                float bx = sb1[c], by = sb1[c + 1];
                split2(sspf(acc[0] + bx), sspf(acc[1] + by), tAh[nb], tAl[nb]);
                split2(sspf(acc[2] + bx), sspf(acc[3] + by), tBh[nb], tBl[nb]);
            }

            // ---- GEMM2 in two 64-column halves; write w = (D+b2)*cc ----
            float cc0 = scc[r0], cc1 = scc[r0 + 8];
            #pragma unroll
            for (int half = 0; half < 2; half++) {
                float acc2[8][4];
                #pragma unroll
                for (int nb = 0; nb < 8; nb++) {
                    acc2[nb][0]=0.f; acc2[nb][1]=0.f; acc2[nb][2]=0.f; acc2[nb][3]=0.f;
                }
                #pragma unroll
                for (int ks = 0; ks < 8; ks++) {
                    #pragma unroll
                    for (int nb = 0; nb < 8; nb++) {
                        int noff = ((half * 8 + nb) * 8 + qr) * B2S + ks * 8 + qc;
                        uint32_t bh0 = B2u[noff], bh1 = B2u[noff + 4];
                        mma16816(acc2[nb], tAh[2*ks], tBh[2*ks], tAh[2*ks+1], tBh[2*ks+1], bh0, bh1);
                        mma16816(acc2[nb], tAl[2*ks], tBl[2*ks], tAl[2*ks+1], tBl[2*ks+1], bh0, bh1);
                        uint32_t bl0 = B2u[noff + 64], bl1 = B2u[noff + 68];
                        mma16816(acc2[nb], tAh[2*ks], tBh[2*ks], tAh[2*ks+1], tBh[2*ks+1], bl0, bl1);
                    }
                }
                #pragma unroll
                for (int nb = 0; nb < 8; nb++) {
                    int c = (half * 8 + nb) * 8 + 2 * qc;
                    float bx = sb2[c], by = sb2[c + 1];
                    *(float2*)&sbuf[r0 * SBS + c] =
                        make_float2((acc2[nb][0] + bx) * cc0, (acc2[nb][1] + by) * cc0);
                    *(float2*)&sbuf[(r0 + 8) * SBS + c] =
                        make_float2((acc2[nb][2] + bx) * cc1, (acc2[nb][3] + by) * cc1);
                }
            }
            __syncthreads();

            // ---- both-direction segmented reduction into register agg ----
            {
                int a = a_own;
                for (int r = siof[a]; r < siof[a + 1]; r++) {
                    const float4* wp = (const float4*)&sbuf[r * SBS + c_own];
                    const float4* hp = (const float4*)&hxs[sjl[r] * HXS + c_own];
                    float4 w0 = wp[0], w1v = wp[1], w2v = wp[2], w3 = wp[3];
                    float4 h0 = hp[0], h1 = hp[1], h2 = hp[2], h3 = hp[3];
                    agg0.x += w0.x*h0.x; agg0.y += w0.y*h0.y; agg0.z += w0.z*h0.z; agg0.w += w0.w*h0.w;
                    agg1.x += w1v.x*h1.x; agg1.y += w1v.y*h1.y; agg1.z += w1v.z*h1.z; agg1.w += w1v.w*h1.w;
                    agg2.x += w2v.x*h2.x; agg2.y += w2v.y*h2.y; agg2.z += w2v.z*h2.z; agg2.w += w2v.w*h2.w;
                    agg3.x += w3.x*h3.x; agg3.y += w3.y*h3.y; agg3.z += w3.z*h3.z; agg3.w += w3.w*h3.w;
                }
                for (int kk = sjof[a]; kk < sjof[a + 1]; kk++) {
                    int r = sjp[kk];
                    const float4* wp = (const float4*)&sbuf[r * SBS + c_own];
                    const float4* hp = (const float4*)&hxs[sil[r] * HXS + c_own];
                    float4 w0 = wp[0], w1v = wp[1], w2v = wp[2], w3 = wp[3];
                    float4 h0 = hp[0], h1 = hp[1], h2 = hp[2], h3 = hp[3];
                    agg0.x += w0.x*h0.x; agg0.y += w0.y*h0.y; agg0.z += w0.z*h0.z; agg0.w += w0.w*h0.w;
                    agg1.x += w1v.x*h1.x; agg1.y += w1v.y*h1.y; agg1.z += w1v.z*h1.z; agg1.w += w1v.w*h1.w;
                    agg2.x += w2v.x*h2.x; agg2.y += w2v.y*h2.y; agg2.z += w2v.z*h2.z; agg2.w += w2v.w*h2.w;
                    agg3.x += w3.x*h3.x; agg3.y += w3.y*h3.y; agg3.z += w3.z*h3.z; agg3.w += w3.w*h3.w;
                }
            }
            __syncthreads();
        }

        float* ap = g_agg + (long)(m * APM + a_own) * 128 + c_own;
        ((float4*)ap)[0] = agg0;
        ((float4*)ap)[1] = agg1;
        ((float4*)ap)[2] = agg2;
        ((float4*)ap)[3] = agg3;
        __syncthreads();
    }
}

// ---------------------------------------------------------------------------
__global__ __launch_bounds__(256) void k_out(
    const float* __restrict__ out1_w, const float* __restrict__ out1_b,
    const float* __restrict__ out2_w, const float* __restrict__ out2_b,
    const int* __restrict__ batch, float* __restrict__ out)
{
    __shared__ float W1[128 * 64];
    __shared__ float w2s[64];
    __shared__ float xs[8][128];

    int tid = threadIdx.x;
    for (int i = tid; i < 128 * 64; i += 256) W1[i] = out1_w[i];
    if (tid < 64) w2s[tid] = out2_w[tid];
    __syncthreads();

    int warp = tid >> 5, lane = tid & 31;
    float ob0 = out1_b[lane], ob1 = out1_b[lane + 32];
    float b2v = out2_b[0];

    for (int row = blockIdx.x * 8 + warp; row < NATOMS; row += gridDim.x * 8) {
        ((float4*)xs[warp])[lane] = ((const float4*)(g_h + (long)row * 128))[lane];
        __syncwarp();
        float a0 = ob0, a1 = ob1;
        #pragma unroll 8
        for (int k = 0; k < 128; k++) {
            float xv = xs[warp][k];
            a0 += xv * W1[k * 64 + lane];
            a1 += xv * W1[k * 64 + lane + 32];
        }
        float v = sspf(a0) * w2s[lane] + sspf(a1) * w2s[lane + 32];
        #pragma unroll
        for (int off = 16; off; off >>= 1) v += __shfl_down_sync(0xffffffffu, v, off);
        if (lane == 0) atomicAdd(&out[batch[row]], v + b2v);
        __syncwarp();
    }
}

// ---------------------------------------------------------------------------
extern "C" void kernel_launch(void* const* d_in, const int* in_sizes, int n_in,
                              void* d_out, int out_size)
{
    const int*   z       = (const int*)  d_in[0];
    const float* pos     = (const float*)d_in[1];
    const int*   batch   = (const int*)  d_in[2];
    const int*   ei      = (const int*)  d_in[3];
    const float* emb     = (const float*)d_in[4];
    const float* mlp_w1  = (const float*)d_in[5];
    const float* mlp_b1  = (const float*)d_in[6];
    const float* mlp_w2  = (const float*)d_in[7];
    const float* mlp_b2  = (const float*)d_in[8];
    const float* cf1_w   = (const float*)d_in[9];
    const float* cf2_w   = (const float*)d_in[10];
    const float* cf2_b   = (const float*)d_in[11];
    const float* lin_w   = (const float*)d_in[12];
    const float* lin_b   = (const float*)d_in[13];
    const float* out1_w  = (const float*)d_in[14];
    const float* out1_b  = (const float*)d_in[15];
    const float* out2_w  = (const float*)d_in[16];
    const float* out2_b  = (const float*)d_in[17];

    int E = in_sizes[3] / 2;
    const int* src = ei;
    const int* dst = ei + E;

    const int GEMM_SMEM = (16384 + 8 * 1024) * 4;
    cudaFuncSetAttribute(k_edge_mma, cudaFuncAttributeMaxDynamicSharedMemorySize, EDGE_SMEM_BYTES);
    cudaFuncSetAttribute(k_gemmx<false,false>, cudaFuncAttributeMaxDynamicSharedMemorySize, GEMM_SMEM);
    cudaFuncSetAttribute(k_gemmx<true ,false>, cudaFuncAttributeMaxDynamicSharedMemorySize, GEMM_SMEM);
    cudaFuncSetAttribute(k_gemmx<false,true >, cudaFuncAttributeMaxDynamicSharedMemorySize, GEMM_SMEM);

    float *ph, *phx, *pagg, *ptmp;
    cudaGetSymbolAddress((void**)&ph,   g_h);
    cudaGetSymbolAddress((void**)&phx,  g_hx);
    cudaGetSymbolAddress((void**)&pagg, g_agg);
    cudaGetSymbolAddress((void**)&ptmp, g_tmp);

    float* out = (float*)d_out;

    k_moff<<<3, 256>>>(src, E);
    k_prep<<<NMOL, 128>>>(src, dst);
    k_embed<<<(NATOMS*HDIM + 255)/256, 256>>>(z, emb);

    for (int l = 0; l < LINT; l++) {
        k_gemmx<false,false><<<256, 256, GEMM_SMEM>>>(
            ph, cf1_w + (long)l*HDIM*HDIM, nullptr, phx, NATOMS);
        k_edge_mma<<<148, 256, EDGE_SMEM_BYTES>>>(
            pos,
            mlp_w1 + (long)l*GDIM*HDIM, mlp_b1 + (long)l*HDIM,
            mlp_w2 + (long)l*HDIM*HDIM, mlp_b2 + (long)l*HDIM);
        k_gemmx<true,false><<<256, 256, GEMM_SMEM>>>(
            pagg, cf2_w + (long)l*HDIM*HDIM, cf2_b + (long)l*HDIM, ptmp, NATOMS);
        k_gemmx<false,true><<<256, 256, GEMM_SMEM>>>(
            ptmp, lin_w + (long)l*HDIM*HDIM, lin_b + (long)l*HDIM, ph, NATOMS);
    }

    k_zero_out<<<1, 512>>>(out);
    k_out<<<256, 256>>>(out1_w, out1_b, out2_w, out2_b, batch, out);
}

// round 6
// speedup vs baseline: 1.8822x; 1.0963x over previous
#include <cuda_runtime.h>
#include <cuda_bf16.h>
#include <math.h>
#include <stdint.h>

#define NATOMS 16384
#define NMOL   512
#define APM    32
#define HDIM   128
#define GDIM   50
#define LINT   3
#define CUTOFF 6.0f

typedef unsigned long long ull;

// Scratch (allocation-free)
__device__ float g_h  [NATOMS * HDIM];
__device__ float g_hx [NATOMS * HDIM];
__device__ float g_agg[NATOMS * HDIM];
__device__ float g_tmp[NATOMS * HDIM];
__device__ int   g_moff[NMOL + 1];
__device__ int   g_ucnt[NMOL];
__device__ unsigned g_upak[NMOL * 512];
__device__ int   g_ioff[NMOL * 4 * 33];
__device__ int   g_joff[NMOL * 4 * 33];
__device__ int   g_jperm[NMOL * 512];

__device__ __forceinline__ float sspf(float x) {
    const float LN2 = 0.6931471805599453f;
    if (x > 20.f) return x - LN2;
    return __logf(1.f + __expf(x)) - LN2;
}
__device__ __forceinline__ void split2(float v0, float v1, uint32_t& hi, uint32_t& lo) {
    __nv_bfloat16 h0 = __float2bfloat16(v0), h1 = __float2bfloat16(v1);
    __nv_bfloat16 l0 = __float2bfloat16(v0 - __bfloat162float(h0));
    __nv_bfloat16 l1 = __float2bfloat16(v1 - __bfloat162float(h1));
    hi = (uint32_t)__bfloat16_as_ushort(h0) | ((uint32_t)__bfloat16_as_ushort(h1) << 16);
    lo = (uint32_t)__bfloat16_as_ushort(l0) | ((uint32_t)__bfloat16_as_ushort(l1) << 16);
}
__device__ __forceinline__ void mma16816(float* d,
    uint32_t a0, uint32_t a1, uint32_t a2, uint32_t a3, uint32_t b0, uint32_t b1) {
    asm volatile(
        "mma.sync.aligned.m16n8k16.row.col.f32.bf16.bf16.f32 "
        "{%0,%1,%2,%3}, {%4,%5,%6,%7}, {%8,%9}, {%0,%1,%2,%3};"
        : "+f"(d[0]), "+f"(d[1]), "+f"(d[2]), "+f"(d[3])
        : "r"(a0), "r"(a1), "r"(a2), "r"(a3), "r"(b0), "r"(b1));
}
__device__ __forceinline__ void eaf(float d, float gofs, float step, float coeff,
                                    uint32_t& hi, uint32_t& lo) {
    float u0 = d - gofs, u1 = d - gofs - step;
    float e0 = __expf(coeff * u0 * u0);
    float e1 = __expf(coeff * u1 * u1);
    split2(e0, e1, hi, lo);
}

// ---------------------------------------------------------------------------
__global__ void k_embed(const int* __restrict__ z, const float* __restrict__ emb) {
    int i = blockIdx.x * blockDim.x + threadIdx.x;
    if (i < NATOMS * HDIM) {
        int a = i >> 7, f = i & 127;
        g_h[i] = emb[z[a] * HDIM + f];
    }
}
__global__ void k_zero_out(float* out) {
    int i = blockIdx.x * blockDim.x + threadIdx.x;
    if (i < NMOL) out[i] = 0.f;
}
__global__ void k_moff(const int* __restrict__ src, int E) {
    int m = blockIdx.x * blockDim.x + threadIdx.x;
    if (m > NMOL) return;
    int target = m * APM;
    int lo = 0, hi = E;
    while (lo < hi) { int mid = (lo + hi) >> 1; if (src[mid] < target) lo = mid + 1; else hi = mid; }
    g_moff[m] = lo;
}

// ---------------------------------------------------------------------------
// Prepass (unchanged from R5)
// ---------------------------------------------------------------------------
__global__ __launch_bounds__(128) void k_prep(const int* __restrict__ src,
                                              const int* __restrict__ dst) {
    __shared__ unsigned spak[128];
    __shared__ int scnt2[33];
    __shared__ int snu;
    int m = blockIdx.x;
    int tid = threadIdx.x, lane = tid & 31, wid = tid >> 5;
    int e0 = g_moff[m], e1 = g_moff[m + 1];

    if (wid == 0) {
        int cnt = 0;
        for (int base = e0; base < e1; base += 32) {
            int e = base + lane;
            bool p = false; unsigned pk = 0;
            if (e < e1) {
                int s = src[e] - m * APM, d2 = dst[e] - m * APM;
                if (d2 > s) { p = true; pk = (unsigned)((s << 8) | d2); }
            }
            unsigned msk = __ballot_sync(0xffffffffu, p);
            if (p) g_upak[m * 512 + cnt + __popc(msk & ((1u << lane) - 1))] = pk;
            cnt += __popc(msk);
        }
        if (lane == 0) { g_ucnt[m] = cnt; snu = cnt; }
    }
    __syncthreads();
    int nu = snu;
    int nt = (nu + 127) / 128;

    for (int t = 0; t < nt; t++) {
        int nr = nu - t * 128; if (nr > 128) nr = 128;
        if (tid < 128) spak[tid] = (tid < nr) ? g_upak[m * 512 + t * 128 + tid] : 0xffffffffu;
        __syncthreads();
        if (wid == 0) {
            int a = lane, c = 0;
            for (int r = 0; r < nr; r++) c += ((int)(spak[r] >> 8) < a) ? 1 : 0;
            g_ioff[(m * 4 + t) * 33 + a] = c;
            if (lane == 0) g_ioff[(m * 4 + t) * 33 + 32] = nr;
        }
        if (wid == 1) {
            int a = lane, c = 0;
            for (int r = 0; r < nr; r++) c += ((int)(spak[r] & 255) == a) ? 1 : 0;
            int x = c;
            #pragma unroll
            for (int o = 1; o < 32; o <<= 1) {
                int y = __shfl_up_sync(0xffffffffu, x, o);
                if (lane >= o) x += y;
            }
            int excl = x - c;
            g_joff[(m * 4 + t) * 33 + a] = excl;
            scnt2[a] = excl;
            if (lane == 31) g_joff[(m * 4 + t) * 33 + 32] = excl + c;
        }
        __syncthreads();
        if (tid == 0) {
            for (int r = 0; r < nr; r++) {
                int j = (int)(spak[r] & 255);
                g_jperm[m * 512 + t * 128 + scnt2[j]] = r;
                scnt2[j]++;
            }
        }
        __syncthreads();
    }
}

// ---------------------------------------------------------------------------
// HMMA node GEMM: y = [ADDTO? y +] act(x @ W + b).  One CTA per 128-row tile.
// W split-bf16 in SMEM (stride 132 u32, conflict-free), X pre-split (stride 68).
// ---------------------------------------------------------------------------
#define NG_BS 132
#define NG_XS 68
#define NG_SMEM ((128*NG_BS + 2*128*NG_XS + 128) * 4)

template<bool ACT, bool ADDTO>
__global__ __launch_bounds__(256, 1) void k_gemm_mma(
    const float* __restrict__ x, const float* __restrict__ W,
    const float* __restrict__ b, float* __restrict__ y, int nrows)
{
    extern __shared__ uint32_t smu[];
    uint32_t* Bu = smu;                      // 128 * 132
    uint32_t* Xh = smu + 128 * NG_BS;        // 128 * 68
    uint32_t* Xl = Xh + 128 * NG_XS;         // 128 * 68
    float*    sb = (float*)(Xl + 128 * NG_XS);

    const int tid = threadIdx.x, wid = tid >> 5, lane = tid & 31;
    const int qr = lane >> 2, qc = lane & 3;

    // stage W (split hi/lo)
    for (int i = tid; i < 128 * 64; i += 256) {
        int kp = i >> 7, n = i & 127;
        float v0 = W[(2 * kp) * 128 + n];
        float v1 = W[(2 * kp + 1) * 128 + n];
        uint32_t h, l; split2(v0, v1, h, l);
        Bu[n * NG_BS + kp] = h;
        Bu[n * NG_BS + 64 + kp] = l;
    }
    if (tid < 128) sb[tid] = b ? b[tid] : 0.f;

    const int r0 = wid * 16 + qr;

    for (int base = blockIdx.x * 128; base < nrows; base += gridDim.x * 128) {
        // stage X rows (split hi/lo, packed pairs)
        __syncthreads();
        for (int i = tid; i < 128 * 64; i += 256) {
            int row = i >> 6, kp = i & 63;
            float2 v = *(const float2*)(x + (long)(base + row) * 128 + 2 * kp);
            uint32_t h, l; split2(v.x, v.y, h, l);
            Xh[row * NG_XS + kp] = h;
            Xl[row * NG_XS + kp] = l;
        }
        __syncthreads();

        float acc[16][4];
        #pragma unroll
        for (int nb = 0; nb < 16; nb++) {
            acc[nb][0]=0.f; acc[nb][1]=0.f; acc[nb][2]=0.f; acc[nb][3]=0.f;
        }

        #pragma unroll
        for (int ks = 0; ks < 8; ks++) {
            int xo0 = r0 * NG_XS + ks * 8 + qc;
            int xo1 = (r0 + 8) * NG_XS + ks * 8 + qc;
            uint32_t aH0 = Xh[xo0],     aH1 = Xh[xo1];
            uint32_t aH2 = Xh[xo0 + 4], aH3 = Xh[xo1 + 4];
            uint32_t aL0 = Xl[xo0],     aL1 = Xl[xo1];
            uint32_t aL2 = Xl[xo0 + 4], aL3 = Xl[xo1 + 4];
            #pragma unroll
            for (int nb = 0; nb < 16; nb++) {
                int noff = (nb * 8 + qr) * NG_BS + ks * 8 + qc;
                uint32_t bh0 = Bu[noff], bh1 = Bu[noff + 4];
                mma16816(acc[nb], aH0, aH1, aH2, aH3, bh0, bh1);
                mma16816(acc[nb], aL0, aL1, aL2, aL3, bh0, bh1);
                uint32_t bl0 = Bu[noff + 64], bl1 = Bu[noff + 68];
                mma16816(acc[nb], aH0, aH1, aH2, aH3, bl0, bl1);
            }
        }

        #pragma unroll
        for (int nb = 0; nb < 16; nb++) {
            int c = nb * 8 + 2 * qc;
            float bx = sb[c], by = sb[c + 1];
            float v0 = acc[nb][0] + bx, v1 = acc[nb][1] + by;
            float v2 = acc[nb][2] + bx, v3 = acc[nb][3] + by;
            if (ACT) { v0 = sspf(v0); v1 = sspf(v1); v2 = sspf(v2); v3 = sspf(v3); }
            float* y0 = y + (long)(base + r0) * 128 + c;
            float* y1 = y + (long)(base + r0 + 8) * 128 + c;
            if (ADDTO) {
                float2 p0 = *(float2*)y0; v0 += p0.x; v1 += p0.y;
                float2 p1 = *(float2*)y1; v2 += p1.x; v3 += p1.y;
            }
            *(float2*)y0 = make_float2(v0, v1);
            *(float2*)y1 = make_float2(v2, v3);
        }
    }
}

// ---------------------------------------------------------------------------
// HMMA edge kernel on UNDIRECTED edges (unchanged from R5)
// ---------------------------------------------------------------------------
#define B1S 68
#define B2S 132
#define SBS 136
#define HXS 132
#define OB1  0
#define OB2  8704
#define OSB  25600
#define OHX  43008
#define OSD  47232
#define OCC  47360
#define OIL  47488
#define OJL  47616
#define OIO  47744
#define OJO  47778
#define OJP  47812
#define OSB1 47940
#define OSB2 48068
#define OPS  48196
#define SMW  48292
#define EDGE_SMEM_BYTES (SMW * 4)

__global__ __launch_bounds__(256, 1)
void k_edge_mma(const float* __restrict__ pos,
                const float* __restrict__ w1, const float* __restrict__ b1,
                const float* __restrict__ w2, const float* __restrict__ b2)
{
    extern __shared__ float sm[];
    uint32_t* B1u = (uint32_t*)(sm + OB1);
    uint32_t* B2u = (uint32_t*)(sm + OB2);
    float* sbuf = sm + OSB;
    float* hxs  = sm + OHX;
    float* sd   = sm + OSD;
    float* scc  = sm + OCC;
    int*   sil  = (int*)(sm + OIL);
    int*   sjl  = (int*)(sm + OJL);
    int*   siof = (int*)(sm + OIO);
    int*   sjof = (int*)(sm + OJO);
    int*   sjp  = (int*)(sm + OJP);
    float* sb1  = sm + OSB1;
    float* sb2  = sm + OSB2;
    float* ps   = sm + OPS;

    const int tid = threadIdx.x, wid = tid >> 5, lane = tid & 31;
    const int qr = lane >> 2, qc = lane & 3;

    for (int i = tid; i < GDIM * 128; i += 256) sbuf[i] = w1[i];
    __syncthreads();
    for (int i = tid; i < 128 * 32; i += 256) {
        int kp = i >> 7, n = i & 127, k = kp * 2;
        float v0 = (k < GDIM)     ? sbuf[k * 128 + n]       : 0.f;
        float v1 = (k + 1 < GDIM) ? sbuf[(k + 1) * 128 + n] : 0.f;
        uint32_t h, l; split2(v0, v1, h, l);
        B1u[n * B1S + kp] = h;
        B1u[n * B1S + 32 + kp] = l;
    }
    __syncthreads();
    for (int i = tid; i < 128 * 128; i += 256) sbuf[i] = w2[i];
    __syncthreads();
    for (int i = tid; i < 128 * 64; i += 256) {
        int kp = i >> 7, n = i & 127, k = kp * 2;
        float v0 = sbuf[k * 128 + n], v1 = sbuf[(k + 1) * 128 + n];
        uint32_t h, l; split2(v0, v1, h, l);
        B2u[n * B2S + kp] = h;
        B2u[n * B2S + 64 + kp] = l;
    }
    if (tid < 128) { sb1[tid] = b1[tid]; sb2[tid] = b2[tid]; }
    __syncthreads();

    const float step  = CUTOFF / (GDIM - 1);
    const float coeff = -0.5f / (step * step);
    const float PIOC  = 3.14159265358979f / CUTOFF;
    const int a_own = tid >> 3, c_own = (tid & 7) * 16;
    const int r0 = wid * 16 + qr;

    for (int m = blockIdx.x; m < NMOL; m += gridDim.x) {
        int nu = g_ucnt[m];
        int nt = (nu + 127) / 128;
        for (int i = tid; i < APM * 128; i += 256) {
            int a = i >> 7, c = i & 127;
            hxs[a * HXS + c] = g_hx[(long)(m * APM + a) * 128 + c];
        }
        if (tid < 96) ps[tid] = pos[m * 96 + tid];
        float4 agg0 = make_float4(0,0,0,0), agg1 = agg0, agg2 = agg0, agg3 = agg0;
        __syncthreads();

        for (int t = 0; t < nt; t++) {
            if (tid < 128) {
                int k = t * 128 + tid;
                float d = 0.f, cc = 0.f; int il = 0, jl = 0;
                if (k < nu) {
                    unsigned pk = g_upak[m * 512 + k];
                    il = (int)(pk >> 8); jl = (int)(pk & 255);
                    float dx = ps[3*il]   - ps[3*jl];
                    float dy = ps[3*il+1] - ps[3*jl+1];
                    float dz = ps[3*il+2] - ps[3*jl+2];
                    d = sqrtf(dx*dx + dy*dy + dz*dz);
                    cc = 0.5f * (cosf(d * PIOC) + 1.f);
                }
                sd[tid] = d; scc[tid] = cc; sil[tid] = il; sjl[tid] = jl;
                sjp[tid] = g_jperm[m * 512 + t * 128 + tid];
            }
            if (tid >= 128 && tid < 161) siof[tid - 128] = g_ioff[(m * 4 + t) * 33 + tid - 128];
            if (tid >= 192 && tid < 225) sjof[tid - 192] = g_joff[(m * 4 + t) * 33 + tid - 192];
            __syncthreads();

            float dv0 = sd[r0], dv1 = sd[r0 + 8];

            uint32_t aH[4][4], aL[4][4];
            #pragma unroll
            for (int ks = 0; ks < 4; ks++) {
                float g0 = (float)(ks * 16 + 2 * qc) * step;
                eaf(dv0, g0,            step, coeff, aH[ks][0], aL[ks][0]);
                eaf(dv1, g0,            step, coeff, aH[ks][1], aL[ks][1]);
                eaf(dv0, g0 + 8.f*step, step, coeff, aH[ks][2], aL[ks][2]);
                eaf(dv1, g0 + 8.f*step, step, coeff, aH[ks][3], aL[ks][3]);
            }

            uint32_t tAh[16], tBh[16], tAl[16], tBl[16];
            #pragma unroll
            for (int nb = 0; nb < 16; nb++) {
                float acc[4] = {0.f, 0.f, 0.f, 0.f};
                #pragma unroll
                for (int ks = 0; ks < 4; ks++) {
                    int noff = (nb * 8 + qr) * B1S + ks * 8 + qc;
                    uint32_t bh0 = B1u[noff], bh1 = B1u[noff + 4];
                    mma16816(acc, aH[ks][0], aH[ks][1], aH[ks][2], aH[ks][3], bh0, bh1);
                    mma16816(acc, aL[ks][0], aL[ks][1], aL[ks][2], aL[ks][3], bh0, bh1);
                    uint32_t bl0 = B1u[noff + 32], bl1 = B1u[noff + 36];
                    mma16816(acc, aH[ks][0], aH[ks][1], aH[ks][2], aH[ks][3], bl0, bl1);
                }
                int c = nb * 8 + 2 * qc;
                float bx = sb1[c], by = sb1[c + 1];
                split2(sspf(acc[0] + bx), sspf(acc[1] + by), tAh[nb], tAl[nb]);
                split2(sspf(acc[2] + bx), sspf(acc[3] + by), tBh[nb], tBl[nb]);
            }

            float cc0 = scc[r0], cc1 = scc[r0 + 8];
            #pragma unroll
            for (int half = 0; half < 2; half++) {
                float acc2[8][4];
                #pragma unroll
                for (int nb = 0; nb < 8; nb++) {
                    acc2[nb][0]=0.f; acc2[nb][1]=0.f; acc2[nb][2]=0.f; acc2[nb][3]=0.f;
                }
                #pragma unroll
                for (int ks = 0; ks < 8; ks++) {
                    #pragma unroll
                    for (int nb = 0; nb < 8; nb++) {
                        int noff = ((half * 8 + nb) * 8 + qr) * B2S + ks * 8 + qc;
                        uint32_t bh0 = B2u[noff], bh1 = B2u[noff + 4];
                        mma16816(acc2[nb], tAh[2*ks], tBh[2*ks], tAh[2*ks+1], tBh[2*ks+1], bh0, bh1);
                        mma16816(acc2[nb], tAl[2*ks], tBl[2*ks], tAl[2*ks+1], tBl[2*ks+1], bh0, bh1);
                        uint32_t bl0 = B2u[noff + 64], bl1 = B2u[noff + 68];
                        mma16816(acc2[nb], tAh[2*ks], tBh[2*ks], tAh[2*ks+1], tBh[2*ks+1], bl0, bl1);
                    }
                }
                #pragma unroll
                for (int nb = 0; nb < 8; nb++) {
                    int c = (half * 8 + nb) * 8 + 2 * qc;
                    float bx = sb2[c], by = sb2[c + 1];
                    *(float2*)&sbuf[r0 * SBS + c] =
                        make_float2((acc2[nb][0] + bx) * cc0, (acc2[nb][1] + by) * cc0);
                    *(float2*)&sbuf[(r0 + 8) * SBS + c] =
                        make_float2((acc2[nb][2] + bx) * cc1, (acc2[nb][3] + by) * cc1);
                }
            }
            __syncthreads();

            {
                int a = a_own;
                for (int r = siof[a]; r < siof[a + 1]; r++) {
                    const float4* wp = (const float4*)&sbuf[r * SBS + c_own];
                    const float4* hp = (const float4*)&hxs[sjl[r] * HXS + c_own];
                    float4 w0 = wp[0], w1v = wp[1], w2v = wp[2], w3 = wp[3];
                    float4 h0 = hp[0], h1 = hp[1], h2 = hp[2], h3 = hp[3];
                    agg0.x += w0.x*h0.x; agg0.y += w0.y*h0.y; agg0.z += w0.z*h0.z; agg0.w += w0.w*h0.w;
                    agg1.x += w1v.x*h1.x; agg1.y += w1v.y*h1.y; agg1.z += w1v.z*h1.z; agg1.w += w1v.w*h1.w;
                    agg2.x += w2v.x*h2.x; agg2.y += w2v.y*h2.y; agg2.z += w2v.z*h2.z; agg2.w += w2v.w*h2.w;
                    agg3.x += w3.x*h3.x; agg3.y += w3.y*h3.y; agg3.z += w3.z*h3.z; agg3.w += w3.w*h3.w;
                }
                for (int kk = sjof[a]; kk < sjof[a + 1]; kk++) {
                    int r = sjp[kk];
                    const float4* wp = (const float4*)&sbuf[r * SBS + c_own];
                    const float4* hp = (const float4*)&hxs[sil[r] * HXS + c_own];
                    float4 w0 = wp[0], w1v = wp[1], w2v = wp[2], w3 = wp[3];
                    float4 h0 = hp[0], h1 = hp[1], h2 = hp[2], h3 = hp[3];
                    agg0.x += w0.x*h0.x; agg0.y += w0.y*h0.y; agg0.z += w0.z*h0.z; agg0.w += w0.w*h0.w;
                    agg1.x += w1v.x*h1.x; agg1.y += w1v.y*h1.y; agg1.z += w1v.z*h1.z; agg1.w += w1v.w*h1.w;
                    agg2.x += w2v.x*h2.x; agg2.y += w2v.y*h2.y; agg2.z += w2v.z*h2.z; agg2.w += w2v.w*h2.w;
                    agg3.x += w3.x*h3.x; agg3.y += w3.y*h3.y; agg3.z += w3.z*h3.z; agg3.w += w3.w*h3.w;
                }
            }
            __syncthreads();
        }

        float* ap = g_agg + (long)(m * APM + a_own) * 128 + c_own;
        ((float4*)ap)[0] = agg0;
        ((float4*)ap)[1] = agg1;
        ((float4*)ap)[2] = agg2;
        ((float4*)ap)[3] = agg3;
        __syncthreads();
    }
}

// ---------------------------------------------------------------------------
__global__ __launch_bounds__(256) void k_out(
    const float* __restrict__ out1_w, const float* __restrict__ out1_b,
    const float* __restrict__ out2_w, const float* __restrict__ out2_b,
    const int* __restrict__ batch, float* __restrict__ out)
{
    __shared__ float W1[128 * 64];
    __shared__ float w2s[64];
    __shared__ float xs[8][128];

    int tid = threadIdx.x;
    for (int i = tid; i < 128 * 64; i += 256) W1[i] = out1_w[i];
    if (tid < 64) w2s[tid] = out2_w[tid];
    __syncthreads();

    int warp = tid >> 5, lane = tid & 31;
    float ob0 = out1_b[lane], ob1 = out1_b[lane + 32];
    float b2v = out2_b[0];

    for (int row = blockIdx.x * 8 + warp; row < NATOMS; row += gridDim.x * 8) {
        ((float4*)xs[warp])[lane] = ((const float4*)(g_h + (long)row * 128))[lane];
        __syncwarp();
        float a0 = ob0, a1 = ob1;
        #pragma unroll 8
        for (int k = 0; k < 128; k++) {
            float xv = xs[warp][k];
            a0 += xv * W1[k * 64 + lane];
            a1 += xv * W1[k * 64 + lane + 32];
        }
        float v = sspf(a0) * w2s[lane] + sspf(a1) * w2s[lane + 32];
        #pragma unroll
        for (int off = 16; off; off >>= 1) v += __shfl_down_sync(0xffffffffu, v, off);
        if (lane == 0) atomicAdd(&out[batch[row]], v + b2v);
        __syncwarp();
    }
}

// ---------------------------------------------------------------------------
extern "C" void kernel_launch(void* const* d_in, const int* in_sizes, int n_in,
                              void* d_out, int out_size)
{
    const int*   z       = (const int*)  d_in[0];
    const float* pos     = (const float*)d_in[1];
    const int*   batch   = (const int*)  d_in[2];
    const int*   ei      = (const int*)  d_in[3];
    const float* emb     = (const float*)d_in[4];
    const float* mlp_w1  = (const float*)d_in[5];
    const float* mlp_b1  = (const float*)d_in[6];
    const float* mlp_w2  = (const float*)d_in[7];
    const float* mlp_b2  = (const float*)d_in[8];
    const float* cf1_w   = (const float*)d_in[9];
    const float* cf2_w   = (const float*)d_in[10];
    const float* cf2_b   = (const float*)d_in[11];
    const float* lin_w   = (const float*)d_in[12];
    const float* lin_b   = (const float*)d_in[13];
    const float* out1_w  = (const float*)d_in[14];
    const float* out1_b  = (const float*)d_in[15];
    const float* out2_w  = (const float*)d_in[16];
    const float* out2_b  = (const float*)d_in[17];

    int E = in_sizes[3] / 2;
    const int* src = ei;
    const int* dst = ei + E;

    cudaFuncSetAttribute(k_edge_mma, cudaFuncAttributeMaxDynamicSharedMemorySize, EDGE_SMEM_BYTES);
    cudaFuncSetAttribute(k_gemm_mma<false,false>, cudaFuncAttributeMaxDynamicSharedMemorySize, NG_SMEM);
    cudaFuncSetAttribute(k_gemm_mma<true ,false>, cudaFuncAttributeMaxDynamicSharedMemorySize, NG_SMEM);
    cudaFuncSetAttribute(k_gemm_mma<false,true >, cudaFuncAttributeMaxDynamicSharedMemorySize, NG_SMEM);

    float *ph, *phx, *pagg, *ptmp;
    cudaGetSymbolAddress((void**)&ph,   g_h);
    cudaGetSymbolAddress((void**)&phx,  g_hx);
    cudaGetSymbolAddress((void**)&pagg, g_agg);
    cudaGetSymbolAddress((void**)&ptmp, g_tmp);

    float* out = (float*)d_out;

    k_moff<<<3, 256>>>(src, E);
    k_prep<<<NMOL, 128>>>(src, dst);
    k_embed<<<(NATOMS*HDIM + 255)/256, 256>>>(z, emb);

    for (int l = 0; l < LINT; l++) {
        k_gemm_mma<false,false><<<128, 256, NG_SMEM>>>(
            ph, cf1_w + (long)l*HDIM*HDIM, nullptr, phx, NATOMS);
        k_edge_mma<<<148, 256, EDGE_SMEM_BYTES>>>(
            pos,
            mlp_w1 + (long)l*GDIM*HDIM, mlp_b1 + (long)l*HDIM,
            mlp_w2 + (long)l*HDIM*HDIM, mlp_b2 + (long)l*HDIM);
        k_gemm_mma<true,false><<<128, 256, NG_SMEM>>>(
            pagg, cf2_w + (long)l*HDIM*HDIM, cf2_b + (long)l*HDIM, ptmp, NATOMS);
        k_gemm_mma<false,true><<<128, 256, NG_SMEM>>>(
            ptmp, lin_w + (long)l*HDIM*HDIM, lin_b + (long)l*HDIM, ph, NATOMS);
    }

    k_zero_out<<<1, 512>>>(out);
    k_out<<<256, 256>>>(out1_w, out1_b, out2_w, out2_b, batch, out);
}

// round 7
// speedup vs baseline: 2.1942x; 1.1658x over previous
#include <cuda_runtime.h>
#include <cuda_bf16.h>
#include <math.h>
#include <stdint.h>

#define NATOMS 16384
#define NMOL   512
#define APM    32
#define HDIM   128
#define GDIM   50
#define LINT   3
#define CUTOFF 6.0f

// Scratch (allocation-free)
__device__ float g_h  [NATOMS * HDIM];
__device__ float g_hx [NATOMS * HDIM];
__device__ float g_agg[NATOMS * HDIM];
__device__ int   g_moff[NMOL + 1];
__device__ int   g_ucnt[NMOL];
__device__ unsigned g_upak[NMOL * 512];
__device__ int   g_ioff[NMOL * 4 * 33];
__device__ int   g_joff[NMOL * 4 * 33];
__device__ int   g_jperm[NMOL * 512];

__device__ __forceinline__ float sspf(float x) {
    const float LN2 = 0.6931471805599453f;
    if (x > 20.f) return x - LN2;
    return __logf(1.f + __expf(x)) - LN2;
}
__device__ __forceinline__ void split2(float v0, float v1, uint32_t& hi, uint32_t& lo) {
    __nv_bfloat16 h0 = __float2bfloat16(v0), h1 = __float2bfloat16(v1);
    __nv_bfloat16 l0 = __float2bfloat16(v0 - __bfloat162float(h0));
    __nv_bfloat16 l1 = __float2bfloat16(v1 - __bfloat162float(h1));
    hi = (uint32_t)__bfloat16_as_ushort(h0) | ((uint32_t)__bfloat16_as_ushort(h1) << 16);
    lo = (uint32_t)__bfloat16_as_ushort(l0) | ((uint32_t)__bfloat16_as_ushort(l1) << 16);
}
__device__ __forceinline__ void mma16816(float* d,
    uint32_t a0, uint32_t a1, uint32_t a2, uint32_t a3, uint32_t b0, uint32_t b1) {
    asm volatile(
        "mma.sync.aligned.m16n8k16.row.col.f32.bf16.bf16.f32 "
        "{%0,%1,%2,%3}, {%4,%5,%6,%7}, {%8,%9}, {%0,%1,%2,%3};"
        : "+f"(d[0]), "+f"(d[1]), "+f"(d[2]), "+f"(d[3])
        : "r"(a0), "r"(a1), "r"(a2), "r"(a3), "r"(b0), "r"(b1));
}
__device__ __forceinline__ void eaf(float d, float gofs, float step, float coeff,
                                    uint32_t& hi, uint32_t& lo) {
    float u0 = d - gofs, u1 = d - gofs - step;
    float e0 = __expf(coeff * u0 * u0);
    float e1 = __expf(coeff * u1 * u1);
    split2(e0, e1, hi, lo);
}

// ---------------------------------------------------------------------------
__global__ void k_embed(const int* __restrict__ z, const float* __restrict__ emb) {
    int i = blockIdx.x * blockDim.x + threadIdx.x;
    if (i < NATOMS * HDIM) {
        int a = i >> 7, f = i & 127;
        g_h[i] = emb[z[a] * HDIM + f];
    }
}
__global__ void k_zero_out(float* out) {
    int i = blockIdx.x * blockDim.x + threadIdx.x;
    if (i < NMOL) out[i] = 0.f;
}
__global__ void k_moff(const int* __restrict__ src, int E) {
    int m = blockIdx.x * blockDim.x + threadIdx.x;
    if (m > NMOL) return;
    int target = m * APM;
    int lo = 0, hi = E;
    while (lo < hi) { int mid = (lo + hi) >> 1; if (src[mid] < target) lo = mid + 1; else hi = mid; }
    g_moff[m] = lo;
}

// ---------------------------------------------------------------------------
// Prepass (unchanged)
// ---------------------------------------------------------------------------
__global__ __launch_bounds__(128) void k_prep(const int* __restrict__ src,
                                              const int* __restrict__ dst) {
    __shared__ unsigned spak[128];
    __shared__ int scnt2[33];
    __shared__ int snu;
    int m = blockIdx.x;
    int tid = threadIdx.x, lane = tid & 31, wid = tid >> 5;
    int e0 = g_moff[m], e1 = g_moff[m + 1];

    if (wid == 0) {
        int cnt = 0;
        for (int base = e0; base < e1; base += 32) {
            int e = base + lane;
            bool p = false; unsigned pk = 0;
            if (e < e1) {
                int s = src[e] - m * APM, d2 = dst[e] - m * APM;
                if (d2 > s) { p = true; pk = (unsigned)((s << 8) | d2); }
            }
            unsigned msk = __ballot_sync(0xffffffffu, p);
            if (p) g_upak[m * 512 + cnt + __popc(msk & ((1u << lane) - 1))] = pk;
            cnt += __popc(msk);
        }
        if (lane == 0) { g_ucnt[m] = cnt; snu = cnt; }
    }
    __syncthreads();
    int nu = snu;
    int nt = (nu + 127) / 128;

    for (int t = 0; t < nt; t++) {
        int nr = nu - t * 128; if (nr > 128) nr = 128;
        if (tid < 128) spak[tid] = (tid < nr) ? g_upak[m * 512 + t * 128 + tid] : 0xffffffffu;
        __syncthreads();
        if (wid == 0) {
            int a = lane, c = 0;
            for (int r = 0; r < nr; r++) c += ((int)(spak[r] >> 8) < a) ? 1 : 0;
            g_ioff[(m * 4 + t) * 33 + a] = c;
            if (lane == 0) g_ioff[(m * 4 + t) * 33 + 32] = nr;
        }
        if (wid == 1) {
            int a = lane, c = 0;
            for (int r = 0; r < nr; r++) c += ((int)(spak[r] & 255) == a) ? 1 : 0;
            int x = c;
            #pragma unroll
            for (int o = 1; o < 32; o <<= 1) {
                int y = __shfl_up_sync(0xffffffffu, x, o);
                if (lane >= o) x += y;
            }
            int excl = x - c;
            g_joff[(m * 4 + t) * 33 + a] = excl;
            scnt2[a] = excl;
            if (lane == 31) g_joff[(m * 4 + t) * 33 + 32] = excl + c;
        }
        __syncthreads();
        if (tid == 0) {
            for (int r = 0; r < nr; r++) {
                int j = (int)(spak[r] & 255);
                g_jperm[m * 512 + t * 128 + scnt2[j]] = r;
                scnt2[j]++;
            }
        }
        __syncthreads();
    }
}

// ---------------------------------------------------------------------------
// 16-warp node GEMM (no bias, no act): y = x @ W.  One CTA = 128 rows.
// Warp w: rows (w&7)*16, cols 64*(w>>3)..+63. A loaded from global.
// ---------------------------------------------------------------------------
#define N1_SMEM (128 * 132 * 4)

__global__ __launch_bounds__(512, 1) void k_n1(
    const float* __restrict__ x, const float* __restrict__ W, float* __restrict__ y)
{
    extern __shared__ uint32_t smu[];
    uint32_t* Bu = smu;
    const int tid = threadIdx.x, wid = tid >> 5, lane = tid & 31;
    const int half = wid >> 3, w8 = wid & 7;
    const int qr = lane >> 2, qc = lane & 3;

    for (int i = tid; i < 128 * 64; i += 512) {
        int kp = i >> 7, n = i & 127;
        uint32_t h, l;
        split2(W[(2 * kp) * 128 + n], W[(2 * kp + 1) * 128 + n], h, l);
        Bu[n * 132 + kp] = h;
        Bu[n * 132 + 64 + kp] = l;
    }
    __syncthreads();

    const int r0 = w8 * 16 + qr;
    const long base = (long)blockIdx.x * 128;

    float acc[8][4];
    #pragma unroll
    for (int nb = 0; nb < 8; nb++) { acc[nb][0]=0.f; acc[nb][1]=0.f; acc[nb][2]=0.f; acc[nb][3]=0.f; }

    #pragma unroll
    for (int ks = 0; ks < 8; ks++) {
        const float* xr = x + (base + r0) * 128 + ks * 16 + 2 * qc;
        float2 v00 = *(const float2*)xr;
        float2 v01 = *(const float2*)(xr + 8);
        float2 v10 = *(const float2*)(xr + 8 * 128);
        float2 v11 = *(const float2*)(xr + 8 * 128 + 8);
        uint32_t aH0,aH1,aH2,aH3,aL0,aL1,aL2,aL3;
        split2(v00.x, v00.y, aH0, aL0);
        split2(v10.x, v10.y, aH1, aL1);
        split2(v01.x, v01.y, aH2, aL2);
        split2(v11.x, v11.y, aH3, aL3);
        #pragma unroll
        for (int nb = 0; nb < 8; nb++) {
            int noff = ((half * 8 + nb) * 8 + qr) * 132 + ks * 8 + qc;
            uint32_t bh0 = Bu[noff], bh1 = Bu[noff + 4];
            mma16816(acc[nb], aH0, aH1, aH2, aH3, bh0, bh1);
            mma16816(acc[nb], aL0, aL1, aL2, aL3, bh0, bh1);
            uint32_t bl0 = Bu[noff + 64], bl1 = Bu[noff + 68];
            mma16816(acc[nb], aH0, aH1, aH2, aH3, bl0, bl1);
        }
    }

    #pragma unroll
    for (int nb = 0; nb < 8; nb++) {
        int c = (half * 8 + nb) * 8 + 2 * qc;
        *(float2*)(y + (base + r0) * 128 + c)     = make_float2(acc[nb][0], acc[nb][1]);
        *(float2*)(y + (base + r0 + 8) * 128 + c) = make_float2(acc[nb][2], acc[nb][3]);
    }
}

// ---------------------------------------------------------------------------
// 16-warp fused node chain: tmp = ssp(agg@W2 + b2); h += tmp@Wl + lb
// t1 exchanged via SMEM.
// ---------------------------------------------------------------------------
#define N2_OB1 0
#define N2_OB2 16896
#define N2_OT1 33792
#define N2_OS2 50688
#define N2_OSL 50816
#define N2_SMEM ((50944) * 4)

__global__ __launch_bounds__(512, 1) void k_n2(
    const float* __restrict__ agg,
    const float* __restrict__ W2, const float* __restrict__ b2,
    const float* __restrict__ Wl, const float* __restrict__ lb,
    float* __restrict__ h)
{
    extern __shared__ uint32_t smu[];
    uint32_t* Bu1 = smu + N2_OB1;
    uint32_t* Bu2 = smu + N2_OB2;
    uint32_t* T1  = smu + N2_OT1;
    float* sb2 = (float*)(smu + N2_OS2);
    float* slb = (float*)(smu + N2_OSL);

    const int tid = threadIdx.x, wid = tid >> 5, lane = tid & 31;
    const int half = wid >> 3, w8 = wid & 7;
    const int qr = lane >> 2, qc = lane & 3;

    for (int i = tid; i < 128 * 64; i += 512) {
        int kp = i >> 7, n = i & 127;
        uint32_t hh, ll;
        split2(W2[(2 * kp) * 128 + n], W2[(2 * kp + 1) * 128 + n], hh, ll);
        Bu1[n * 132 + kp] = hh; Bu1[n * 132 + 64 + kp] = ll;
        split2(Wl[(2 * kp) * 128 + n], Wl[(2 * kp + 1) * 128 + n], hh, ll);
        Bu2[n * 132 + kp] = hh; Bu2[n * 132 + 64 + kp] = ll;
    }
    if (tid < 128) { sb2[tid] = b2[tid]; slb[tid] = lb[tid]; }
    __syncthreads();

    const int r0 = w8 * 16 + qr;
    const long base = (long)blockIdx.x * 128;

    // GEMM1: agg @ W2
    {
        float acc[8][4];
        #pragma unroll
        for (int nb = 0; nb < 8; nb++) { acc[nb][0]=0.f; acc[nb][1]=0.f; acc[nb][2]=0.f; acc[nb][3]=0.f; }
        #pragma unroll
        for (int ks = 0; ks < 8; ks++) {
            const float* xr = agg + (base + r0) * 128 + ks * 16 + 2 * qc;
            float2 v00 = *(const float2*)xr;
            float2 v01 = *(const float2*)(xr + 8);
            float2 v10 = *(const float2*)(xr + 8 * 128);
            float2 v11 = *(const float2*)(xr + 8 * 128 + 8);
            uint32_t aH0,aH1,aH2,aH3,aL0,aL1,aL2,aL3;
            split2(v00.x, v00.y, aH0, aL0);
            split2(v10.x, v10.y, aH1, aL1);
            split2(v01.x, v01.y, aH2, aL2);
            split2(v11.x, v11.y, aH3, aL3);
            #pragma unroll
            for (int nb = 0; nb < 8; nb++) {
                int noff = ((half * 8 + nb) * 8 + qr) * 132 + ks * 8 + qc;
                uint32_t bh0 = Bu1[noff], bh1 = Bu1[noff + 4];
                mma16816(acc[nb], aH0, aH1, aH2, aH3, bh0, bh1);
                mma16816(acc[nb], aL0, aL1, aL2, aL3, bh0, bh1);
                uint32_t bl0 = Bu1[noff + 64], bl1 = Bu1[noff + 68];
                mma16816(acc[nb], aH0, aH1, aH2, aH3, bl0, bl1);
            }
        }
        // ssp + split -> T1
        #pragma unroll
        for (int nb = 0; nb < 8; nb++) {
            int c = (half * 8 + nb) * 8 + 2 * qc;
            int kp = (c >> 1);
            float bx = sb2[c], by = sb2[c + 1];
            uint32_t hh, ll;
            split2(sspf(acc[nb][0] + bx), sspf(acc[nb][1] + by), hh, ll);
            T1[r0 * 132 + kp] = hh; T1[r0 * 132 + 64 + kp] = ll;
            split2(sspf(acc[nb][2] + bx), sspf(acc[nb][3] + by), hh, ll);
            T1[(r0 + 8) * 132 + kp] = hh; T1[(r0 + 8) * 132 + 64 + kp] = ll;
        }
    }
    __syncthreads();

    // GEMM2: T1 @ Wl, residual into h
    {
        float acc[8][4];
        #pragma unroll
        for (int nb = 0; nb < 8; nb++) { acc[nb][0]=0.f; acc[nb][1]=0.f; acc[nb][2]=0.f; acc[nb][3]=0.f; }
        #pragma unroll
        for (int ks = 0; ks < 8; ks++) {
            int xo0 = r0 * 132 + ks * 8 + qc;
            int xo1 = (r0 + 8) * 132 + ks * 8 + qc;
            uint32_t aH0 = T1[xo0],      aH1 = T1[xo1];
            uint32_t aH2 = T1[xo0 + 4],  aH3 = T1[xo1 + 4];
            uint32_t aL0 = T1[xo0 + 64], aL1 = T1[xo1 + 64];
            uint32_t aL2 = T1[xo0 + 68], aL3 = T1[xo1 + 68];
            #pragma unroll
            for (int nb = 0; nb < 8; nb++) {
                int noff = ((half * 8 + nb) * 8 + qr) * 132 + ks * 8 + qc;
                uint32_t bh0 = Bu2[noff], bh1 = Bu2[noff + 4];
                mma16816(acc[nb], aH0, aH1, aH2, aH3, bh0, bh1);
                mma16816(acc[nb], aL0, aL1, aL2, aL3, bh0, bh1);
                uint32_t bl0 = Bu2[noff + 64], bl1 = Bu2[noff + 68];
                mma16816(acc[nb], aH0, aH1, aH2, aH3, bl0, bl1);
            }
        }
        #pragma unroll
        for (int nb = 0; nb < 8; nb++) {
            int c = (half * 8 + nb) * 8 + 2 * qc;
            float bx = slb[c], by = slb[c + 1];
            float* y0 = h + (base + r0) * 128 + c;
            float* y1 = h + (base + r0 + 8) * 128 + c;
            float2 p0 = *(float2*)y0, p1 = *(float2*)y1;
            *(float2*)y0 = make_float2(p0.x + acc[nb][0] + bx, p0.y + acc[nb][1] + by);
            *(float2*)y1 = make_float2(p1.x + acc[nb][2] + bx, p1.y + acc[nb][3] + by);
        }
    }
}

// ---------------------------------------------------------------------------
// 16-warp edge kernel (undirected). Warp w: rows (w&7)*16.., cols 64*(w>>3)..
// t1 exchanged through SMEM; same region reused as msg buffer.
// ---------------------------------------------------------------------------
#define EOB1 0
#define EOB2 8704
#define EOT1 25600
#define EOHX 42496
#define EOSD 46720
#define EOCC 46848
#define EOIL 46976
#define EOJL 47104
#define EOJP 47232
#define EOIO 47360
#define EOJO 47394
#define EOB1B 47428
#define EOB2B 47556
#define EOPS 47684
#define ESMW 47780
#define EDGE_SMEM_BYTES (ESMW * 4)

__global__ __launch_bounds__(512, 1)
void k_edge_mma(const float* __restrict__ pos,
                const float* __restrict__ w1, const float* __restrict__ b1,
                const float* __restrict__ w2, const float* __restrict__ b2)
{
    extern __shared__ uint32_t smu[];
    uint32_t* B1u = smu + EOB1;
    uint32_t* B2u = smu + EOB2;
    uint32_t* T1  = smu + EOT1;
    float* sbuf = (float*)(smu + EOT1);   // alias (msg after GEMM2)
    float* hxs  = (float*)(smu + EOHX);
    float* sd   = (float*)(smu + EOSD);
    float* scc  = (float*)(smu + EOCC);
    int*   sil  = (int*)(smu + EOIL);
    int*   sjl  = (int*)(smu + EOJL);
    int*   sjp  = (int*)(smu + EOJP);
    int*   siof = (int*)(smu + EOIO);
    int*   sjof = (int*)(smu + EOJO);
    float* sb1  = (float*)(smu + EOB1B);
    float* sb2  = (float*)(smu + EOB2B);
    float* ps   = (float*)(smu + EOPS);

    const int tid = threadIdx.x, wid = tid >> 5, lane = tid & 31;
    const int half = wid >> 3, w8 = wid & 7;
    const int qr = lane >> 2, qc = lane & 3;

    // stage split-bf16 weight tiles
    for (int i = tid; i < 128 * 32; i += 512) {
        int kp = i >> 7, n = i & 127, k = 2 * kp;
        float v0 = (k < GDIM)     ? w1[k * 128 + n]       : 0.f;
        float v1 = (k + 1 < GDIM) ? w1[(k + 1) * 128 + n] : 0.f;
        uint32_t h, l; split2(v0, v1, h, l);
        B1u[n * 68 + kp] = h;
        B1u[n * 68 + 32 + kp] = l;
    }
    for (int i = tid; i < 128 * 64; i += 512) {
        int kp = i >> 7, n = i & 127;
        uint32_t h, l;
        split2(w2[(2 * kp) * 128 + n], w2[(2 * kp + 1) * 128 + n], h, l);
        B2u[n * 132 + kp] = h;
        B2u[n * 132 + 64 + kp] = l;
    }
    if (tid < 128) { sb1[tid] = b1[tid]; sb2[tid] = b2[tid]; }
    __syncthreads();

    const float step  = CUTOFF / (GDIM - 1);
    const float coeff = -0.5f / (step * step);
    const float PIOC  = 3.14159265358979f / CUTOFF;
    const int a_own = tid >> 4, sub = tid & 15, c_own = sub * 8;
    const int r0 = w8 * 16 + qr;

    for (int m = blockIdx.x; m < NMOL; m += gridDim.x) {
        int nu = g_ucnt[m];
        int nt = (nu + 127) / 128;
        for (int i = tid; i < APM * 128; i += 512) {
            int a = i >> 7, c = i & 127;
            hxs[a * 132 + c] = g_hx[(long)(m * APM + a) * 128 + c];
        }
        if (tid < 96) ps[tid] = pos[m * 96 + tid];
        float4 agg0 = make_float4(0,0,0,0), agg1 = agg0;
        __syncthreads();

        for (int t = 0; t < nt; t++) {
            if (tid < 128) {
                int k = t * 128 + tid;
                float d = 0.f, cc = 0.f; int il = 0, jl = 0;
                if (k < nu) {
                    unsigned pk = g_upak[m * 512 + k];
                    il = (int)(pk >> 8); jl = (int)(pk & 255);
                    float dx = ps[3*il]   - ps[3*jl];
                    float dy = ps[3*il+1] - ps[3*jl+1];
                    float dz = ps[3*il+2] - ps[3*jl+2];
                    d = sqrtf(dx*dx + dy*dy + dz*dz);
                    cc = 0.5f * (cosf(d * PIOC) + 1.f);
                }
                sd[tid] = d; scc[tid] = cc; sil[tid] = il; sjl[tid] = jl;
                sjp[tid] = g_jperm[m * 512 + t * 128 + tid];
            }
            if (tid >= 128 && tid < 161) siof[tid - 128] = g_ioff[(m * 4 + t) * 33 + tid - 128];
            if (tid >= 192 && tid < 225) sjof[tid - 192] = g_joff[(m * 4 + t) * 33 + tid - 192];
            __syncthreads();

            float dv0 = sd[r0], dv1 = sd[r0 + 8];

            // ea A-fragments
            uint32_t aH[4][4], aL[4][4];
            #pragma unroll
            for (int ks = 0; ks < 4; ks++) {
                float g0 = (float)(ks * 16 + 2 * qc) * step;
                eaf(dv0, g0,            step, coeff, aH[ks][0], aL[ks][0]);
                eaf(dv1, g0,            step, coeff, aH[ks][1], aL[ks][1]);
                eaf(dv0, g0 + 8.f*step, step, coeff, aH[ks][2], aL[ks][2]);
                eaf(dv1, g0 + 8.f*step, step, coeff, aH[ks][3], aL[ks][3]);
            }

            // GEMM1 (our N-half) -> ssp -> T1
            #pragma unroll
            for (int nb = 0; nb < 8; nb++) {
                float acc[4] = {0.f, 0.f, 0.f, 0.f};
                #pragma unroll
                for (int ks = 0; ks < 4; ks++) {
                    int noff = ((half * 8 + nb) * 8 + qr) * 68 + ks * 8 + qc;
                    uint32_t bh0 = B1u[noff], bh1 = B1u[noff + 4];
                    mma16816(acc, aH[ks][0], aH[ks][1], aH[ks][2], aH[ks][3], bh0, bh1);
                    mma16816(acc, aL[ks][0], aL[ks][1], aL[ks][2], aL[ks][3], bh0, bh1);
                    uint32_t bl0 = B1u[noff + 32], bl1 = B1u[noff + 36];
                    mma16816(acc, aH[ks][0], aH[ks][1], aH[ks][2], aH[ks][3], bl0, bl1);
                }
                int c = (half * 8 + nb) * 8 + 2 * qc;
                int kp = c >> 1;
                float bx = sb1[c], by = sb1[c + 1];
                uint32_t hh, ll;
                split2(sspf(acc[0] + bx), sspf(acc[1] + by), hh, ll);
                T1[r0 * 132 + kp] = hh; T1[r0 * 132 + 64 + kp] = ll;
                split2(sspf(acc[2] + bx), sspf(acc[3] + by), hh, ll);
                T1[(r0 + 8) * 132 + kp] = hh; T1[(r0 + 8) * 132 + 64 + kp] = ll;
            }
            __syncthreads();

            // GEMM2 (our N-half), A from T1
            float acc2[8][4];
            #pragma unroll
            for (int nb = 0; nb < 8; nb++) { acc2[nb][0]=0.f; acc2[nb][1]=0.f; acc2[nb][2]=0.f; acc2[nb][3]=0.f; }
            #pragma unroll
            for (int ks = 0; ks < 8; ks++) {
                int xo0 = r0 * 132 + ks * 8 + qc;
                int xo1 = (r0 + 8) * 132 + ks * 8 + qc;
                uint32_t aH0 = T1[xo0],      aH1 = T1[xo1];
                uint32_t aH2 = T1[xo0 + 4],  aH3 = T1[xo1 + 4];
                uint32_t aL0 = T1[xo0 + 64], aL1 = T1[xo1 + 64];
                uint32_t aL2 = T1[xo0 + 68], aL3 = T1[xo1 + 68];
                #pragma unroll
                for (int nb = 0; nb < 8; nb++) {
                    int noff = ((half * 8 + nb) * 8 + qr) * 132 + ks * 8 + qc;
                    uint32_t bh0 = B2u[noff], bh1 = B2u[noff + 4];
                    mma16816(acc2[nb], aH0, aH1, aH2, aH3, bh0, bh1);
                    mma16816(acc2[nb], aL0, aL1, aL2, aL3, bh0, bh1);
                    uint32_t bl0 = B2u[noff + 64], bl1 = B2u[noff + 68];
                    mma16816(acc2[nb], aH0, aH1, aH2, aH3, bl0, bl1);
                }
            }
            __syncthreads();   // all T1 reads done before msg overwrites

            float cc0 = scc[r0], cc1 = scc[r0 + 8];
            #pragma unroll
            for (int nb = 0; nb < 8; nb++) {
                int c = (half * 8 + nb) * 8 + 2 * qc;
                float bx = sb2[c], by = sb2[c + 1];
                *(float2*)&sbuf[r0 * 132 + c] =
                    make_float2((acc2[nb][0] + bx) * cc0, (acc2[nb][1] + by) * cc0);
                *(float2*)&sbuf[(r0 + 8) * 132 + c] =
                    make_float2((acc2[nb][2] + bx) * cc1, (acc2[nb][3] + by) * cc1);
            }
            __syncthreads();

            // both-direction segmented reduction (16 threads per atom, 8 cols each)
            for (int r = siof[a_own]; r < siof[a_own + 1]; r++) {
                float4 w0 = *(const float4*)&sbuf[r * 132 + c_own];
                float4 w1v = *(const float4*)&sbuf[r * 132 + c_own + 4];
                const float* hp = &hxs[sjl[r] * 132 + c_own];
                float4 h0 = *(const float4*)hp, h1 = *(const float4*)(hp + 4);
                agg0.x += w0.x*h0.x; agg0.y += w0.y*h0.y; agg0.z += w0.z*h0.z; agg0.w += w0.w*h0.w;
                agg1.x += w1v.x*h1.x; agg1.y += w1v.y*h1.y; agg1.z += w1v.z*h1.z; agg1.w += w1v.w*h1.w;
            }
            for (int kk = sjof[a_own]; kk < sjof[a_own + 1]; kk++) {
                int r = sjp[kk];
                float4 w0 = *(const float4*)&sbuf[r * 132 + c_own];
                float4 w1v = *(const float4*)&sbuf[r * 132 + c_own + 4];
                const float* hp = &hxs[sil[r] * 132 + c_own];
                float4 h0 = *(const float4*)hp, h1 = *(const float4*)(hp + 4);
                agg0.x += w0.x*h0.x; agg0.y += w0.y*h0.y; agg0.z += w0.z*h0.z; agg0.w += w0.w*h0.w;
                agg1.x += w1v.x*h1.x; agg1.y += w1v.y*h1.y; agg1.z += w1v.z*h1.z; agg1.w += w1v.w*h1.w;
            }
            __syncthreads();
        }

        float* ap = g_agg + (long)(m * APM + a_own) * 128 + c_own;
        *(float4*)ap = agg0;
        *(float4*)(ap + 4) = agg1;
        __syncthreads();
    }
}

// ---------------------------------------------------------------------------
__global__ __launch_bounds__(256) void k_out(
    const float* __restrict__ out1_w, const float* __restrict__ out1_b,
    const float* __restrict__ out2_w, const float* __restrict__ out2_b,
    const int* __restrict__ batch, float* __restrict__ out)
{
    __shared__ float W1[128 * 64];
    __shared__ float w2s[64];
    __shared__ float xs[8][128];

    int tid = threadIdx.x;
    for (int i = tid; i < 128 * 64; i += 256) W1[i] = out1_w[i];
    if (tid < 64) w2s[tid] = out2_w[tid];
    __syncthreads();

    int warp = tid >> 5, lane = tid & 31;
    float ob0 = out1_b[lane], ob1 = out1_b[lane + 32];
    float b2v = out2_b[0];

    for (int row = blockIdx.x * 8 + warp; row < NATOMS; row += gridDim.x * 8) {
        ((float4*)xs[warp])[lane] = ((const float4*)(g_h + (long)row * 128))[lane];
        __syncwarp();
        float a0 = ob0, a1 = ob1;
        #pragma unroll 8
        for (int k = 0; k < 128; k++) {
            float xv = xs[warp][k];
            a0 += xv * W1[k * 64 + lane];
            a1 += xv * W1[k * 64 + lane + 32];
        }
        float v = sspf(a0) * w2s[lane] + sspf(a1) * w2s[lane + 32];
        #pragma unroll
        for (int off = 16; off; off >>= 1) v += __shfl_down_sync(0xffffffffu, v, off);
        if (lane == 0) atomicAdd(&out[batch[row]], v + b2v);
        __syncwarp();
    }
}

// ---------------------------------------------------------------------------
extern "C" void kernel_launch(void* const* d_in, const int* in_sizes, int n_in,
                              void* d_out, int out_size)
{
    const int*   z       = (const int*)  d_in[0];
    const float* pos     = (const float*)d_in[1];
    const int*   batch   = (const int*)  d_in[2];
    const int*   ei      = (const int*)  d_in[3];
    const float* emb     = (const float*)d_in[4];
    const float* mlp_w1  = (const float*)d_in[5];
    const float* mlp_b1  = (const float*)d_in[6];
    const float* mlp_w2  = (const float*)d_in[7];
    const float* mlp_b2  = (const float*)d_in[8];
    const float* cf1_w   = (const float*)d_in[9];
    const float* cf2_w   = (const float*)d_in[10];
    const float* cf2_b   = (const float*)d_in[11];
    const float* lin_w   = (const float*)d_in[12];
    const float* lin_b   = (const float*)d_in[13];
    const float* out1_w  = (const float*)d_in[14];
    const float* out1_b  = (const float*)d_in[15];
    const float* out2_w  = (const float*)d_in[16];
    const float* out2_b  = (const float*)d_in[17];

    int E = in_sizes[3] / 2;
    const int* src = ei;
    const int* dst = ei + E;

    cudaFuncSetAttribute(k_edge_mma, cudaFuncAttributeMaxDynamicSharedMemorySize, EDGE_SMEM_BYTES);
    cudaFuncSetAttribute(k_n1, cudaFuncAttributeMaxDynamicSharedMemorySize, N1_SMEM);
    cudaFuncSetAttribute(k_n2, cudaFuncAttributeMaxDynamicSharedMemorySize, N2_SMEM);

    float *ph, *phx, *pagg;
    cudaGetSymbolAddress((void**)&ph,   g_h);
    cudaGetSymbolAddress((void**)&phx,  g_hx);
    cudaGetSymbolAddress((void**)&pagg, g_agg);

    float* out = (float*)d_out;

    k_moff<<<3, 256>>>(src, E);
    k_prep<<<NMOL, 128>>>(src, dst);
    k_embed<<<(NATOMS*HDIM + 255)/256, 256>>>(z, emb);

    for (int l = 0; l < LINT; l++) {
        k_n1<<<128, 512, N1_SMEM>>>(ph, cf1_w + (long)l*HDIM*HDIM, phx);
        k_edge_mma<<<148, 512, EDGE_SMEM_BYTES>>>(
            pos,
            mlp_w1 + (long)l*GDIM*HDIM, mlp_b1 + (long)l*HDIM,
            mlp_w2 + (long)l*HDIM*HDIM, mlp_b2 + (long)l*HDIM);
        k_n2<<<128, 512, N2_SMEM>>>(
            pagg, cf2_w + (long)l*HDIM*HDIM, cf2_b + (long)l*HDIM,
            lin_w + (long)l*HDIM*HDIM, lin_b + (long)l*HDIM, ph);
    }

    k_zero_out<<<1, 512>>>(out);
    k_out<<<256, 256>>>(out1_w, out1_b, out2_w, out2_b, batch, out);
}

// round 8
// speedup vs baseline: 3.4397x; 1.5677x over previous
#include <cuda_runtime.h>
#include <cuda_bf16.h>
#include <math.h>
#include <stdint.h>

#define NATOMS 16384
#define NMOL   512
#define APM    32
#define HDIM   128
#define GDIM   50
#define LINT   3
#define CUTOFF 6.0f
#define TAB_N  8192

// Scratch (allocation-free)
__device__ float g_h  [NATOMS * HDIM];
__device__ float g_hx [NATOMS * HDIM];
__device__ float g_agg[NATOMS * HDIM];
__device__ int   g_moff[NMOL + 1];
__device__ int   g_ucnt[NMOL];
__device__ unsigned g_upak[NMOL * 512];
__device__ int   g_ioff[NMOL * 4 * 33];
__device__ int   g_joff[NMOL * 4 * 33];
__device__ int   g_jperm[NMOL * 512];
__device__ float g_wtab[LINT * (TAB_N + 1) * HDIM];   // 12.6 MB

__device__ __forceinline__ float sspf(float x) {
    const float LN2 = 0.6931471805599453f;
    if (x > 20.f) return x - LN2;
    return __logf(1.f + __expf(x)) - LN2;
}
__device__ __forceinline__ void split2(float v0, float v1, uint32_t& hi, uint32_t& lo) {
    __nv_bfloat16 h0 = __float2bfloat16(v0), h1 = __float2bfloat16(v1);
    __nv_bfloat16 l0 = __float2bfloat16(v0 - __bfloat162float(h0));
    __nv_bfloat16 l1 = __float2bfloat16(v1 - __bfloat162float(h1));
    hi = (uint32_t)__bfloat16_as_ushort(h0) | ((uint32_t)__bfloat16_as_ushort(h1) << 16);
    lo = (uint32_t)__bfloat16_as_ushort(l0) | ((uint32_t)__bfloat16_as_ushort(l1) << 16);
}
__device__ __forceinline__ void mma16816(float* d,
    uint32_t a0, uint32_t a1, uint32_t a2, uint32_t a3, uint32_t b0, uint32_t b1) {
    asm volatile(
        "mma.sync.aligned.m16n8k16.row.col.f32.bf16.bf16.f32 "
        "{%0,%1,%2,%3}, {%4,%5,%6,%7}, {%8,%9}, {%0,%1,%2,%3};"
        : "+f"(d[0]), "+f"(d[1]), "+f"(d[2]), "+f"(d[3])
        : "r"(a0), "r"(a1), "r"(a2), "r"(a3), "r"(b0), "r"(b1));
}
__device__ __forceinline__ void eaf(float d, float gofs, float step, float coeff,
                                    uint32_t& hi, uint32_t& lo) {
    float u0 = d - gofs, u1 = d - gofs - step;
    float e0 = __expf(coeff * u0 * u0);
    float e1 = __expf(coeff * u1 * u1);
    split2(e0, e1, hi, lo);
}

// ---------------------------------------------------------------------------
__global__ void k_embed(const int* __restrict__ z, const float* __restrict__ emb) {
    int i = blockIdx.x * blockDim.x + threadIdx.x;
    if (i < NATOMS * HDIM) {
        int a = i >> 7, f = i & 127;
        g_h[i] = emb[z[a] * HDIM + f];
    }
}
__global__ void k_zero_out(float* out) {
    int i = blockIdx.x * blockDim.x + threadIdx.x;
    if (i < NMOL) out[i] = 0.f;
}
__global__ void k_ztab() {
    g_wtab[((long)blockIdx.x * (TAB_N + 1) + TAB_N) * HDIM + threadIdx.x] = 0.f;
}
__global__ void k_moff(const int* __restrict__ src, int E) {
    int m = blockIdx.x * blockDim.x + threadIdx.x;
    if (m > NMOL) return;
    int target = m * APM;
    int lo = 0, hi = E;
    while (lo < hi) { int mid = (lo + hi) >> 1; if (src[mid] < target) lo = mid + 1; else hi = mid; }
    g_moff[m] = lo;
}

// ---------------------------------------------------------------------------
// Prepass (unchanged)
// ---------------------------------------------------------------------------
__global__ __launch_bounds__(128) void k_prep(const int* __restrict__ src,
                                              const int* __restrict__ dst) {
    __shared__ unsigned spak[128];
    __shared__ int scnt2[33];
    __shared__ int snu;
    int m = blockIdx.x;
    int tid = threadIdx.x, lane = tid & 31, wid = tid >> 5;
    int e0 = g_moff[m], e1 = g_moff[m + 1];

    if (wid == 0) {
        int cnt = 0;
        for (int base = e0; base < e1; base += 32) {
            int e = base + lane;
            bool p = false; unsigned pk = 0;
            if (e < e1) {
                int s = src[e] - m * APM, d2 = dst[e] - m * APM;
                if (d2 > s) { p = true; pk = (unsigned)((s << 8) | d2); }
            }
            unsigned msk = __ballot_sync(0xffffffffu, p);
            if (p) g_upak[m * 512 + cnt + __popc(msk & ((1u << lane) - 1))] = pk;
            cnt += __popc(msk);
        }
        if (lane == 0) { g_ucnt[m] = cnt; snu = cnt; }
    }
    __syncthreads();
    int nu = snu;
    int nt = (nu + 127) / 128;

    for (int t = 0; t < nt; t++) {
        int nr = nu - t * 128; if (nr > 128) nr = 128;
        if (tid < 128) spak[tid] = (tid < nr) ? g_upak[m * 512 + t * 128 + tid] : 0xffffffffu;
        __syncthreads();
        if (wid == 0) {
            int a = lane, c = 0;
            for (int r = 0; r < nr; r++) c += ((int)(spak[r] >> 8) < a) ? 1 : 0;
            g_ioff[(m * 4 + t) * 33 + a] = c;
            if (lane == 0) g_ioff[(m * 4 + t) * 33 + 32] = nr;
        }
        if (wid == 1) {
            int a = lane, c = 0;
            for (int r = 0; r < nr; r++) c += ((int)(spak[r] & 255) == a) ? 1 : 0;
            int x = c;
            #pragma unroll
            for (int o = 1; o < 32; o <<= 1) {
                int y = __shfl_up_sync(0xffffffffu, x, o);
                if (lane >= o) x += y;
            }
            int excl = x - c;
            g_joff[(m * 4 + t) * 33 + a] = excl;
            scnt2[a] = excl;
            if (lane == 31) g_joff[(m * 4 + t) * 33 + 32] = excl + c;
        }
        __syncthreads();
        if (tid == 0) {
            for (int r = 0; r < nr; r++) {
                int j = (int)(spak[r] & 255);
                g_jperm[m * 512 + t * 128 + scnt2[j]] = r;
                scnt2[j]++;
            }
        }
        __syncthreads();
    }
}

// ---------------------------------------------------------------------------
// 16-warp node GEMM (no bias, no act): y = x @ W (unchanged from R7)
// ---------------------------------------------------------------------------
#define N1_SMEM (128 * 132 * 4)

__global__ __launch_bounds__(512, 1) void k_n1(
    const float* __restrict__ x, const float* __restrict__ W, float* __restrict__ y)
{
    extern __shared__ uint32_t smu[];
    uint32_t* Bu = smu;
    const int tid = threadIdx.x, wid = tid >> 5, lane = tid & 31;
    const int half = wid >> 3, w8 = wid & 7;
    const int qr = lane >> 2, qc = lane & 3;

    for (int i = tid; i < 128 * 64; i += 512) {
        int kp = i >> 7, n = i & 127;
        uint32_t h, l;
        split2(W[(2 * kp) * 128 + n], W[(2 * kp + 1) * 128 + n], h, l);
        Bu[n * 132 + kp] = h;
        Bu[n * 132 + 64 + kp] = l;
    }
    __syncthreads();

    const int r0 = w8 * 16 + qr;
    const long base = (long)blockIdx.x * 128;

    float acc[8][4];
    #pragma unroll
    for (int nb = 0; nb < 8; nb++) { acc[nb][0]=0.f; acc[nb][1]=0.f; acc[nb][2]=0.f; acc[nb][3]=0.f; }

    #pragma unroll
    for (int ks = 0; ks < 8; ks++) {
        const float* xr = x + (base + r0) * 128 + ks * 16 + 2 * qc;
        float2 v00 = *(const float2*)xr;
        float2 v01 = *(const float2*)(xr + 8);
        float2 v10 = *(const float2*)(xr + 8 * 128);
        float2 v11 = *(const float2*)(xr + 8 * 128 + 8);
        uint32_t aH0,aH1,aH2,aH3,aL0,aL1,aL2,aL3;
        split2(v00.x, v00.y, aH0, aL0);
        split2(v10.x, v10.y, aH1, aL1);
        split2(v01.x, v01.y, aH2, aL2);
        split2(v11.x, v11.y, aH3, aL3);
        #pragma unroll
        for (int nb = 0; nb < 8; nb++) {
            int noff = ((half * 8 + nb) * 8 + qr) * 132 + ks * 8 + qc;
            uint32_t bh0 = Bu[noff], bh1 = Bu[noff + 4];
            mma16816(acc[nb], aH0, aH1, aH2, aH3, bh0, bh1);
            mma16816(acc[nb], aL0, aL1, aL2, aL3, bh0, bh1);
            uint32_t bl0 = Bu[noff + 64], bl1 = Bu[noff + 68];
            mma16816(acc[nb], aH0, aH1, aH2, aH3, bl0, bl1);
        }
    }

    #pragma unroll
    for (int nb = 0; nb < 8; nb++) {
        int c = (half * 8 + nb) * 8 + 2 * qc;
        *(float2*)(y + (base + r0) * 128 + c)     = make_float2(acc[nb][0], acc[nb][1]);
        *(float2*)(y + (base + r0 + 8) * 128 + c) = make_float2(acc[nb][2], acc[nb][3]);
    }
}

// ---------------------------------------------------------------------------
// 16-warp fused node chain (unchanged from R7)
// ---------------------------------------------------------------------------
#define N2_OB1 0
#define N2_OB2 16896
#define N2_OT1 33792
#define N2_OS2 50688
#define N2_OSL 50816
#define N2_SMEM ((50944) * 4)

__global__ __launch_bounds__(512, 1) void k_n2(
    const float* __restrict__ agg,
    const float* __restrict__ W2, const float* __restrict__ b2,
    const float* __restrict__ Wl, const float* __restrict__ lb,
    float* __restrict__ h)
{
    extern __shared__ uint32_t smu[];
    uint32_t* Bu1 = smu + N2_OB1;
    uint32_t* Bu2 = smu + N2_OB2;
    uint32_t* T1  = smu + N2_OT1;
    float* sb2 = (float*)(smu + N2_OS2);
    float* slb = (float*)(smu + N2_OSL);

    const int tid = threadIdx.x, wid = tid >> 5, lane = tid & 31;
    const int half = wid >> 3, w8 = wid & 7;
    const int qr = lane >> 2, qc = lane & 3;

    for (int i = tid; i < 128 * 64; i += 512) {
        int kp = i >> 7, n = i & 127;
        uint32_t hh, ll;
        split2(W2[(2 * kp) * 128 + n], W2[(2 * kp + 1) * 128 + n], hh, ll);
        Bu1[n * 132 + kp] = hh; Bu1[n * 132 + 64 + kp] = ll;
        split2(Wl[(2 * kp) * 128 + n], Wl[(2 * kp + 1) * 128 + n], hh, ll);
        Bu2[n * 132 + kp] = hh; Bu2[n * 132 + 64 + kp] = ll;
    }
    if (tid < 128) { sb2[tid] = b2[tid]; slb[tid] = lb[tid]; }
    __syncthreads();

    const int r0 = w8 * 16 + qr;
    const long base = (long)blockIdx.x * 128;

    {
        float acc[8][4];
        #pragma unroll
        for (int nb = 0; nb < 8; nb++) { acc[nb][0]=0.f; acc[nb][1]=0.f; acc[nb][2]=0.f; acc[nb][3]=0.f; }
        #pragma unroll
        for (int ks = 0; ks < 8; ks++) {
            const float* xr = agg + (base + r0) * 128 + ks * 16 + 2 * qc;
            float2 v00 = *(const float2*)xr;
            float2 v01 = *(const float2*)(xr + 8);
            float2 v10 = *(const float2*)(xr + 8 * 128);
            float2 v11 = *(const float2*)(xr + 8 * 128 + 8);
            uint32_t aH0,aH1,aH2,aH3,aL0,aL1,aL2,aL3;
            split2(v00.x, v00.y, aH0, aL0);
            split2(v10.x, v10.y, aH1, aL1);
            split2(v01.x, v01.y, aH2, aL2);
            split2(v11.x, v11.y, aH3, aL3);
            #pragma unroll
            for (int nb = 0; nb < 8; nb++) {
                int noff = ((half * 8 + nb) * 8 + qr) * 132 + ks * 8 + qc;
                uint32_t bh0 = Bu1[noff], bh1 = Bu1[noff + 4];
                mma16816(acc[nb], aH0, aH1, aH2, aH3, bh0, bh1);
                mma16816(acc[nb], aL0, aL1, aL2, aL3, bh0, bh1);
                uint32_t bl0 = Bu1[noff + 64], bl1 = Bu1[noff + 68];
                mma16816(acc[nb], aH0, aH1, aH2, aH3, bl0, bl1);
            }
        }
        #pragma unroll
        for (int nb = 0; nb < 8; nb++) {
            int c = (half * 8 + nb) * 8 + 2 * qc;
            int kp = (c >> 1);
            float bx = sb2[c], by = sb2[c + 1];
            uint32_t hh, ll;
            split2(sspf(acc[nb][0] + bx), sspf(acc[nb][1] + by), hh, ll);
            T1[r0 * 132 + kp] = hh; T1[r0 * 132 + 64 + kp] = ll;
            split2(sspf(acc[nb][2] + bx), sspf(acc[nb][3] + by), hh, ll);
            T1[(r0 + 8) * 132 + kp] = hh; T1[(r0 + 8) * 132 + 64 + kp] = ll;
        }
    }
    __syncthreads();

    {
        float acc[8][4];
        #pragma unroll
        for (int nb = 0; nb < 8; nb++) { acc[nb][0]=0.f; acc[nb][1]=0.f; acc[nb][2]=0.f; acc[nb][3]=0.f; }
        #pragma unroll
        for (int ks = 0; ks < 8; ks++) {
            int xo0 = r0 * 132 + ks * 8 + qc;
            int xo1 = (r0 + 8) * 132 + ks * 8 + qc;
            uint32_t aH0 = T1[xo0],      aH1 = T1[xo1];
            uint32_t aH2 = T1[xo0 + 4],  aH3 = T1[xo1 + 4];
            uint32_t aL0 = T1[xo0 + 64], aL1 = T1[xo1 + 64];
            uint32_t aL2 = T1[xo0 + 68], aL3 = T1[xo1 + 68];
            #pragma unroll
            for (int nb = 0; nb < 8; nb++) {
                int noff = ((half * 8 + nb) * 8 + qr) * 132 + ks * 8 + qc;
                uint32_t bh0 = Bu2[noff], bh1 = Bu2[noff + 4];
                mma16816(acc[nb], aH0, aH1, aH2, aH3, bh0, bh1);
                mma16816(acc[nb], aL0, aL1, aL2, aL3, bh0, bh1);
                uint32_t bl0 = Bu2[noff + 64], bl1 = Bu2[noff + 68];
                mma16816(acc[nb], aH0, aH1, aH2, aH3, bl0, bl1);
            }
        }
        #pragma unroll
        for (int nb = 0; nb < 8; nb++) {
            int c = (half * 8 + nb) * 8 + 2 * qc;
            float bx = slb[c], by = slb[c + 1];
            float* y0 = h + (base + r0) * 128 + c;
            float* y1 = h + (base + r0 + 8) * 128 + c;
            float2 p0 = *(float2*)y0, p1 = *(float2*)y1;
            *(float2*)y0 = make_float2(p0.x + acc[nb][0] + bx, p0.y + acc[nb][1] + by);
            *(float2*)y1 = make_float2(p1.x + acc[nb][2] + bx, p1.y + acc[nb][3] + by);
        }
    }
}

// ---------------------------------------------------------------------------
// Table builder: Wc(d) = (ssp(ea(d)@w1+b1)@w2 + b2) * Ccut(d), on TAB_N grid.
// One CTA = (layer, 128-d-point tile). Adapted from R7 edge GEMM machinery.
// ---------------------------------------------------------------------------
#define BLD_OB1 0
#define BLD_OB2 8704
#define BLD_OT1 25600
#define BLD_OS1 42496
#define BLD_OS2 42624
#define BLD_SMEM ((42752) * 4)

__global__ __launch_bounds__(512, 1)
void k_build(const float* __restrict__ w1all, const float* __restrict__ b1all,
             const float* __restrict__ w2all, const float* __restrict__ b2all)
{
    extern __shared__ uint32_t smu[];
    uint32_t* B1u = smu + BLD_OB1;
    uint32_t* B2u = smu + BLD_OB2;
    uint32_t* T1  = smu + BLD_OT1;
    float* sb1 = (float*)(smu + BLD_OS1);
    float* sb2 = (float*)(smu + BLD_OS2);

    const int l = blockIdx.x >> 6, t = blockIdx.x & 63;
    const float* w1 = w1all + (long)l * GDIM * HDIM;
    const float* b1 = b1all + (long)l * HDIM;
    const float* w2 = w2all + (long)l * HDIM * HDIM;
    const float* b2 = b2all + (long)l * HDIM;

    const int tid = threadIdx.x, wid = tid >> 5, lane = tid & 31;
    const int half = wid >> 3, w8 = wid & 7;
    const int qr = lane >> 2, qc = lane & 3;

    for (int i = tid; i < 128 * 32; i += 512) {
        int kp = i >> 7, n = i & 127, k = 2 * kp;
        float v0 = (k < GDIM)     ? w1[k * 128 + n]       : 0.f;
        float v1 = (k + 1 < GDIM) ? w1[(k + 1) * 128 + n] : 0.f;
        uint32_t h, lv; split2(v0, v1, h, lv);
        B1u[n * 68 + kp] = h;
        B1u[n * 68 + 32 + kp] = lv;
    }
    for (int i = tid; i < 128 * 64; i += 512) {
        int kp = i >> 7, n = i & 127;
        uint32_t h, lv;
        split2(w2[(2 * kp) * 128 + n], w2[(2 * kp + 1) * 128 + n], h, lv);
        B2u[n * 132 + kp] = h;
        B2u[n * 132 + 64 + kp] = lv;
    }
    if (tid < 128) { sb1[tid] = b1[tid]; sb2[tid] = b2[tid]; }
    __syncthreads();

    const float step  = CUTOFF / (GDIM - 1);
    const float coeff = -0.5f / (step * step);
    const float PIOC  = 3.14159265358979f / CUTOFF;
    const float DELTA = CUTOFF / (float)TAB_N;
    const int r0 = w8 * 16 + qr;

    float dv0 = (float)(t * 128 + r0) * DELTA;
    float dv1 = (float)(t * 128 + r0 + 8) * DELTA;

    uint32_t aH[4][4], aL[4][4];
    #pragma unroll
    for (int ks = 0; ks < 4; ks++) {
        float g0 = (float)(ks * 16 + 2 * qc) * step;
        eaf(dv0, g0,            step, coeff, aH[ks][0], aL[ks][0]);
        eaf(dv1, g0,            step, coeff, aH[ks][1], aL[ks][1]);
        eaf(dv0, g0 + 8.f*step, step, coeff, aH[ks][2], aL[ks][2]);
        eaf(dv1, g0 + 8.f*step, step, coeff, aH[ks][3], aL[ks][3]);
    }

    #pragma unroll
    for (int nb = 0; nb < 8; nb++) {
        float acc[4] = {0.f, 0.f, 0.f, 0.f};
        #pragma unroll
        for (int ks = 0; ks < 4; ks++) {
            int noff = ((half * 8 + nb) * 8 + qr) * 68 + ks * 8 + qc;
            uint32_t bh0 = B1u[noff], bh1 = B1u[noff + 4];
            mma16816(acc, aH[ks][0], aH[ks][1], aH[ks][2], aH[ks][3], bh0, bh1);
            mma16816(acc, aL[ks][0], aL[ks][1], aL[ks][2], aL[ks][3], bh0, bh1);
            uint32_t bl0 = B1u[noff + 32], bl1 = B1u[noff + 36];
            mma16816(acc, aH[ks][0], aH[ks][1], aH[ks][2], aH[ks][3], bl0, bl1);
        }
        int c = (half * 8 + nb) * 8 + 2 * qc;
        int kp = c >> 1;
        float bx = sb1[c], by = sb1[c + 1];
        uint32_t hh, ll;
        split2(sspf(acc[0] + bx), sspf(acc[1] + by), hh, ll);
        T1[r0 * 132 + kp] = hh; T1[r0 * 132 + 64 + kp] = ll;
        split2(sspf(acc[2] + bx), sspf(acc[3] + by), hh, ll);
        T1[(r0 + 8) * 132 + kp] = hh; T1[(r0 + 8) * 132 + 64 + kp] = ll;
    }
    __syncthreads();

    float acc2[8][4];
    #pragma unroll
    for (int nb = 0; nb < 8; nb++) { acc2[nb][0]=0.f; acc2[nb][1]=0.f; acc2[nb][2]=0.f; acc2[nb][3]=0.f; }
    #pragma unroll
    for (int ks = 0; ks < 8; ks++) {
        int xo0 = r0 * 132 + ks * 8 + qc;
        int xo1 = (r0 + 8) * 132 + ks * 8 + qc;
        uint32_t aH0 = T1[xo0],      aH1 = T1[xo1];
        uint32_t aH2 = T1[xo0 + 4],  aH3 = T1[xo1 + 4];
        uint32_t aL0 = T1[xo0 + 64], aL1 = T1[xo1 + 64];
        uint32_t aL2 = T1[xo0 + 68], aL3 = T1[xo1 + 68];
        #pragma unroll
        for (int nb = 0; nb < 8; nb++) {
            int noff = ((half * 8 + nb) * 8 + qr) * 132 + ks * 8 + qc;
            uint32_t bh0 = B2u[noff], bh1 = B2u[noff + 4];
            mma16816(acc2[nb], aH0, aH1, aH2, aH3, bh0, bh1);
            mma16816(acc2[nb], aL0, aL1, aL2, aL3, bh0, bh1);
            uint32_t bl0 = B2u[noff + 64], bl1 = B2u[noff + 68];
            mma16816(acc2[nb], aH0, aH1, aH2, aH3, bl0, bl1);
        }
    }

    float cc0 = 0.5f * (cosf(dv0 * PIOC) + 1.f);
    float cc1 = 0.5f * (cosf(dv1 * PIOC) + 1.f);
    float* trow = g_wtab + ((long)l * (TAB_N + 1) + t * 128 + r0) * 128;
    #pragma unroll
    for (int nb = 0; nb < 8; nb++) {
        int c = (half * 8 + nb) * 8 + 2 * qc;
        float bx = sb2[c], by = sb2[c + 1];
        *(float2*)(trow + c) =
            make_float2((acc2[nb][0] + bx) * cc0, (acc2[nb][1] + by) * cc0);
        *(float2*)(trow + 8 * 128 + c) =
            make_float2((acc2[nb][2] + bx) * cc1, (acc2[nb][3] + by) * cc1);
    }
}

// ---------------------------------------------------------------------------
// Table-lookup edge kernel: one CTA (256 thr) per molecule, 2 CTAs/SM.
// Per 128-edge tile: fill sbuf via table lerp, then both-direction segmented
// reduction into register agg (16 cols per thread).
// ---------------------------------------------------------------------------
#define ET_HX 0
#define ET_SB 4224
#define ET_SD 21120
#define ET_IL 21248
#define ET_JL 21376
#define ET_JP 21504
#define ET_IO 21632
#define ET_JO 21665
#define ET_PS 21698
#define ET_W  21794
#define ETAB_SMEM (ET_W * 4)

__global__ __launch_bounds__(256, 2)
void k_edge_tab(const float* __restrict__ pos, const float* __restrict__ wtab)
{
    extern __shared__ float sm[];
    float* hxs  = sm + ET_HX;     // 32 x 132
    float* sbuf = sm + ET_SB;     // 128 x 132
    float* sd   = sm + ET_SD;
    int*   sil  = (int*)(sm + ET_IL);
    int*   sjl  = (int*)(sm + ET_JL);
    int*   sjp  = (int*)(sm + ET_JP);
    int*   siof = (int*)(sm + ET_IO);
    int*   sjof = (int*)(sm + ET_JO);
    float* ps   = sm + ET_PS;

    const int tid = threadIdx.x, wid = tid >> 5, lane = tid & 31;
    const int m = blockIdx.x;
    const int a_own = tid >> 3, c_own = (tid & 7) * 16;
    const float SCALE = (float)TAB_N / CUTOFF;

    int nu = g_ucnt[m];
    int nt = (nu + 127) / 128;

    for (int i = tid; i < APM * 128; i += 256) {
        int a = i >> 7, c = i & 127;
        hxs[a * 132 + c] = g_hx[(long)(m * APM + a) * 128 + c];
    }
    if (tid < 96) ps[tid] = pos[m * 96 + tid];
    float4 agg0 = make_float4(0,0,0,0), agg1 = agg0, agg2 = agg0, agg3 = agg0;
    __syncthreads();

    for (int t = 0; t < nt; t++) {
        if (tid < 128) {
            int k = t * 128 + tid;
            float d = 0.f; int il = 0, jl = 0;
            if (k < nu) {
                unsigned pk = g_upak[m * 512 + k];
                il = (int)(pk >> 8); jl = (int)(pk & 255);
                float dx = ps[3*il]   - ps[3*jl];
                float dy = ps[3*il+1] - ps[3*jl+1];
                float dz = ps[3*il+2] - ps[3*jl+2];
                d = sqrtf(dx*dx + dy*dy + dz*dz);
            }
            sd[tid] = d; sil[tid] = il; sjl[tid] = jl;
            sjp[tid] = g_jperm[m * 512 + t * 128 + tid];
        }
        if (tid >= 128 && tid < 161) siof[tid - 128] = g_ioff[(m * 4 + t) * 33 + tid - 128];
        if (tid >= 192 && tid < 225) sjof[tid - 192] = g_joff[(m * 4 + t) * 33 + tid - 192];
        __syncthreads();

        // fill sbuf: w(e, :) = lerp(table)
        for (int e = wid; e < 128; e += 8) {
            float d = sd[e];
            float tt = d * SCALE;
            int i0 = (int)tt;
            i0 = (i0 > TAB_N - 1) ? (TAB_N - 1) : i0;
            float f = tt - (float)i0;
            const float4* T0 = (const float4*)(wtab + (long)i0 * 128);
            float4 wa = T0[lane];
            float4 wb = T0[32 + lane];
            float4 wv;
            wv.x = wa.x + f * (wb.x - wa.x);
            wv.y = wa.y + f * (wb.y - wa.y);
            wv.z = wa.z + f * (wb.z - wa.z);
            wv.w = wa.w + f * (wb.w - wa.w);
            *(float4*)&sbuf[e * 132 + lane * 4] = wv;
        }
        __syncthreads();

        // both-direction segmented reduction
        for (int r = siof[a_own]; r < siof[a_own + 1]; r++) {
            const float4* wp = (const float4*)&sbuf[r * 132 + c_own];
            const float4* hp = (const float4*)&hxs[sjl[r] * 132 + c_own];
            float4 w0 = wp[0], w1v = wp[1], w2v = wp[2], w3 = wp[3];
            float4 h0 = hp[0], h1 = hp[1], h2 = hp[2], h3 = hp[3];
            agg0.x += w0.x*h0.x; agg0.y += w0.y*h0.y; agg0.z += w0.z*h0.z; agg0.w += w0.w*h0.w;
            agg1.x += w1v.x*h1.x; agg1.y += w1v.y*h1.y; agg1.z += w1v.z*h1.z; agg1.w += w1v.w*h1.w;
            agg2.x += w2v.x*h2.x; agg2.y += w2v.y*h2.y; agg2.z += w2v.z*h2.z; agg2.w += w2v.w*h2.w;
            agg3.x += w3.x*h3.x; agg3.y += w3.y*h3.y; agg3.z += w3.z*h3.z; agg3.w += w3.w*h3.w;
        }
        for (int kk = sjof[a_own]; kk < sjof[a_own + 1]; kk++) {
            int r = sjp[kk];
            const float4* wp = (const float4*)&sbuf[r * 132 + c_own];
            const float4* hp = (const float4*)&hxs[sil[r] * 132 + c_own];
            float4 w0 = wp[0], w1v = wp[1], w2v = wp[2], w3 = wp[3];
            float4 h0 = hp[0], h1 = hp[1], h2 = hp[2], h3 = hp[3];
            agg0.x += w0.x*h0.x; agg0.y += w0.y*h0.y; agg0.z += w0.z*h0.z; agg0.w += w0.w*h0.w;
            agg1.x += w1v.x*h1.x; agg1.y += w1v.y*h1.y; agg1.z += w1v.z*h1.z; agg1.w += w1v.w*h1.w;
            agg2.x += w2v.x*h2.x; agg2.y += w2v.y*h2.y; agg2.z += w2v.z*h2.z; agg2.w += w2v.w*h2.w;
            agg3.x += w3.x*h3.x; agg3.y += w3.y*h3.y; agg3.z += w3.z*h3.z; agg3.w += w3.w*h3.w;
        }
        __syncthreads();
    }

    float* ap = g_agg + (long)(m * APM + a_own) * 128 + c_own;
    ((float4*)ap)[0] = agg0;
    ((float4*)ap)[1] = agg1;
    ((float4*)ap)[2] = agg2;
    ((float4*)ap)[3] = agg3;
}

// ---------------------------------------------------------------------------
__global__ __launch_bounds__(256) void k_out(
    const float* __restrict__ out1_w, const float* __restrict__ out1_b,
    const float* __restrict__ out2_w, const float* __restrict__ out2_b,
    const int* __restrict__ batch, float* __restrict__ out)
{
    __shared__ float W1[128 * 64];
    __shared__ float w2s[64];
    __shared__ float xs[8][128];

    int tid = threadIdx.x;
    for (int i = tid; i < 128 * 64; i += 256) W1[i] = out1_w[i];
    if (tid < 64) w2s[tid] = out2_w[tid];
    __syncthreads();

    int warp = tid >> 5, lane = tid & 31;
    float ob0 = out1_b[lane], ob1 = out1_b[lane + 32];
    float b2v = out2_b[0];

    for (int row = blockIdx.x * 8 + warp; row < NATOMS; row += gridDim.x * 8) {
        ((float4*)xs[warp])[lane] = ((const float4*)(g_h + (long)row * 128))[lane];
        __syncwarp();
        float a0 = ob0, a1 = ob1;
        #pragma unroll 8
        for (int k = 0; k < 128; k++) {
            float xv = xs[warp][k];
            a0 += xv * W1[k * 64 + lane];
            a1 += xv * W1[k * 64 + lane + 32];
        }
        float v = sspf(a0) * w2s[lane] + sspf(a1) * w2s[lane + 32];
        #pragma unroll
        for (int off = 16; off; off >>= 1) v += __shfl_down_sync(0xffffffffu, v, off);
        if (lane == 0) atomicAdd(&out[batch[row]], v + b2v);
        __syncwarp();
    }
}

// ---------------------------------------------------------------------------
extern "C" void kernel_launch(void* const* d_in, const int* in_sizes, int n_in,
                              void* d_out, int out_size)
{
    const int*   z       = (const int*)  d_in[0];
    const float* pos     = (const float*)d_in[1];
    const int*   batch   = (const int*)  d_in[2];
    const int*   ei      = (const int*)  d_in[3];
    const float* emb     = (const float*)d_in[4];
    const float* mlp_w1  = (const float*)d_in[5];
    const float* mlp_b1  = (const float*)d_in[6];
    const float* mlp_w2  = (const float*)d_in[7];
    const float* mlp_b2  = (const float*)d_in[8];
    const float* cf1_w   = (const float*)d_in[9];
    const float* cf2_w   = (const float*)d_in[10];
    const float* cf2_b   = (const float*)d_in[11];
    const float* lin_w   = (const float*)d_in[12];
    const float* lin_b   = (const float*)d_in[13];
    const float* out1_w  = (const float*)d_in[14];
    const float* out1_b  = (const float*)d_in[15];
    const float* out2_w  = (const float*)d_in[16];
    const float* out2_b  = (const float*)d_in[17];

    int E = in_sizes[3] / 2;
    const int* src = ei;
    const int* dst = ei + E;

    cudaFuncSetAttribute(k_build, cudaFuncAttributeMaxDynamicSharedMemorySize, BLD_SMEM);
    cudaFuncSetAttribute(k_edge_tab, cudaFuncAttributeMaxDynamicSharedMemorySize, ETAB_SMEM);
    cudaFuncSetAttribute(k_n1, cudaFuncAttributeMaxDynamicSharedMemorySize, N1_SMEM);
    cudaFuncSetAttribute(k_n2, cudaFuncAttributeMaxDynamicSharedMemorySize, N2_SMEM);

    float *ph, *phx, *pagg, *ptab;
    cudaGetSymbolAddress((void**)&ph,   g_h);
    cudaGetSymbolAddress((void**)&phx,  g_hx);
    cudaGetSymbolAddress((void**)&pagg, g_agg);
    cudaGetSymbolAddress((void**)&ptab, g_wtab);

    float* out = (float*)d_out;

    k_moff<<<3, 256>>>(src, E);
    k_prep<<<NMOL, 128>>>(src, dst);
    k_ztab<<<LINT, 128>>>();
    k_build<<<LINT * 64, 512, BLD_SMEM>>>(mlp_w1, mlp_b1, mlp_w2, mlp_b2);
    k_embed<<<(NATOMS*HDIM + 255)/256, 256>>>(z, emb);

    for (int l = 0; l < LINT; l++) {
        k_n1<<<128, 512, N1_SMEM>>>(ph, cf1_w + (long)l*HDIM*HDIM, phx);
        k_edge_tab<<<NMOL, 256, ETAB_SMEM>>>(pos, ptab + (long)l * (TAB_N + 1) * HDIM);
        k_n2<<<128, 512, N2_SMEM>>>(
            pagg, cf2_w + (long)l*HDIM*HDIM, cf2_b + (long)l*HDIM,
            lin_w + (long)l*HDIM*HDIM, lin_b + (long)l*HDIM, ph);
    }

    k_zero_out<<<1, 512>>>(out);
    k_out<<<256, 256>>>(out1_w, out1_b, out2_w, out2_b, batch, out);
}

// round 9
// speedup vs baseline: 3.5279x; 1.0256x over previous
#include <cuda_runtime.h>
#include <cuda_bf16.h>
#include <math.h>
#include <stdint.h>

#define NATOMS 16384
#define NMOL   512
#define APM    32
#define HDIM   128
#define GDIM   50
#define LINT   3
#define CUTOFF 6.0f
#define TAB_N  4096
#define TILES  8
#define TS     64

// Scratch (allocation-free)
__device__ float g_h  [NATOMS * HDIM];
__device__ float g_hx [NATOMS * HDIM];
__device__ float g_agg[NATOMS * HDIM];
__device__ int   g_moff[NMOL + 1];
__device__ int   g_ucnt[NMOL];
__device__ unsigned g_upak[NMOL * 512];
__device__ int   g_ioff[NMOL * TILES * 33];
__device__ int   g_joff[NMOL * TILES * 33];
__device__ int   g_jperm[NMOL * 512];
__device__ float g_wtab[LINT * (TAB_N + 1) * HDIM];

__device__ __forceinline__ float sspf(float x) {
    const float LN2 = 0.6931471805599453f;
    if (x > 20.f) return x - LN2;
    return __logf(1.f + __expf(x)) - LN2;
}
__device__ __forceinline__ void split2(float v0, float v1, uint32_t& hi, uint32_t& lo) {
    __nv_bfloat16 h0 = __float2bfloat16(v0), h1 = __float2bfloat16(v1);
    __nv_bfloat16 l0 = __float2bfloat16(v0 - __bfloat162float(h0));
    __nv_bfloat16 l1 = __float2bfloat16(v1 - __bfloat162float(h1));
    hi = (uint32_t)__bfloat16_as_ushort(h0) | ((uint32_t)__bfloat16_as_ushort(h1) << 16);
    lo = (uint32_t)__bfloat16_as_ushort(l0) | ((uint32_t)__bfloat16_as_ushort(l1) << 16);
}
__device__ __forceinline__ void mma16816(float* d,
    uint32_t a0, uint32_t a1, uint32_t a2, uint32_t a3, uint32_t b0, uint32_t b1) {
    asm volatile(
        "mma.sync.aligned.m16n8k16.row.col.f32.bf16.bf16.f32 "
        "{%0,%1,%2,%3}, {%4,%5,%6,%7}, {%8,%9}, {%0,%1,%2,%3};"
        : "+f"(d[0]), "+f"(d[1]), "+f"(d[2]), "+f"(d[3])
        : "r"(a0), "r"(a1), "r"(a2), "r"(a3), "r"(b0), "r"(b1));
}
__device__ __forceinline__ void eaf(float d, float gofs, float step, float coeff,
                                    uint32_t& hi, uint32_t& lo) {
    float u0 = d - gofs, u1 = d - gofs - step;
    float e0 = __expf(coeff * u0 * u0);
    float e1 = __expf(coeff * u1 * u1);
    split2(e0, e1, hi, lo);
}

// ---------------------------------------------------------------------------
__global__ void k_embed(const int* __restrict__ z, const float* __restrict__ emb) {
    int i = blockIdx.x * blockDim.x + threadIdx.x;
    if (i < NATOMS * HDIM) {
        int a = i >> 7, f = i & 127;
        g_h[i] = emb[z[a] * HDIM + f];
    }
}
__global__ void k_zero_out(float* out) {
    int i = blockIdx.x * blockDim.x + threadIdx.x;
    if (i < NMOL) out[i] = 0.f;
}
__global__ void k_ztab() {
    g_wtab[((long)blockIdx.x * (TAB_N + 1) + TAB_N) * HDIM + threadIdx.x] = 0.f;
}
__global__ void k_moff(const int* __restrict__ src, int E) {
    int m = blockIdx.x * blockDim.x + threadIdx.x;
    if (m > NMOL) return;
    int target = m * APM;
    int lo = 0, hi = E;
    while (lo < hi) { int mid = (lo + hi) >> 1; if (src[mid] < target) lo = mid + 1; else hi = mid; }
    g_moff[m] = lo;
}

// ---------------------------------------------------------------------------
// Prepass: compact undirected edges; 64-row tile segment offsets + j-perm.
// ---------------------------------------------------------------------------
__global__ __launch_bounds__(128) void k_prep(const int* __restrict__ src,
                                              const int* __restrict__ dst) {
    __shared__ unsigned spak[TS];
    __shared__ int scnt2[33];
    __shared__ int snu;
    int m = blockIdx.x;
    int tid = threadIdx.x, lane = tid & 31, wid = tid >> 5;
    int e0 = g_moff[m], e1 = g_moff[m + 1];

    if (wid == 0) {
        int cnt = 0;
        for (int base = e0; base < e1; base += 32) {
            int e = base + lane;
            bool p = false; unsigned pk = 0;
            if (e < e1) {
                int s = src[e] - m * APM, d2 = dst[e] - m * APM;
                if (d2 > s) { p = true; pk = (unsigned)((s << 8) | d2); }
            }
            unsigned msk = __ballot_sync(0xffffffffu, p);
            if (p) g_upak[m * 512 + cnt + __popc(msk & ((1u << lane) - 1))] = pk;
            cnt += __popc(msk);
        }
        if (lane == 0) { g_ucnt[m] = cnt; snu = cnt; }
    }
    __syncthreads();
    int nu = snu;
    int nt = (nu + TS - 1) / TS;

    for (int t = 0; t < nt; t++) {
        int nr = nu - t * TS; if (nr > TS) nr = TS;
        if (tid < TS) spak[tid] = (tid < nr) ? g_upak[m * 512 + t * TS + tid] : 0xffffffffu;
        __syncthreads();
        if (wid == 0) {
            int a = lane, c = 0;
            for (int r = 0; r < nr; r++) c += ((int)(spak[r] >> 8) < a) ? 1 : 0;
            g_ioff[(m * TILES + t) * 33 + a] = c;
            if (lane == 0) g_ioff[(m * TILES + t) * 33 + 32] = nr;
        }
        if (wid == 1) {
            int a = lane, c = 0;
            for (int r = 0; r < nr; r++) c += ((int)(spak[r] & 255) == a) ? 1 : 0;
            int x = c;
            #pragma unroll
            for (int o = 1; o < 32; o <<= 1) {
                int y = __shfl_up_sync(0xffffffffu, x, o);
                if (lane >= o) x += y;
            }
            int excl = x - c;
            g_joff[(m * TILES + t) * 33 + a] = excl;
            scnt2[a] = excl;
            if (lane == 31) g_joff[(m * TILES + t) * 33 + 32] = excl + c;
        }
        __syncthreads();
        if (tid == 0) {
            for (int r = 0; r < nr; r++) {
                int j = (int)(spak[r] & 255);
                g_jperm[m * 512 + t * TS + scnt2[j]] = r;
                scnt2[j]++;
            }
        }
        __syncthreads();
    }
}

// ---------------------------------------------------------------------------
// 16-warp node GEMM (no bias, no act): y = x @ W  (layer 0 only)
// ---------------------------------------------------------------------------
#define N1_SMEM (128 * 132 * 4)

__global__ __launch_bounds__(512, 1) void k_n1(
    const float* __restrict__ x, const float* __restrict__ W, float* __restrict__ y)
{
    extern __shared__ uint32_t smu[];
    uint32_t* Bu = smu;
    const int tid = threadIdx.x, wid = tid >> 5, lane = tid & 31;
    const int half = wid >> 3, w8 = wid & 7;
    const int qr = lane >> 2, qc = lane & 3;

    for (int i = tid; i < 128 * 64; i += 512) {
        int kp = i >> 7, n = i & 127;
        uint32_t h, l;
        split2(W[(2 * kp) * 128 + n], W[(2 * kp + 1) * 128 + n], h, l);
        Bu[n * 132 + kp] = h;
        Bu[n * 132 + 64 + kp] = l;
    }
    __syncthreads();

    const int r0 = w8 * 16 + qr;
    const long base = (long)blockIdx.x * 128;

    float acc[8][4];
    #pragma unroll
    for (int nb = 0; nb < 8; nb++) { acc[nb][0]=0.f; acc[nb][1]=0.f; acc[nb][2]=0.f; acc[nb][3]=0.f; }

    #pragma unroll
    for (int ks = 0; ks < 8; ks++) {
        const float* xr = x + (base + r0) * 128 + ks * 16 + 2 * qc;
        float2 v00 = *(const float2*)xr;
        float2 v01 = *(const float2*)(xr + 8);
        float2 v10 = *(const float2*)(xr + 8 * 128);
        float2 v11 = *(const float2*)(xr + 8 * 128 + 8);
        uint32_t aH0,aH1,aH2,aH3,aL0,aL1,aL2,aL3;
        split2(v00.x, v00.y, aH0, aL0);
        split2(v10.x, v10.y, aH1, aL1);
        split2(v01.x, v01.y, aH2, aL2);
        split2(v11.x, v11.y, aH3, aL3);
        #pragma unroll
        for (int nb = 0; nb < 8; nb++) {
            int noff = ((half * 8 + nb) * 8 + qr) * 132 + ks * 8 + qc;
            uint32_t bh0 = Bu[noff], bh1 = Bu[noff + 4];
            mma16816(acc[nb], aH0, aH1, aH2, aH3, bh0, bh1);
            mma16816(acc[nb], aL0, aL1, aL2, aL3, bh0, bh1);
            uint32_t bl0 = Bu[noff + 64], bl1 = Bu[noff + 68];
            mma16816(acc[nb], aH0, aH1, aH2, aH3, bl0, bl1);
        }
    }

    #pragma unroll
    for (int nb = 0; nb < 8; nb++) {
        int c = (half * 8 + nb) * 8 + 2 * qc;
        *(float2*)(y + (base + r0) * 128 + c)     = make_float2(acc[nb][0], acc[nb][1]);
        *(float2*)(y + (base + r0 + 8) * 128 + c) = make_float2(acc[nb][2], acc[nb][3]);
    }
}

// ---------------------------------------------------------------------------
// Fused node chain: tmp = ssp(agg@W2 + b2); h += tmp@Wl + lb;
// if (cf1n) hx = h_new @ cf1n   (cf1n staged into Bu1 region after GEMM1)
// ---------------------------------------------------------------------------
#define N2_OB1 0
#define N2_OB2 16896
#define N2_OT1 33792
#define N2_OS2 50688
#define N2_OSL 50816
#define N2_SMEM ((50944) * 4)

__global__ __launch_bounds__(512, 1) void k_n2x(
    const float* __restrict__ agg,
    const float* __restrict__ W2, const float* __restrict__ b2,
    const float* __restrict__ Wl, const float* __restrict__ lb,
    float* __restrict__ h,
    const float* __restrict__ cf1n, float* __restrict__ hx)
{
    extern __shared__ uint32_t smu[];
    uint32_t* Bu1 = smu + N2_OB1;
    uint32_t* Bu2 = smu + N2_OB2;
    uint32_t* T1  = smu + N2_OT1;
    float* sb2 = (float*)(smu + N2_OS2);
    float* slb = (float*)(smu + N2_OSL);

    const int tid = threadIdx.x, wid = tid >> 5, lane = tid & 31;
    const int half = wid >> 3, w8 = wid & 7;
    const int qr = lane >> 2, qc = lane & 3;

    for (int i = tid; i < 128 * 64; i += 512) {
        int kp = i >> 7, n = i & 127;
        uint32_t hh, ll;
        split2(W2[(2 * kp) * 128 + n], W2[(2 * kp + 1) * 128 + n], hh, ll);
        Bu1[n * 132 + kp] = hh; Bu1[n * 132 + 64 + kp] = ll;
        split2(Wl[(2 * kp) * 128 + n], Wl[(2 * kp + 1) * 128 + n], hh, ll);
        Bu2[n * 132 + kp] = hh; Bu2[n * 132 + 64 + kp] = ll;
    }
    if (tid < 128) { sb2[tid] = b2[tid]; slb[tid] = lb[tid]; }
    __syncthreads();

    const int r0 = w8 * 16 + qr;
    const long base = (long)blockIdx.x * 128;

    // GEMM1: agg @ W2 -> ssp -> T1 (per-warp-private rows)
    {
        float acc[8][4];
        #pragma unroll
        for (int nb = 0; nb < 8; nb++) { acc[nb][0]=0.f; acc[nb][1]=0.f; acc[nb][2]=0.f; acc[nb][3]=0.f; }
        #pragma unroll
        for (int ks = 0; ks < 8; ks++) {
            const float* xr = agg + (base + r0) * 128 + ks * 16 + 2 * qc;
            float2 v00 = *(const float2*)xr;
            float2 v01 = *(const float2*)(xr + 8);
            float2 v10 = *(const float2*)(xr + 8 * 128);
            float2 v11 = *(const float2*)(xr + 8 * 128 + 8);
            uint32_t aH0,aH1,aH2,aH3,aL0,aL1,aL2,aL3;
            split2(v00.x, v00.y, aH0, aL0);
            split2(v10.x, v10.y, aH1, aL1);
            split2(v01.x, v01.y, aH2, aL2);
            split2(v11.x, v11.y, aH3, aL3);
            #pragma unroll
            for (int nb = 0; nb < 8; nb++) {
                int noff = ((half * 8 + nb) * 8 + qr) * 132 + ks * 8 + qc;
                uint32_t bh0 = Bu1[noff], bh1 = Bu1[noff + 4];
                mma16816(acc[nb], aH0, aH1, aH2, aH3, bh0, bh1);
                mma16816(acc[nb], aL0, aL1, aL2, aL3, bh0, bh1);
                uint32_t bl0 = Bu1[noff + 64], bl1 = Bu1[noff + 68];
                mma16816(acc[nb], aH0, aH1, aH2, aH3, bl0, bl1);
            }
        }
        #pragma unroll
        for (int nb = 0; nb < 8; nb++) {
            int c = (half * 8 + nb) * 8 + 2 * qc;
            int kp = (c >> 1);
            float bx = sb2[c], by = sb2[c + 1];
            uint32_t hh, ll;
            split2(sspf(acc[nb][0] + bx), sspf(acc[nb][1] + by), hh, ll);
            T1[r0 * 132 + kp] = hh; T1[r0 * 132 + 64 + kp] = ll;
            split2(sspf(acc[nb][2] + bx), sspf(acc[nb][3] + by), hh, ll);
            T1[(r0 + 8) * 132 + kp] = hh; T1[(r0 + 8) * 132 + 64 + kp] = ll;
        }
    }
    __syncthreads();   // T1 complete; Bu1 (W2) no longer needed

    // Stage next-layer cf1 into Bu1 region (overlaps with GEMM2 scheduling)
    if (cf1n) {
        for (int i = tid; i < 128 * 64; i += 512) {
            int kp = i >> 7, n = i & 127;
            uint32_t hh, ll;
            split2(cf1n[(2 * kp) * 128 + n], cf1n[(2 * kp + 1) * 128 + n], hh, ll);
            Bu1[n * 132 + kp] = hh; Bu1[n * 132 + 64 + kp] = ll;
        }
    }

    // GEMM2: T1 @ Wl, residual -> h_new; write h; re-split h_new into T1 (own rows)
    {
        float acc[8][4];
        #pragma unroll
        for (int nb = 0; nb < 8; nb++) { acc[nb][0]=0.f; acc[nb][1]=0.f; acc[nb][2]=0.f; acc[nb][3]=0.f; }
        #pragma unroll
        for (int ks = 0; ks < 8; ks++) {
            int xo0 = r0 * 132 + ks * 8 + qc;
            int xo1 = (r0 + 8) * 132 + ks * 8 + qc;
            uint32_t aH0 = T1[xo0],      aH1 = T1[xo1];
            uint32_t aH2 = T1[xo0 + 4],  aH3 = T1[xo1 + 4];
            uint32_t aL0 = T1[xo0 + 64], aL1 = T1[xo1 + 64];
            uint32_t aL2 = T1[xo0 + 68], aL3 = T1[xo1 + 68];
            #pragma unroll
            for (int nb = 0; nb < 8; nb++) {
                int noff = ((half * 8 + nb) * 8 + qr) * 132 + ks * 8 + qc;
                uint32_t bh0 = Bu2[noff], bh1 = Bu2[noff + 4];
                mma16816(acc[nb], aH0, aH1, aH2, aH3, bh0, bh1);
                mma16816(acc[nb], aL0, aL1, aL2, aL3, bh0, bh1);
                uint32_t bl0 = Bu2[noff + 64], bl1 = Bu2[noff + 68];
                mma16816(acc[nb], aH0, aH1, aH2, aH3, bl0, bl1);
            }
        }
        #pragma unroll
        for (int nb = 0; nb < 8; nb++) {
            int c = (half * 8 + nb) * 8 + 2 * qc;
            float bx = slb[c], by = slb[c + 1];
            float* y0 = h + (base + r0) * 128 + c;
            float* y1 = h + (base + r0 + 8) * 128 + c;
            float2 p0 = *(float2*)y0, p1 = *(float2*)y1;
            float v0 = p0.x + acc[nb][0] + bx, v1 = p0.y + acc[nb][1] + by;
            float v2 = p1.x + acc[nb][2] + bx, v3 = p1.y + acc[nb][3] + by;
            *(float2*)y0 = make_float2(v0, v1);
            *(float2*)y1 = make_float2(v2, v3);
            if (cf1n) {
                int kp = c >> 1;
                uint32_t hh, ll;
                split2(v0, v1, hh, ll);
                T1[r0 * 132 + kp] = hh; T1[r0 * 132 + 64 + kp] = ll;
                split2(v2, v3, hh, ll);
                T1[(r0 + 8) * 132 + kp] = hh; T1[(r0 + 8) * 132 + 64 + kp] = ll;
            }
        }
    }

    if (!cf1n) return;
    __syncthreads();   // cf1 staged + all T1 rows rewritten

    // GEMM3: hx = h_new @ cf1n
    {
        float acc[8][4];
        #pragma unroll
        for (int nb = 0; nb < 8; nb++) { acc[nb][0]=0.f; acc[nb][1]=0.f; acc[nb][2]=0.f; acc[nb][3]=0.f; }
        #pragma unroll
        for (int ks = 0; ks < 8; ks++) {
            int xo0 = r0 * 132 + ks * 8 + qc;
            int xo1 = (r0 + 8) * 132 + ks * 8 + qc;
            uint32_t aH0 = T1[xo0],      aH1 = T1[xo1];
            uint32_t aH2 = T1[xo0 + 4],  aH3 = T1[xo1 + 4];
            uint32_t aL0 = T1[xo0 + 64], aL1 = T1[xo1 + 64];
            uint32_t aL2 = T1[xo0 + 68], aL3 = T1[xo1 + 68];
            #pragma unroll
            for (int nb = 0; nb < 8; nb++) {
                int noff = ((half * 8 + nb) * 8 + qr) * 132 + ks * 8 + qc;
                uint32_t bh0 = Bu1[noff], bh1 = Bu1[noff + 4];
                mma16816(acc[nb], aH0, aH1, aH2, aH3, bh0, bh1);
                mma16816(acc[nb], aL0, aL1, aL2, aL3, bh0, bh1);
                uint32_t bl0 = Bu1[noff + 64], bl1 = Bu1[noff + 68];
                mma16816(acc[nb], aH0, aH1, aH2, aH3, bl0, bl1);
            }
        }
        #pragma unroll
        for (int nb = 0; nb < 8; nb++) {
            int c = (half * 8 + nb) * 8 + 2 * qc;
            *(float2*)(hx + (base + r0) * 128 + c)     = make_float2(acc[nb][0], acc[nb][1]);
            *(float2*)(hx + (base + r0 + 8) * 128 + c) = make_float2(acc[nb][2], acc[nb][3]);
        }
    }
}

// ---------------------------------------------------------------------------
// Table builder (TAB_N grid): one CTA = (layer, 128-point tile)
// ---------------------------------------------------------------------------
#define BLD_OB1 0
#define BLD_OB2 8704
#define BLD_OT1 25600
#define BLD_OS1 42496
#define BLD_OS2 42624
#define BLD_SMEM ((42752) * 4)

__global__ __launch_bounds__(512, 1)
void k_build(const float* __restrict__ w1all, const float* __restrict__ b1all,
             const float* __restrict__ w2all, const float* __restrict__ b2all)
{
    extern __shared__ uint32_t smu[];
    uint32_t* B1u = smu + BLD_OB1;
    uint32_t* B2u = smu + BLD_OB2;
    uint32_t* T1  = smu + BLD_OT1;
    float* sb1 = (float*)(smu + BLD_OS1);
    float* sb2 = (float*)(smu + BLD_OS2);

    const int tpl = TAB_N / 128;           // tiles per layer
    const int l = blockIdx.x / tpl, t = blockIdx.x % tpl;
    const float* w1 = w1all + (long)l * GDIM * HDIM;
    const float* b1 = b1all + (long)l * HDIM;
    const float* w2 = w2all + (long)l * HDIM * HDIM;
    const float* b2 = b2all + (long)l * HDIM;

    const int tid = threadIdx.x, wid = tid >> 5, lane = tid & 31;
    const int half = wid >> 3, w8 = wid & 7;
    const int qr = lane >> 2, qc = lane & 3;

    for (int i = tid; i < 128 * 32; i += 512) {
        int kp = i >> 7, n = i & 127, k = 2 * kp;
        float v0 = (k < GDIM)     ? w1[k * 128 + n]       : 0.f;
        float v1 = (k + 1 < GDIM) ? w1[(k + 1) * 128 + n] : 0.f;
        uint32_t h, lv; split2(v0, v1, h, lv);
        B1u[n * 68 + kp] = h;
        B1u[n * 68 + 32 + kp] = lv;
    }
    for (int i = tid; i < 128 * 64; i += 512) {
        int kp = i >> 7, n = i & 127;
        uint32_t h, lv;
        split2(w2[(2 * kp) * 128 + n], w2[(2 * kp + 1) * 128 + n], h, lv);
        B2u[n * 132 + kp] = h;
        B2u[n * 132 + 64 + kp] = lv;
    }
    if (tid < 128) { sb1[tid] = b1[tid]; sb2[tid] = b2[tid]; }
    __syncthreads();

    const float step  = CUTOFF / (GDIM - 1);
    const float coeff = -0.5f / (step * step);
    const float PIOC  = 3.14159265358979f / CUTOFF;
    const float DELTA = CUTOFF / (float)TAB_N;
    const int r0 = w8 * 16 + qr;

    float dv0 = (float)(t * 128 + r0) * DELTA;
    float dv1 = (float)(t * 128 + r0 + 8) * DELTA;

    uint32_t aH[4][4], aL[4][4];
    #pragma unroll
    for (int ks = 0; ks < 4; ks++) {
        float g0 = (float)(ks * 16 + 2 * qc) * step;
        eaf(dv0, g0,            step, coeff, aH[ks][0], aL[ks][0]);
        eaf(dv1, g0,            step, coeff, aH[ks][1], aL[ks][1]);
        eaf(dv0, g0 + 8.f*step, step, coeff, aH[ks][2], aL[ks][2]);
        eaf(dv1, g0 + 8.f*step, step, coeff, aH[ks][3], aL[ks][3]);
    }

    #pragma unroll
    for (int nb = 0; nb < 8; nb++) {
        float acc[4] = {0.f, 0.f, 0.f, 0.f};
        #pragma unroll
        for (int ks = 0; ks < 4; ks++) {
            int noff = ((half * 8 + nb) * 8 + qr) * 68 + ks * 8 + qc;
            uint32_t bh0 = B1u[noff], bh1 = B1u[noff + 4];
            mma16816(acc, aH[ks][0], aH[ks][1], aH[ks][2], aH[ks][3], bh0, bh1);
            mma16816(acc, aL[ks][0], aL[ks][1], aL[ks][2], aL[ks][3], bh0, bh1);
            uint32_t bl0 = B1u[noff + 32], bl1 = B1u[noff + 36];
            mma16816(acc, aH[ks][0], aH[ks][1], aH[ks][2], aH[ks][3], bl0, bl1);
        }
        int c = (half * 8 + nb) * 8 + 2 * qc;
        int kp = c >> 1;
        float bx = sb1[c], by = sb1[c + 1];
        uint32_t hh, ll;
        split2(sspf(acc[0] + bx), sspf(acc[1] + by), hh, ll);
        T1[r0 * 132 + kp] = hh; T1[r0 * 132 + 64 + kp] = ll;
        split2(sspf(acc[2] + bx), sspf(acc[3] + by), hh, ll);
        T1[(r0 + 8) * 132 + kp] = hh; T1[(r0 + 8) * 132 + 64 + kp] = ll;
    }
    __syncthreads();

    float acc2[8][4];
    #pragma unroll
    for (int nb = 0; nb < 8; nb++) { acc2[nb][0]=0.f; acc2[nb][1]=0.f; acc2[nb][2]=0.f; acc2[nb][3]=0.f; }
    #pragma unroll
    for (int ks = 0; ks < 8; ks++) {
        int xo0 = r0 * 132 + ks * 8 + qc;
        int xo1 = (r0 + 8) * 132 + ks * 8 + qc;
        uint32_t aH0 = T1[xo0],      aH1 = T1[xo1];
        uint32_t aH2 = T1[xo0 + 4],  aH3 = T1[xo1 + 4];
        uint32_t aL0 = T1[xo0 + 64], aL1 = T1[xo1 + 64];
        uint32_t aL2 = T1[xo0 + 68], aL3 = T1[xo1 + 68];
        #pragma unroll
        for (int nb = 0; nb < 8; nb++) {
            int noff = ((half * 8 + nb) * 8 + qr) * 132 + ks * 8 + qc;
            uint32_t bh0 = B2u[noff], bh1 = B2u[noff + 4];
            mma16816(acc2[nb], aH0, aH1, aH2, aH3, bh0, bh1);
            mma16816(acc2[nb], aL0, aL1, aL2, aL3, bh0, bh1);
            uint32_t bl0 = B2u[noff + 64], bl1 = B2u[noff + 68];
            mma16816(acc2[nb], aH0, aH1, aH2, aH3, bl0, bl1);
        }
    }

    float cc0 = 0.5f * (cosf(dv0 * PIOC) + 1.f);
    float cc1 = 0.5f * (cosf(dv1 * PIOC) + 1.f);
    float* trow = g_wtab + ((long)l * (TAB_N + 1) + t * 128 + r0) * 128;
    #pragma unroll
    for (int nb = 0; nb < 8; nb++) {
        int c = (half * 8 + nb) * 8 + 2 * qc;
        float bx = sb2[c], by = sb2[c + 1];
        *(float2*)(trow + c) =
            make_float2((acc2[nb][0] + bx) * cc0, (acc2[nb][1] + by) * cc0);
        *(float2*)(trow + 8 * 128 + c) =
            make_float2((acc2[nb][2] + bx) * cc1, (acc2[nb][3] + by) * cc1);
    }
}

// ---------------------------------------------------------------------------
// Table-lookup edge kernel: one CTA (256 thr) per molecule, 64-edge tiles,
// 3 CTAs/SM (52 KB SMEM).
// ---------------------------------------------------------------------------
#define ET_HX 0
#define ET_SB 4224
#define ET_SD 12672
#define ET_IL 12736
#define ET_JL 12800
#define ET_JP 12864
#define ET_IO 12928
#define ET_JO 12961
#define ET_PS 12994
#define ET_W  13090
#define ETAB_SMEM (ET_W * 4)

__global__ __launch_bounds__(256, 3)
void k_edge_tab(const float* __restrict__ pos, const float* __restrict__ wtab)
{
    extern __shared__ float sm[];
    float* hxs  = sm + ET_HX;     // 32 x 132
    float* sbuf = sm + ET_SB;     // 64 x 132
    float* sd   = sm + ET_SD;
    int*   sil  = (int*)(sm + ET_IL);
    int*   sjl  = (int*)(sm + ET_JL);
    int*   sjp  = (int*)(sm + ET_JP);
    int*   siof = (int*)(sm + ET_IO);
    int*   sjof = (int*)(sm + ET_JO);
    float* ps   = sm + ET_PS;

    const int tid = threadIdx.x, wid = tid >> 5, lane = tid & 31;
    const int m = blockIdx.x;
    const int a_own = tid >> 3, c_own = (tid & 7) * 16;
    const float SCALE = (float)TAB_N / CUTOFF;

    int nu = g_ucnt[m];
    int nt = (nu + TS - 1) / TS;

    for (int i = tid; i < APM * 128; i += 256) {
        int a = i >> 7, c = i & 127;
        hxs[a * 132 + c] = g_hx[(long)(m * APM + a) * 128 + c];
    }
    if (tid < 96) ps[tid] = pos[m * 96 + tid];
    float4 agg0 = make_float4(0,0,0,0), agg1 = agg0, agg2 = agg0, agg3 = agg0;
    __syncthreads();

    for (int t = 0; t < nt; t++) {
        if (tid < TS) {
            int k = t * TS + tid;
            float d = 0.f; int il = 0, jl = 0;
            if (k < nu) {
                unsigned pk = g_upak[m * 512 + k];
                il = (int)(pk >> 8); jl = (int)(pk & 255);
                float dx = ps[3*il]   - ps[3*jl];
                float dy = ps[3*il+1] - ps[3*jl+1];
                float dz = ps[3*il+2] - ps[3*jl+2];
                d = sqrtf(dx*dx + dy*dy + dz*dz);
            }
            sd[tid] = d; sil[tid] = il; sjl[tid] = jl;
            sjp[tid] = g_jperm[m * 512 + t * TS + tid];
        }
        if (tid >= 64 && tid < 97)   siof[tid - 64]  = g_ioff[(m * TILES + t) * 33 + tid - 64];
        if (tid >= 128 && tid < 161) sjof[tid - 128] = g_joff[(m * TILES + t) * 33 + tid - 128];
        __syncthreads();

        // fill sbuf: w(e, :) = lerp(table)
        for (int e = wid; e < TS; e += 8) {
            float d = sd[e];
            float tt = d * SCALE;
            int i0 = (int)tt;
            i0 = (i0 > TAB_N - 1) ? (TAB_N - 1) : i0;
            float f = tt - (float)i0;
            const float4* T0 = (const float4*)(wtab + (long)i0 * 128);
            float4 wa = T0[lane];
            float4 wb = T0[32 + lane];
            float4 wv;
            wv.x = wa.x + f * (wb.x - wa.x);
            wv.y = wa.y + f * (wb.y - wa.y);
            wv.z = wa.z + f * (wb.z - wa.z);
            wv.w = wa.w + f * (wb.w - wa.w);
            *(float4*)&sbuf[e * 132 + lane * 4] = wv;
        }
        __syncthreads();

        // both-direction segmented reduction
        for (int r = siof[a_own]; r < siof[a_own + 1]; r++) {
            const float4* wp = (const float4*)&sbuf[r * 132 + c_own];
            const float4* hp = (const float4*)&hxs[sjl[r] * 132 + c_own];
            float4 w0 = wp[0], w1v = wp[1], w2v = wp[2], w3 = wp[3];
            float4 h0 = hp[0], h1 = hp[1], h2 = hp[2], h3 = hp[3];
            agg0.x += w0.x*h0.x; agg0.y += w0.y*h0.y; agg0.z += w0.z*h0.z; agg0.w += w0.w*h0.w;
            agg1.x += w1v.x*h1.x; agg1.y += w1v.y*h1.y; agg1.z += w1v.z*h1.z; agg1.w += w1v.w*h1.w;
            agg2.x += w2v.x*h2.x; agg2.y += w2v.y*h2.y; agg2.z += w2v.z*h2.z; agg2.w += w2v.w*h2.w;
            agg3.x += w3.x*h3.x; agg3.y += w3.y*h3.y; agg3.z += w3.z*h3.z; agg3.w += w3.w*h3.w;
        }
        for (int kk = sjof[a_own]; kk < sjof[a_own + 1]; kk++) {
            int r = sjp[kk];
            const float4* wp = (const float4*)&sbuf[r * 132 + c_own];
            const float4* hp = (const float4*)&hxs[sil[r] * 132 + c_own];
            float4 w0 = wp[0], w1v = wp[1], w2v = wp[2], w3 = wp[3];
            float4 h0 = hp[0], h1 = hp[1], h2 = hp[2], h3 = hp[3];
            agg0.x += w0.x*h0.x; agg0.y += w0.y*h0.y; agg0.z += w0.z*h0.z; agg0.w += w0.w*h0.w;
            agg1.x += w1v.x*h1.x; agg1.y += w1v.y*h1.y; agg1.z += w1v.z*h1.z; agg1.w += w1v.w*h1.w;
            agg2.x += w2v.x*h2.x; agg2.y += w2v.y*h2.y; agg2.z += w2v.z*h2.z; agg2.w += w2v.w*h2.w;
            agg3.x += w3.x*h3.x; agg3.y += w3.y*h3.y; agg3.z += w3.z*h3.z; agg3.w += w3.w*h3.w;
        }
        __syncthreads();
    }

    float* ap = g_agg + (long)(m * APM + a_own) * 128 + c_own;
    ((float4*)ap)[0] = agg0;
    ((float4*)ap)[1] = agg1;
    ((float4*)ap)[2] = agg2;
    ((float4*)ap)[3] = agg3;
}

// ---------------------------------------------------------------------------
__global__ __launch_bounds__(256) void k_out(
    const float* __restrict__ out1_w, const float* __restrict__ out1_b,
    const float* __restrict__ out2_w, const float* __restrict__ out2_b,
    const int* __restrict__ batch, float* __restrict__ out)
{
    __shared__ float W1[128 * 64];
    __shared__ float w2s[64];
    __shared__ float xs[8][128];

    int tid = threadIdx.x;
    for (int i = tid; i < 128 * 64; i += 256) W1[i] = out1_w[i];
    if (tid < 64) w2s[tid] = out2_w[tid];
    __syncthreads();

    int warp = tid >> 5, lane = tid & 31;
    float ob0 = out1_b[lane], ob1 = out1_b[lane + 32];
    float b2v = out2_b[0];

    for (int row = blockIdx.x * 8 + warp; row < NATOMS; row += gridDim.x * 8) {
        ((float4*)xs[warp])[lane] = ((const float4*)(g_h + (long)row * 128))[lane];
        __syncwarp();
        float a0 = ob0, a1 = ob1;
        #pragma unroll 8
        for (int k = 0; k < 128; k++) {
            float xv = xs[warp][k];
            a0 += xv * W1[k * 64 + lane];
            a1 += xv * W1[k * 64 + lane + 32];
        }
        float v = sspf(a0) * w2s[lane] + sspf(a1) * w2s[lane + 32];
        #pragma unroll
        for (int off = 16; off; off >>= 1) v += __shfl_down_sync(0xffffffffu, v, off);
        if (lane == 0) atomicAdd(&out[batch[row]], v + b2v);
        __syncwarp();
    }
}

// ---------------------------------------------------------------------------
extern "C" void kernel_launch(void* const* d_in, const int* in_sizes, int n_in,
                              void* d_out, int out_size)
{
    const int*   z       = (const int*)  d_in[0];
    const float* pos     = (const float*)d_in[1];
    const int*   batch   = (const int*)  d_in[2];
    const int*   ei      = (const int*)  d_in[3];
    const float* emb     = (const float*)d_in[4];
    const float* mlp_w1  = (const float*)d_in[5];
    const float* mlp_b1  = (const float*)d_in[6];
    const float* mlp_w2  = (const float*)d_in[7];
    const float* mlp_b2  = (const float*)d_in[8];
    const float* cf1_w   = (const float*)d_in[9];
    const float* cf2_w   = (const float*)d_in[10];
    const float* cf2_b   = (const float*)d_in[11];
    const float* lin_w   = (const float*)d_in[12];
    const float* lin_b   = (const float*)d_in[13];
    const float* out1_w  = (const float*)d_in[14];
    const float* out1_b  = (const float*)d_in[15];
    const float* out2_w  = (const float*)d_in[16];
    const float* out2_b  = (const float*)d_in[17];

    int E = in_sizes[3] / 2;
    const int* src = ei;
    const int* dst = ei + E;

    cudaFuncSetAttribute(k_build, cudaFuncAttributeMaxDynamicSharedMemorySize, BLD_SMEM);
    cudaFuncSetAttribute(k_edge_tab, cudaFuncAttributeMaxDynamicSharedMemorySize, ETAB_SMEM);
    cudaFuncSetAttribute(k_n1, cudaFuncAttributeMaxDynamicSharedMemorySize, N1_SMEM);
    cudaFuncSetAttribute(k_n2x, cudaFuncAttributeMaxDynamicSharedMemorySize, N2_SMEM);

    float *ph, *phx, *pagg, *ptab;
    cudaGetSymbolAddress((void**)&ph,   g_h);
    cudaGetSymbolAddress((void**)&phx,  g_hx);
    cudaGetSymbolAddress((void**)&pagg, g_agg);
    cudaGetSymbolAddress((void**)&ptab, g_wtab);

    float* out = (float*)d_out;

    k_moff<<<3, 256>>>(src, E);
    k_prep<<<NMOL, 128>>>(src, dst);
    k_ztab<<<LINT, 128>>>();
    k_build<<<LINT * (TAB_N / 128), 512, BLD_SMEM>>>(mlp_w1, mlp_b1, mlp_w2, mlp_b2);
    k_embed<<<(NATOMS*HDIM + 255)/256, 256>>>(z, emb);
    k_n1<<<128, 512, N1_SMEM>>>(ph, cf1_w, phx);

    for (int l = 0; l < LINT; l++) {
        k_edge_tab<<<NMOL, 256, ETAB_SMEM>>>(pos, ptab + (long)l * (TAB_N + 1) * HDIM);
        const float* cf1n = (l + 1 < LINT) ? (cf1_w + (long)(l + 1) * HDIM * HDIM) : nullptr;
        k_n2x<<<128, 512, N2_SMEM>>>(
            pagg, cf2_w + (long)l*HDIM*HDIM, cf2_b + (long)l*HDIM,
            lin_w + (long)l*HDIM*HDIM, lin_b + (long)l*HDIM, ph,
            cf1n, phx);
    }

    k_zero_out<<<1, 512>>>(out);
    k_out<<<256, 256>>>(out1_w, out1_b, out2_w, out2_b, batch, out);
}

// round 10
// speedup vs baseline: 4.3454x; 1.2317x over previous
#include <cuda_runtime.h>
#include <cuda_bf16.h>
#include <math.h>
#include <stdint.h>

#define NATOMS 16384
#define NMOL   512
#define APM    32
#define HDIM   128
#define GDIM   50
#define LINT   3
#define CUTOFF 6.0f
#define TAB_N  2048
#define TILES  8
#define TS     64

// Scratch (allocation-free)
__device__ float g_h  [NATOMS * HDIM];
__device__ float g_hx [NATOMS * HDIM];
__device__ float g_agg[NATOMS * HDIM];
__device__ int   g_moff[NMOL + 1];
__device__ int   g_ucnt[NMOL];
__device__ unsigned g_upak[NMOL * 512];
__device__ int   g_ioff[NMOL * TILES * 33];
__device__ int   g_joff[NMOL * TILES * 33];
__device__ int   g_jperm[NMOL * 512];
__device__ float g_wtab[LINT * (TAB_N + 1) * HDIM];

__device__ __forceinline__ float sspf(float x) {
    const float LN2 = 0.6931471805599453f;
    if (x > 20.f) return x - LN2;
    return __logf(1.f + __expf(x)) - LN2;
}
__device__ __forceinline__ void split2(float v0, float v1, uint32_t& hi, uint32_t& lo) {
    __nv_bfloat16 h0 = __float2bfloat16(v0), h1 = __float2bfloat16(v1);
    __nv_bfloat16 l0 = __float2bfloat16(v0 - __bfloat162float(h0));
    __nv_bfloat16 l1 = __float2bfloat16(v1 - __bfloat162float(h1));
    hi = (uint32_t)__bfloat16_as_ushort(h0) | ((uint32_t)__bfloat16_as_ushort(h1) << 16);
    lo = (uint32_t)__bfloat16_as_ushort(l0) | ((uint32_t)__bfloat16_as_ushort(l1) << 16);
}
__device__ __forceinline__ void mma16816(float* d,
    uint32_t a0, uint32_t a1, uint32_t a2, uint32_t a3, uint32_t b0, uint32_t b1) {
    asm volatile(
        "mma.sync.aligned.m16n8k16.row.col.f32.bf16.bf16.f32 "
        "{%0,%1,%2,%3}, {%4,%5,%6,%7}, {%8,%9}, {%0,%1,%2,%3};"
        : "+f"(d[0]), "+f"(d[1]), "+f"(d[2]), "+f"(d[3])
        : "r"(a0), "r"(a1), "r"(a2), "r"(a3), "r"(b0), "r"(b1));
}
__device__ __forceinline__ void eaf(float d, float gofs, float step, float coeff,
                                    uint32_t& hi, uint32_t& lo) {
    float u0 = d - gofs, u1 = d - gofs - step;
    float e0 = __expf(coeff * u0 * u0);
    float e1 = __expf(coeff * u1 * u1);
    split2(e0, e1, hi, lo);
}

// ---------------------------------------------------------------------------
__global__ void k_embed(const int* __restrict__ z, const float* __restrict__ emb) {
    int i = blockIdx.x * blockDim.x + threadIdx.x;
    if (i < NATOMS * HDIM) {
        int a = i >> 7, f = i & 127;
        g_h[i] = emb[z[a] * HDIM + f];
    }
}
__global__ void k_zero_out(float* out) {
    int i = blockIdx.x * blockDim.x + threadIdx.x;
    if (i < NMOL) out[i] = 0.f;
}
__global__ void k_ztab() {
    g_wtab[((long)blockIdx.x * (TAB_N + 1) + TAB_N) * HDIM + threadIdx.x] = 0.f;
}
__global__ void k_moff(const int* __restrict__ src, int E) {
    int m = blockIdx.x * blockDim.x + threadIdx.x;
    if (m > NMOL) return;
    int target = m * APM;
    int lo = 0, hi = E;
    while (lo < hi) { int mid = (lo + hi) >> 1; if (src[mid] < target) lo = mid + 1; else hi = mid; }
    g_moff[m] = lo;
}

// ---------------------------------------------------------------------------
// Prepass: compact undirected edges; 64-row tile segment offsets + j-perm.
// ---------------------------------------------------------------------------
__global__ __launch_bounds__(128) void k_prep(const int* __restrict__ src,
                                              const int* __restrict__ dst) {
    __shared__ unsigned spak[TS];
    __shared__ int scnt2[33];
    __shared__ int snu;
    int m = blockIdx.x;
    int tid = threadIdx.x, lane = tid & 31, wid = tid >> 5;
    int e0 = g_moff[m], e1 = g_moff[m + 1];

    if (wid == 0) {
        int cnt = 0;
        for (int base = e0; base < e1; base += 32) {
            int e = base + lane;
            bool p = false; unsigned pk = 0;
            if (e < e1) {
                int s = src[e] - m * APM, d2 = dst[e] - m * APM;
                if (d2 > s) { p = true; pk = (unsigned)((s << 8) | d2); }
            }
            unsigned msk = __ballot_sync(0xffffffffu, p);
            if (p) g_upak[m * 512 + cnt + __popc(msk & ((1u << lane) - 1))] = pk;
            cnt += __popc(msk);
        }
        if (lane == 0) { g_ucnt[m] = cnt; snu = cnt; }
    }
    __syncthreads();
    int nu = snu;
    int nt = (nu + TS - 1) / TS;

    for (int t = 0; t < nt; t++) {
        int nr = nu - t * TS; if (nr > TS) nr = TS;
        if (tid < TS) spak[tid] = (tid < nr) ? g_upak[m * 512 + t * TS + tid] : 0xffffffffu;
        __syncthreads();
        if (wid == 0) {
            int a = lane, c = 0;
            for (int r = 0; r < nr; r++) c += ((int)(spak[r] >> 8) < a) ? 1 : 0;
            g_ioff[(m * TILES + t) * 33 + a] = c;
            if (lane == 0) g_ioff[(m * TILES + t) * 33 + 32] = nr;
        }
        if (wid == 1) {
            int a = lane, c = 0;
            for (int r = 0; r < nr; r++) c += ((int)(spak[r] & 255) == a) ? 1 : 0;
            int x = c;
            #pragma unroll
            for (int o = 1; o < 32; o <<= 1) {
                int y = __shfl_up_sync(0xffffffffu, x, o);
                if (lane >= o) x += y;
            }
            int excl = x - c;
            g_joff[(m * TILES + t) * 33 + a] = excl;
            scnt2[a] = excl;
            if (lane == 31) g_joff[(m * TILES + t) * 33 + 32] = excl + c;
        }
        __syncthreads();
        if (tid == 0) {
            for (int r = 0; r < nr; r++) {
                int j = (int)(spak[r] & 255);
                g_jperm[m * 512 + t * TS + scnt2[j]] = r;
                scnt2[j]++;
            }
        }
        __syncthreads();
    }
}

// ---------------------------------------------------------------------------
// 16-warp node GEMM (no bias, no act): y = x @ W  (layer 0 only)
// ---------------------------------------------------------------------------
#define N1_SMEM (128 * 132 * 4)

__global__ __launch_bounds__(512, 1) void k_n1(
    const float* __restrict__ x, const float* __restrict__ W, float* __restrict__ y)
{
    extern __shared__ uint32_t smu[];
    uint32_t* Bu = smu;
    const int tid = threadIdx.x, wid = tid >> 5, lane = tid & 31;
    const int half = wid >> 3, w8 = wid & 7;
    const int qr = lane >> 2, qc = lane & 3;

    for (int i = tid; i < 128 * 64; i += 512) {
        int kp = i >> 7, n = i & 127;
        uint32_t h, l;
        split2(W[(2 * kp) * 128 + n], W[(2 * kp + 1) * 128 + n], h, l);
        Bu[n * 132 + kp] = h;
        Bu[n * 132 + 64 + kp] = l;
    }
    __syncthreads();

    const int r0 = w8 * 16 + qr;
    const long base = (long)blockIdx.x * 128;

    float acc[8][4];
    #pragma unroll
    for (int nb = 0; nb < 8; nb++) { acc[nb][0]=0.f; acc[nb][1]=0.f; acc[nb][2]=0.f; acc[nb][3]=0.f; }

    #pragma unroll
    for (int ks = 0; ks < 8; ks++) {
        const float* xr = x + (base + r0) * 128 + ks * 16 + 2 * qc;
        float2 v00 = *(const float2*)xr;
        float2 v01 = *(const float2*)(xr + 8);
        float2 v10 = *(const float2*)(xr + 8 * 128);
        float2 v11 = *(const float2*)(xr + 8 * 128 + 8);
        uint32_t aH0,aH1,aH2,aH3,aL0,aL1,aL2,aL3;
        split2(v00.x, v00.y, aH0, aL0);
        split2(v10.x, v10.y, aH1, aL1);
        split2(v01.x, v01.y, aH2, aL2);
        split2(v11.x, v11.y, aH3, aL3);
        #pragma unroll
        for (int nb = 0; nb < 8; nb++) {
            int noff = ((half * 8 + nb) * 8 + qr) * 132 + ks * 8 + qc;
            uint32_t bh0 = Bu[noff], bh1 = Bu[noff + 4];
            mma16816(acc[nb], aH0, aH1, aH2, aH3, bh0, bh1);
            mma16816(acc[nb], aL0, aL1, aL2, aL3, bh0, bh1);
            uint32_t bl0 = Bu[noff + 64], bl1 = Bu[noff + 68];
            mma16816(acc[nb], aH0, aH1, aH2, aH3, bl0, bl1);
        }
    }

    #pragma unroll
    for (int nb = 0; nb < 8; nb++) {
        int c = (half * 8 + nb) * 8 + 2 * qc;
        *(float2*)(y + (base + r0) * 128 + c)     = make_float2(acc[nb][0], acc[nb][1]);
        *(float2*)(y + (base + r0 + 8) * 128 + c) = make_float2(acc[nb][2], acc[nb][3]);
    }
}

// ---------------------------------------------------------------------------
// Fused node chain (unchanged from R9)
// ---------------------------------------------------------------------------
#define N2_OB1 0
#define N2_OB2 16896
#define N2_OT1 33792
#define N2_OS2 50688
#define N2_OSL 50816
#define N2_SMEM ((50944) * 4)

__global__ __launch_bounds__(512, 1) void k_n2x(
    const float* __restrict__ agg,
    const float* __restrict__ W2, const float* __restrict__ b2,
    const float* __restrict__ Wl, const float* __restrict__ lb,
    float* __restrict__ h,
    const float* __restrict__ cf1n, float* __restrict__ hx)
{
    extern __shared__ uint32_t smu[];
    uint32_t* Bu1 = smu + N2_OB1;
    uint32_t* Bu2 = smu + N2_OB2;
    uint32_t* T1  = smu + N2_OT1;
    float* sb2 = (float*)(smu + N2_OS2);
    float* slb = (float*)(smu + N2_OSL);

    const int tid = threadIdx.x, wid = tid >> 5, lane = tid & 31;
    const int half = wid >> 3, w8 = wid & 7;
    const int qr = lane >> 2, qc = lane & 3;

    for (int i = tid; i < 128 * 64; i += 512) {
        int kp = i >> 7, n = i & 127;
        uint32_t hh, ll;
        split2(W2[(2 * kp) * 128 + n], W2[(2 * kp + 1) * 128 + n], hh, ll);
        Bu1[n * 132 + kp] = hh; Bu1[n * 132 + 64 + kp] = ll;
        split2(Wl[(2 * kp) * 128 + n], Wl[(2 * kp + 1) * 128 + n], hh, ll);
        Bu2[n * 132 + kp] = hh; Bu2[n * 132 + 64 + kp] = ll;
    }
    if (tid < 128) { sb2[tid] = b2[tid]; slb[tid] = lb[tid]; }
    __syncthreads();

    const int r0 = w8 * 16 + qr;
    const long base = (long)blockIdx.x * 128;

    {
        float acc[8][4];
        #pragma unroll
        for (int nb = 0; nb < 8; nb++) { acc[nb][0]=0.f; acc[nb][1]=0.f; acc[nb][2]=0.f; acc[nb][3]=0.f; }
        #pragma unroll
        for (int ks = 0; ks < 8; ks++) {
            const float* xr = agg + (base + r0) * 128 + ks * 16 + 2 * qc;
            float2 v00 = *(const float2*)xr;
            float2 v01 = *(const float2*)(xr + 8);
            float2 v10 = *(const float2*)(xr + 8 * 128);
            float2 v11 = *(const float2*)(xr + 8 * 128 + 8);
            uint32_t aH0,aH1,aH2,aH3,aL0,aL1,aL2,aL3;
            split2(v00.x, v00.y, aH0, aL0);
            split2(v10.x, v10.y, aH1, aL1);
            split2(v01.x, v01.y, aH2, aL2);
            split2(v11.x, v11.y, aH3, aL3);
            #pragma unroll
            for (int nb = 0; nb < 8; nb++) {
                int noff = ((half * 8 + nb) * 8 + qr) * 132 + ks * 8 + qc;
                uint32_t bh0 = Bu1[noff], bh1 = Bu1[noff + 4];
                mma16816(acc[nb], aH0, aH1, aH2, aH3, bh0, bh1);
                mma16816(acc[nb], aL0, aL1, aL2, aL3, bh0, bh1);
                uint32_t bl0 = Bu1[noff + 64], bl1 = Bu1[noff + 68];
                mma16816(acc[nb], aH0, aH1, aH2, aH3, bl0, bl1);
            }
        }
        #pragma unroll
        for (int nb = 0; nb < 8; nb++) {
            int c = (half * 8 + nb) * 8 + 2 * qc;
            int kp = (c >> 1);
            float bx = sb2[c], by = sb2[c + 1];
            uint32_t hh, ll;
            split2(sspf(acc[nb][0] + bx), sspf(acc[nb][1] + by), hh, ll);
            T1[r0 * 132 + kp] = hh; T1[r0 * 132 + 64 + kp] = ll;
            split2(sspf(acc[nb][2] + bx), sspf(acc[nb][3] + by), hh, ll);
            T1[(r0 + 8) * 132 + kp] = hh; T1[(r0 + 8) * 132 + 64 + kp] = ll;
        }
    }
    __syncthreads();

    if (cf1n) {
        for (int i = tid; i < 128 * 64; i += 512) {
            int kp = i >> 7, n = i & 127;
            uint32_t hh, ll;
            split2(cf1n[(2 * kp) * 128 + n], cf1n[(2 * kp + 1) * 128 + n], hh, ll);
            Bu1[n * 132 + kp] = hh; Bu1[n * 132 + 64 + kp] = ll;
        }
    }

    {
        float acc[8][4];
        #pragma unroll
        for (int nb = 0; nb < 8; nb++) { acc[nb][0]=0.f; acc[nb][1]=0.f; acc[nb][2]=0.f; acc[nb][3]=0.f; }
        #pragma unroll
        for (int ks = 0; ks < 8; ks++) {
            int xo0 = r0 * 132 + ks * 8 + qc;
            int xo1 = (r0 + 8) * 132 + ks * 8 + qc;
            uint32_t aH0 = T1[xo0],      aH1 = T1[xo1];
            uint32_t aH2 = T1[xo0 + 4],  aH3 = T1[xo1 + 4];
            uint32_t aL0 = T1[xo0 + 64], aL1 = T1[xo1 + 64];
            uint32_t aL2 = T1[xo0 + 68], aL3 = T1[xo1 + 68];
            #pragma unroll
            for (int nb = 0; nb < 8; nb++) {
                int noff = ((half * 8 + nb) * 8 + qr) * 132 + ks * 8 + qc;
                uint32_t bh0 = Bu2[noff], bh1 = Bu2[noff + 4];
                mma16816(acc[nb], aH0, aH1, aH2, aH3, bh0, bh1);
                mma16816(acc[nb], aL0, aL1, aL2, aL3, bh0, bh1);
                uint32_t bl0 = Bu2[noff + 64], bl1 = Bu2[noff + 68];
                mma16816(acc[nb], aH0, aH1, aH2, aH3, bl0, bl1);
            }
        }
        #pragma unroll
        for (int nb = 0; nb < 8; nb++) {
            int c = (half * 8 + nb) * 8 + 2 * qc;
            float bx = slb[c], by = slb[c + 1];
            float* y0 = h + (base + r0) * 128 + c;
            float* y1 = h + (base + r0 + 8) * 128 + c;
            float2 p0 = *(float2*)y0, p1 = *(float2*)y1;
            float v0 = p0.x + acc[nb][0] + bx, v1 = p0.y + acc[nb][1] + by;
            float v2 = p1.x + acc[nb][2] + bx, v3 = p1.y + acc[nb][3] + by;
            *(float2*)y0 = make_float2(v0, v1);
            *(float2*)y1 = make_float2(v2, v3);
            if (cf1n) {
                int kp = c >> 1;
                uint32_t hh, ll;
                split2(v0, v1, hh, ll);
                T1[r0 * 132 + kp] = hh; T1[r0 * 132 + 64 + kp] = ll;
                split2(v2, v3, hh, ll);
                T1[(r0 + 8) * 132 + kp] = hh; T1[(r0 + 8) * 132 + 64 + kp] = ll;
            }
        }
    }

    if (!cf1n) return;
    __syncthreads();

    {
        float acc[8][4];
        #pragma unroll
        for (int nb = 0; nb < 8; nb++) { acc[nb][0]=0.f; acc[nb][1]=0.f; acc[nb][2]=0.f; acc[nb][3]=0.f; }
        #pragma unroll
        for (int ks = 0; ks < 8; ks++) {
            int xo0 = r0 * 132 + ks * 8 + qc;
            int xo1 = (r0 + 8) * 132 + ks * 8 + qc;
            uint32_t aH0 = T1[xo0],      aH1 = T1[xo1];
            uint32_t aH2 = T1[xo0 + 4],  aH3 = T1[xo1 + 4];
            uint32_t aL0 = T1[xo0 + 64], aL1 = T1[xo1 + 64];
            uint32_t aL2 = T1[xo0 + 68], aL3 = T1[xo1 + 68];
            #pragma unroll
            for (int nb = 0; nb < 8; nb++) {
                int noff = ((half * 8 + nb) * 8 + qr) * 132 + ks * 8 + qc;
                uint32_t bh0 = Bu1[noff], bh1 = Bu1[noff + 4];
                mma16816(acc[nb], aH0, aH1, aH2, aH3, bh0, bh1);
                mma16816(acc[nb], aL0, aL1, aL2, aL3, bh0, bh1);
                uint32_t bl0 = Bu1[noff + 64], bl1 = Bu1[noff + 68];
                mma16816(acc[nb], aH0, aH1, aH2, aH3, bl0, bl1);
            }
        }
        #pragma unroll
        for (int nb = 0; nb < 8; nb++) {
            int c = (half * 8 + nb) * 8 + 2 * qc;
            *(float2*)(hx + (base + r0) * 128 + c)     = make_float2(acc[nb][0], acc[nb][1]);
            *(float2*)(hx + (base + r0 + 8) * 128 + c) = make_float2(acc[nb][2], acc[nb][3]);
        }
    }
}

// ---------------------------------------------------------------------------
// Table builder (TAB_N grid)
// ---------------------------------------------------------------------------
#define BLD_OB1 0
#define BLD_OB2 8704
#define BLD_OT1 25600
#define BLD_OS1 42496
#define BLD_OS2 42624
#define BLD_SMEM ((42752) * 4)

__global__ __launch_bounds__(512, 1)
void k_build(const float* __restrict__ w1all, const float* __restrict__ b1all,
             const float* __restrict__ w2all, const float* __restrict__ b2all)
{
    extern __shared__ uint32_t smu[];
    uint32_t* B1u = smu + BLD_OB1;
    uint32_t* B2u = smu + BLD_OB2;
    uint32_t* T1  = smu + BLD_OT1;
    float* sb1 = (float*)(smu + BLD_OS1);
    float* sb2 = (float*)(smu + BLD_OS2);

    const int tpl = TAB_N / 128;
    const int l = blockIdx.x / tpl, t = blockIdx.x % tpl;
    const float* w1 = w1all + (long)l * GDIM * HDIM;
    const float* b1 = b1all + (long)l * HDIM;
    const float* w2 = w2all + (long)l * HDIM * HDIM;
    const float* b2 = b2all + (long)l * HDIM;

    const int tid = threadIdx.x, wid = tid >> 5, lane = tid & 31;
    const int half = wid >> 3, w8 = wid & 7;
    const int qr = lane >> 2, qc = lane & 3;

    for (int i = tid; i < 128 * 32; i += 512) {
        int kp = i >> 7, n = i & 127, k = 2 * kp;
        float v0 = (k < GDIM)     ? w1[k * 128 + n]       : 0.f;
        float v1 = (k + 1 < GDIM) ? w1[(k + 1) * 128 + n] : 0.f;
        uint32_t h, lv; split2(v0, v1, h, lv);
        B1u[n * 68 + kp] = h;
        B1u[n * 68 + 32 + kp] = lv;
    }
    for (int i = tid; i < 128 * 64; i += 512) {
        int kp = i >> 7, n = i & 127;
        uint32_t h, lv;
        split2(w2[(2 * kp) * 128 + n], w2[(2 * kp + 1) * 128 + n], h, lv);
        B2u[n * 132 + kp] = h;
        B2u[n * 132 + 64 + kp] = lv;
    }
    if (tid < 128) { sb1[tid] = b1[tid]; sb2[tid] = b2[tid]; }
    __syncthreads();

    const float step  = CUTOFF / (GDIM - 1);
    const float coeff = -0.5f / (step * step);
    const float PIOC  = 3.14159265358979f / CUTOFF;
    const float DELTA = CUTOFF / (float)TAB_N;
    const int r0 = w8 * 16 + qr;

    float dv0 = (float)(t * 128 + r0) * DELTA;
    float dv1 = (float)(t * 128 + r0 + 8) * DELTA;

    uint32_t aH[4][4], aL[4][4];
    #pragma unroll
    for (int ks = 0; ks < 4; ks++) {
        float g0 = (float)(ks * 16 + 2 * qc) * step;
        eaf(dv0, g0,            step, coeff, aH[ks][0], aL[ks][0]);
        eaf(dv1, g0,            step, coeff, aH[ks][1], aL[ks][1]);
        eaf(dv0, g0 + 8.f*step, step, coeff, aH[ks][2], aL[ks][2]);
        eaf(dv1, g0 + 8.f*step, step, coeff, aH[ks][3], aL[ks][3]);
    }

    #pragma unroll
    for (int nb = 0; nb < 8; nb++) {
        float acc[4] = {0.f, 0.f, 0.f, 0.f};
        #pragma unroll
        for (int ks = 0; ks < 4; ks++) {
            int noff = ((half * 8 + nb) * 8 + qr) * 68 + ks * 8 + qc;
            uint32_t bh0 = B1u[noff], bh1 = B1u[noff + 4];
            mma16816(acc, aH[ks][0], aH[ks][1], aH[ks][2], aH[ks][3], bh0, bh1);
            mma16816(acc, aL[ks][0], aL[ks][1], aL[ks][2], aL[ks][3], bh0, bh1);
            uint32_t bl0 = B1u[noff + 32], bl1 = B1u[noff + 36];
            mma16816(acc, aH[ks][0], aH[ks][1], aH[ks][2], aH[ks][3], bl0, bl1);
        }
        int c = (half * 8 + nb) * 8 + 2 * qc;
        int kp = c >> 1;
        float bx = sb1[c], by = sb1[c + 1];
        uint32_t hh, ll;
        split2(sspf(acc[0] + bx), sspf(acc[1] + by), hh, ll);
        T1[r0 * 132 + kp] = hh; T1[r0 * 132 + 64 + kp] = ll;
        split2(sspf(acc[2] + bx), sspf(acc[3] + by), hh, ll);
        T1[(r0 + 8) * 132 + kp] = hh; T1[(r0 + 8) * 132 + 64 + kp] = ll;
    }
    __syncthreads();

    float acc2[8][4];
    #pragma unroll
    for (int nb = 0; nb < 8; nb++) { acc2[nb][0]=0.f; acc2[nb][1]=0.f; acc2[nb][2]=0.f; acc2[nb][3]=0.f; }
    #pragma unroll
    for (int ks = 0; ks < 8; ks++) {
        int xo0 = r0 * 132 + ks * 8 + qc;
        int xo1 = (r0 + 8) * 132 + ks * 8 + qc;
        uint32_t aH0 = T1[xo0],      aH1 = T1[xo1];
        uint32_t aH2 = T1[xo0 + 4],  aH3 = T1[xo1 + 4];
        uint32_t aL0 = T1[xo0 + 64], aL1 = T1[xo1 + 64];
        uint32_t aL2 = T1[xo0 + 68], aL3 = T1[xo1 + 68];
        #pragma unroll
        for (int nb = 0; nb < 8; nb++) {
            int noff = ((half * 8 + nb) * 8 + qr) * 132 + ks * 8 + qc;
            uint32_t bh0 = B2u[noff], bh1 = B2u[noff + 4];
            mma16816(acc2[nb], aH0, aH1, aH2, aH3, bh0, bh1);
            mma16816(acc2[nb], aL0, aL1, aL2, aL3, bh0, bh1);
            uint32_t bl0 = B2u[noff + 64], bl1 = B2u[noff + 68];
            mma16816(acc2[nb], aH0, aH1, aH2, aH3, bl0, bl1);
        }
    }

    float cc0 = 0.5f * (cosf(dv0 * PIOC) + 1.f);
    float cc1 = 0.5f * (cosf(dv1 * PIOC) + 1.f);
    float* trow = g_wtab + ((long)l * (TAB_N + 1) + t * 128 + r0) * 128;
    #pragma unroll
    for (int nb = 0; nb < 8; nb++) {
        int c = (half * 8 + nb) * 8 + 2 * qc;
        float bx = sb2[c], by = sb2[c + 1];
        *(float2*)(trow + c) =
            make_float2((acc2[nb][0] + bx) * cc0, (acc2[nb][1] + by) * cc0);
        *(float2*)(trow + 8 * 128 + c) =
            make_float2((acc2[nb][2] + bx) * cc1, (acc2[nb][3] + by) * cc1);
    }
}

// ---------------------------------------------------------------------------
// Column-split table-lookup edge kernel: CTA = (molecule, 64-col half).
// 256 threads, 27.8 KB SMEM, 6 CTAs/SM target.
// ---------------------------------------------------------------------------
#define E2_HX 0
#define E2_SB 2176
#define E2_SD 6528
#define E2_IL 6592
#define E2_JL 6656
#define E2_JP 6720
#define E2_IO 6784
#define E2_JO 6817
#define E2_PS 6850
#define E2_W  6946
#define ETAB_SMEM (E2_W * 4)

__global__ __launch_bounds__(256, 6)
void k_edge_tab(const float* __restrict__ pos, const float* __restrict__ wtab)
{
    extern __shared__ float sm[];
    float* hxs  = sm + E2_HX;     // 32 x 68
    float* sbuf = sm + E2_SB;     // 64 x 68
    float* sd   = sm + E2_SD;
    int*   sil  = (int*)(sm + E2_IL);
    int*   sjl  = (int*)(sm + E2_JL);
    int*   sjp  = (int*)(sm + E2_JP);
    int*   siof = (int*)(sm + E2_IO);
    int*   sjof = (int*)(sm + E2_JO);
    float* ps   = sm + E2_PS;

    const int tid = threadIdx.x, wid = tid >> 5, lane = tid & 31;
    const int m = blockIdx.x >> 1, ch = blockIdx.x & 1;
    const int cb = ch * 64;
    const int a_own = tid >> 3, c_own = (tid & 7) * 8;
    const float SCALE = (float)TAB_N / CUTOFF;

    int nu = g_ucnt[m];
    int nt = (nu + TS - 1) / TS;

    for (int i = tid; i < APM * 64; i += 256) {
        int a = i >> 6, c = i & 63;
        hxs[a * 68 + c] = g_hx[(long)(m * APM + a) * 128 + cb + c];
    }
    if (tid < 96) ps[tid] = pos[m * 96 + tid];
    float4 agg0 = make_float4(0,0,0,0), agg1 = agg0;
    __syncthreads();

    for (int t = 0; t < nt; t++) {
        if (tid < TS) {
            int k = t * TS + tid;
            float d = 0.f; int il = 0, jl = 0;
            if (k < nu) {
                unsigned pk = g_upak[m * 512 + k];
                il = (int)(pk >> 8); jl = (int)(pk & 255);
                float dx = ps[3*il]   - ps[3*jl];
                float dy = ps[3*il+1] - ps[3*jl+1];
                float dz = ps[3*il+2] - ps[3*jl+2];
                d = sqrtf(dx*dx + dy*dy + dz*dz);
            }
            sd[tid] = d; sil[tid] = il; sjl[tid] = jl;
            sjp[tid] = g_jperm[m * 512 + t * TS + tid];
        }
        if (tid >= 64 && tid < 97)   siof[tid - 64]  = g_ioff[(m * TILES + t) * 33 + tid - 64];
        if (tid >= 128 && tid < 161) sjof[tid - 128] = g_joff[(m * TILES + t) * 33 + tid - 128];
        __syncthreads();

        // fill sbuf: w(e, cb..cb+63) via lerp; half-warp per row
        #pragma unroll
        for (int it = 0; it < 4; it++) {
            int e = wid * 8 + it * 2 + (lane >> 4);
            int col4 = lane & 15;
            float d = sd[e];
            float tt = d * SCALE;
            int i0 = (int)tt;
            i0 = (i0 > TAB_N - 1) ? (TAB_N - 1) : i0;
            float f = tt - (float)i0;
            const float4* T0 = (const float4*)(wtab + (long)i0 * 128 + cb);
            float4 wa = T0[col4];
            float4 wb = T0[32 + col4];   // next row = +128 floats = +32 float4
            float4 wv;
            wv.x = wa.x + f * (wb.x - wa.x);
            wv.y = wa.y + f * (wb.y - wa.y);
            wv.z = wa.z + f * (wb.z - wa.z);
            wv.w = wa.w + f * (wb.w - wa.w);
            *(float4*)&sbuf[e * 68 + col4 * 4] = wv;
        }
        __syncthreads();

        // both-direction segmented reduction (8 cols per thread)
        for (int r = siof[a_own]; r < siof[a_own + 1]; r++) {
            const float4* wp = (const float4*)&sbuf[r * 68 + c_own];
            const float4* hp = (const float4*)&hxs[sjl[r] * 68 + c_own];
            float4 w0 = wp[0], w1v = wp[1];
            float4 h0 = hp[0], h1 = hp[1];
            agg0.x += w0.x*h0.x; agg0.y += w0.y*h0.y; agg0.z += w0.z*h0.z; agg0.w += w0.w*h0.w;
            agg1.x += w1v.x*h1.x; agg1.y += w1v.y*h1.y; agg1.z += w1v.z*h1.z; agg1.w += w1v.w*h1.w;
        }
        for (int kk = sjof[a_own]; kk < sjof[a_own + 1]; kk++) {
            int r = sjp[kk];
            const float4* wp = (const float4*)&sbuf[r * 68 + c_own];
            const float4* hp = (const float4*)&hxs[sil[r] * 68 + c_own];
            float4 w0 = wp[0], w1v = wp[1];
            float4 h0 = hp[0], h1 = hp[1];
            agg0.x += w0.x*h0.x; agg0.y += w0.y*h0.y; agg0.z += w0.z*h0.z; agg0.w += w0.w*h0.w;
            agg1.x += w1v.x*h1.x; agg1.y += w1v.y*h1.y; agg1.z += w1v.z*h1.z; agg1.w += w1v.w*h1.w;
        }
        __syncthreads();
    }

    float* ap = g_agg + (long)(m * APM + a_own) * 128 + cb + c_own;
    ((float4*)ap)[0] = agg0;
    ((float4*)ap)[1] = agg1;
}

// ---------------------------------------------------------------------------
__global__ __launch_bounds__(256) void k_out(
    const float* __restrict__ out1_w, const float* __restrict__ out1_b,
    const float* __restrict__ out2_w, const float* __restrict__ out2_b,
    const int* __restrict__ batch, float* __restrict__ out)
{
    __shared__ float W1[128 * 64];
    __shared__ float w2s[64];
    __shared__ float xs[8][128];

    int tid = threadIdx.x;
    for (int i = tid; i < 128 * 64; i += 256) W1[i] = out1_w[i];
    if (tid < 64) w2s[tid] = out2_w[tid];
    __syncthreads();

    int warp = tid >> 5, lane = tid & 31;
    float ob0 = out1_b[lane], ob1 = out1_b[lane + 32];
    float b2v = out2_b[0];

    for (int row = blockIdx.x * 8 + warp; row < NATOMS; row += gridDim.x * 8) {
        ((float4*)xs[warp])[lane] = ((const float4*)(g_h + (long)row * 128))[lane];
        __syncwarp();
        float a0 = ob0, a1 = ob1;
        #pragma unroll 8
        for (int k = 0; k < 128; k++) {
            float xv = xs[warp][k];
            a0 += xv * W1[k * 64 + lane];
            a1 += xv * W1[k * 64 + lane + 32];
        }
        float v = sspf(a0) * w2s[lane] + sspf(a1) * w2s[lane + 32];
        #pragma unroll
        for (int off = 16; off; off >>= 1) v += __shfl_down_sync(0xffffffffu, v, off);
        if (lane == 0) atomicAdd(&out[batch[row]], v + b2v);
        __syncwarp();
    }
}

// ---------------------------------------------------------------------------
extern "C" void kernel_launch(void* const* d_in, const int* in_sizes, int n_in,
                              void* d_out, int out_size)
{
    const int*   z       = (const int*)  d_in[0];
    const float* pos     = (const float*)d_in[1];
    const int*   batch   = (const int*)  d_in[2];
    const int*   ei      = (const int*)  d_in[3];
    const float* emb     = (const float*)d_in[4];
    const float* mlp_w1  = (const float*)d_in[5];
    const float* mlp_b1  = (const float*)d_in[6];
    const float* mlp_w2  = (const float*)d_in[7];
    const float* mlp_b2  = (const float*)d_in[8];
    const float* cf1_w   = (const float*)d_in[9];
    const float* cf2_w   = (const float*)d_in[10];
    const float* cf2_b   = (const float*)d_in[11];
    const float* lin_w   = (const float*)d_in[12];
    const float* lin_b   = (const float*)d_in[13];
    const float* out1_w  = (const float*)d_in[14];
    const float* out1_b  = (const float*)d_in[15];
    const float* out2_w  = (const float*)d_in[16];
    const float* out2_b  = (const float*)d_in[17];

    int E = in_sizes[3] / 2;
    const int* src = ei;
    const int* dst = ei + E;

    cudaFuncSetAttribute(k_build, cudaFuncAttributeMaxDynamicSharedMemorySize, BLD_SMEM);
    cudaFuncSetAttribute(k_edge_tab, cudaFuncAttributeMaxDynamicSharedMemorySize, ETAB_SMEM);
    cudaFuncSetAttribute(k_n1, cudaFuncAttributeMaxDynamicSharedMemorySize, N1_SMEM);
    cudaFuncSetAttribute(k_n2x, cudaFuncAttributeMaxDynamicSharedMemorySize, N2_SMEM);

    float *ph, *phx, *pagg, *ptab;
    cudaGetSymbolAddress((void**)&ph,   g_h);
    cudaGetSymbolAddress((void**)&phx,  g_hx);
    cudaGetSymbolAddress((void**)&pagg, g_agg);
    cudaGetSymbolAddress((void**)&ptab, g_wtab);

    float* out = (float*)d_out;

    k_moff<<<3, 256>>>(src, E);
    k_prep<<<NMOL, 128>>>(src, dst);
    k_ztab<<<LINT, 128>>>();
    k_build<<<LINT * (TAB_N / 128), 512, BLD_SMEM>>>(mlp_w1, mlp_b1, mlp_w2, mlp_b2);
    k_embed<<<(NATOMS*HDIM + 255)/256, 256>>>(z, emb);
    k_n1<<<128, 512, N1_SMEM>>>(ph, cf1_w, phx);

    for (int l = 0; l < LINT; l++) {
        k_edge_tab<<<NMOL * 2, 256, ETAB_SMEM>>>(pos, ptab + (long)l * (TAB_N + 1) * HDIM);
        const float* cf1n = (l + 1 < LINT) ? (cf1_w + (long)(l + 1) * HDIM * HDIM) : nullptr;
        k_n2x<<<128, 512, N2_SMEM>>>(
            pagg, cf2_w + (long)l*HDIM*HDIM, cf2_b + (long)l*HDIM,
            lin_w + (long)l*HDIM*HDIM, lin_b + (long)l*HDIM, ph,
            cf1n, phx);
    }

    k_zero_out<<<1, 512>>>(out);
    k_out<<<256, 256>>>(out1_w, out1_b, out2_w, out2_b, batch, out);
}

// round 11
// speedup vs baseline: 4.5316x; 1.0429x over previous
#include <cuda_runtime.h>
#include <cuda_bf16.h>
#include <math.h>
#include <stdint.h>

#define NATOMS 16384
#define NMOL   512
#define APM    32
#define HDIM   128
#define GDIM   50
#define LINT   3
#define CUTOFF 6.0f
#define TAB_N  2048
#define TILES  8
#define TS     64

// Scratch (allocation-free)
__device__ float g_h  [NATOMS * HDIM];
__device__ float g_hx [NATOMS * HDIM];
__device__ float g_agg[NATOMS * HDIM];
__device__ int   g_ucnt[NMOL];
__device__ unsigned g_upak[NMOL * 512];
__device__ int   g_ioff[NMOL * TILES * 33];
__device__ int   g_joff[NMOL * TILES * 33];
__device__ int   g_jperm[NMOL * 512];
__device__ float g_wtab[LINT * (TAB_N + 1) * HDIM];

__device__ __forceinline__ float sspf(float x) {
    const float LN2 = 0.6931471805599453f;
    if (x > 20.f) return x - LN2;
    return __logf(1.f + __expf(x)) - LN2;
}
__device__ __forceinline__ void split2(float v0, float v1, uint32_t& hi, uint32_t& lo) {
    __nv_bfloat16 h0 = __float2bfloat16(v0), h1 = __float2bfloat16(v1);
    __nv_bfloat16 l0 = __float2bfloat16(v0 - __bfloat162float(h0));
    __nv_bfloat16 l1 = __float2bfloat16(v1 - __bfloat162float(h1));
    hi = (uint32_t)__bfloat16_as_ushort(h0) | ((uint32_t)__bfloat16_as_ushort(h1) << 16);
    lo = (uint32_t)__bfloat16_as_ushort(l0) | ((uint32_t)__bfloat16_as_ushort(l1) << 16);
}
__device__ __forceinline__ void mma16816(float* d,
    uint32_t a0, uint32_t a1, uint32_t a2, uint32_t a3, uint32_t b0, uint32_t b1) {
    asm volatile(
        "mma.sync.aligned.m16n8k16.row.col.f32.bf16.bf16.f32 "
        "{%0,%1,%2,%3}, {%4,%5,%6,%7}, {%8,%9}, {%0,%1,%2,%3};"
        : "+f"(d[0]), "+f"(d[1]), "+f"(d[2]), "+f"(d[3])
        : "r"(a0), "r"(a1), "r"(a2), "r"(a3), "r"(b0), "r"(b1));
}
__device__ __forceinline__ void eaf(float d, float gofs, float step, float coeff,
                                    uint32_t& hi, uint32_t& lo) {
    float u0 = d - gofs, u1 = d - gofs - step;
    float e0 = __expf(coeff * u0 * u0);
    float e1 = __expf(coeff * u1 * u1);
    split2(e0, e1, hi, lo);
}

// ---------------------------------------------------------------------------
// Prepass with fused moff: binary search per CTA, then compact + offsets.
// ---------------------------------------------------------------------------
__global__ __launch_bounds__(128) void k_prep(const int* __restrict__ src,
                                              const int* __restrict__ dst, int E) {
    __shared__ unsigned spak[TS];
    __shared__ int scnt2[33];
    __shared__ int snu;
    __shared__ int sbounds[2];
    int m = blockIdx.x;
    int tid = threadIdx.x, lane = tid & 31, wid = tid >> 5;

    if (tid < 2) {
        int target = (m + tid) * APM;
        int lo = 0, hi = E;
        while (lo < hi) { int mid = (lo + hi) >> 1; if (src[mid] < target) lo = mid + 1; else hi = mid; }
        sbounds[tid] = lo;
    }
    __syncthreads();
    int e0 = sbounds[0], e1 = sbounds[1];

    if (wid == 0) {
        int cnt = 0;
        for (int base = e0; base < e1; base += 32) {
            int e = base + lane;
            bool p = false; unsigned pk = 0;
            if (e < e1) {
                int s = src[e] - m * APM, d2 = dst[e] - m * APM;
                if (d2 > s) { p = true; pk = (unsigned)((s << 8) | d2); }
            }
            unsigned msk = __ballot_sync(0xffffffffu, p);
            if (p) g_upak[m * 512 + cnt + __popc(msk & ((1u << lane) - 1))] = pk;
            cnt += __popc(msk);
        }
        if (lane == 0) { g_ucnt[m] = cnt; snu = cnt; }
    }
    __syncthreads();
    int nu = snu;
    int nt = (nu + TS - 1) / TS;

    for (int t = 0; t < nt; t++) {
        int nr = nu - t * TS; if (nr > TS) nr = TS;
        if (tid < TS) spak[tid] = (tid < nr) ? g_upak[m * 512 + t * TS + tid] : 0xffffffffu;
        __syncthreads();
        if (wid == 0) {
            int a = lane, c = 0;
            for (int r = 0; r < nr; r++) c += ((int)(spak[r] >> 8) < a) ? 1 : 0;
            g_ioff[(m * TILES + t) * 33 + a] = c;
            if (lane == 0) g_ioff[(m * TILES + t) * 33 + 32] = nr;
        }
        if (wid == 1) {
            int a = lane, c = 0;
            for (int r = 0; r < nr; r++) c += ((int)(spak[r] & 255) == a) ? 1 : 0;
            int x = c;
            #pragma unroll
            for (int o = 1; o < 32; o <<= 1) {
                int y = __shfl_up_sync(0xffffffffu, x, o);
                if (lane >= o) x += y;
            }
            int excl = x - c;
            g_joff[(m * TILES + t) * 33 + a] = excl;
            scnt2[a] = excl;
            if (lane == 31) g_joff[(m * TILES + t) * 33 + 32] = excl + c;
        }
        __syncthreads();
        if (tid == 0) {
            for (int r = 0; r < nr; r++) {
                int j = (int)(spak[r] & 255);
                g_jperm[m * 512 + t * TS + scnt2[j]] = r;
                scnt2[j]++;
            }
        }
        __syncthreads();
    }
}

// ---------------------------------------------------------------------------
// Fused embed + node GEMM: h = emb[z]; hx = h @ W.  One CTA = 128 rows.
// ---------------------------------------------------------------------------
#define N1_SMEM (128 * 132 * 4)

__global__ __launch_bounds__(512, 1) void k_n1e(
    const int* __restrict__ z, const float* __restrict__ emb,
    const float* __restrict__ W, float* __restrict__ h, float* __restrict__ hx)
{
    extern __shared__ uint32_t smu[];
    uint32_t* Bu = smu;
    const int tid = threadIdx.x, wid = tid >> 5, lane = tid & 31;
    const int half = wid >> 3, w8 = wid & 7;
    const int qr = lane >> 2, qc = lane & 3;

    for (int i = tid; i < 128 * 64; i += 512) {
        int kp = i >> 7, n = i & 127;
        uint32_t hh, ll;
        split2(W[(2 * kp) * 128 + n], W[(2 * kp + 1) * 128 + n], hh, ll);
        Bu[n * 132 + kp] = hh;
        Bu[n * 132 + 64 + kp] = ll;
    }
    __syncthreads();

    const int r0 = w8 * 16 + qr;
    const long base = (long)blockIdx.x * 128;
    const long za = (long)z[base + r0], zb = (long)z[base + r0 + 8];

    float acc[8][4];
    #pragma unroll
    for (int nb = 0; nb < 8; nb++) { acc[nb][0]=0.f; acc[nb][1]=0.f; acc[nb][2]=0.f; acc[nb][3]=0.f; }

    #pragma unroll
    for (int ks = 0; ks < 8; ks++) {
        const float* xr0 = emb + za * 128 + ks * 16 + 2 * qc;
        const float* xr1 = emb + zb * 128 + ks * 16 + 2 * qc;
        float2 v00 = *(const float2*)xr0;
        float2 v01 = *(const float2*)(xr0 + 8);
        float2 v10 = *(const float2*)xr1;
        float2 v11 = *(const float2*)(xr1 + 8);
        if (half == 0) {   // write h = emb[z] (each element exactly once)
            *(float2*)(h + (base + r0) * 128 + ks * 16 + 2 * qc)         = v00;
            *(float2*)(h + (base + r0) * 128 + ks * 16 + 8 + 2 * qc)     = v01;
            *(float2*)(h + (base + r0 + 8) * 128 + ks * 16 + 2 * qc)     = v10;
            *(float2*)(h + (base + r0 + 8) * 128 + ks * 16 + 8 + 2 * qc) = v11;
        }
        uint32_t aH0,aH1,aH2,aH3,aL0,aL1,aL2,aL3;
        split2(v00.x, v00.y, aH0, aL0);
        split2(v10.x, v10.y, aH1, aL1);
        split2(v01.x, v01.y, aH2, aL2);
        split2(v11.x, v11.y, aH3, aL3);
        #pragma unroll
        for (int nb = 0; nb < 8; nb++) {
            int noff = ((half * 8 + nb) * 8 + qr) * 132 + ks * 8 + qc;
            uint32_t bh0 = Bu[noff], bh1 = Bu[noff + 4];
            mma16816(acc[nb], aH0, aH1, aH2, aH3, bh0, bh1);
            mma16816(acc[nb], aL0, aL1, aL2, aL3, bh0, bh1);
            uint32_t bl0 = Bu[noff + 64], bl1 = Bu[noff + 68];
            mma16816(acc[nb], aH0, aH1, aH2, aH3, bl0, bl1);
        }
    }

    #pragma unroll
    for (int nb = 0; nb < 8; nb++) {
        int c = (half * 8 + nb) * 8 + 2 * qc;
        *(float2*)(hx + (base + r0) * 128 + c)     = make_float2(acc[nb][0], acc[nb][1]);
        *(float2*)(hx + (base + r0 + 8) * 128 + c) = make_float2(acc[nb][2], acc[nb][3]);
    }
}

// ---------------------------------------------------------------------------
// Fused node chain (R9) + zero-out fold on last layer.
// ---------------------------------------------------------------------------
#define N2_OB1 0
#define N2_OB2 16896
#define N2_OT1 33792
#define N2_OS2 50688
#define N2_OSL 50816
#define N2_SMEM ((50944) * 4)

__global__ __launch_bounds__(512, 1) void k_n2x(
    const float* __restrict__ agg,
    const float* __restrict__ W2, const float* __restrict__ b2,
    const float* __restrict__ Wl, const float* __restrict__ lb,
    float* __restrict__ h,
    const float* __restrict__ cf1n, float* __restrict__ hx,
    float* __restrict__ out)
{
    extern __shared__ uint32_t smu[];
    uint32_t* Bu1 = smu + N2_OB1;
    uint32_t* Bu2 = smu + N2_OB2;
    uint32_t* T1  = smu + N2_OT1;
    float* sb2 = (float*)(smu + N2_OS2);
    float* slb = (float*)(smu + N2_OSL);

    const int tid = threadIdx.x, wid = tid >> 5, lane = tid & 31;
    const int half = wid >> 3, w8 = wid & 7;
    const int qr = lane >> 2, qc = lane & 3;

    for (int i = tid; i < 128 * 64; i += 512) {
        int kp = i >> 7, n = i & 127;
        uint32_t hh, ll;
        split2(W2[(2 * kp) * 128 + n], W2[(2 * kp + 1) * 128 + n], hh, ll);
        Bu1[n * 132 + kp] = hh; Bu1[n * 132 + 64 + kp] = ll;
        split2(Wl[(2 * kp) * 128 + n], Wl[(2 * kp + 1) * 128 + n], hh, ll);
        Bu2[n * 132 + kp] = hh; Bu2[n * 132 + 64 + kp] = ll;
    }
    if (tid < 128) { sb2[tid] = b2[tid]; slb[tid] = lb[tid]; }
    if (!cf1n && tid < 4) out[blockIdx.x * 4 + tid] = 0.f;   // zero molecule sums
    __syncthreads();

    const int r0 = w8 * 16 + qr;
    const long base = (long)blockIdx.x * 128;

    {
        float acc[8][4];
        #pragma unroll
        for (int nb = 0; nb < 8; nb++) { acc[nb][0]=0.f; acc[nb][1]=0.f; acc[nb][2]=0.f; acc[nb][3]=0.f; }
        #pragma unroll
        for (int ks = 0; ks < 8; ks++) {
            const float* xr = agg + (base + r0) * 128 + ks * 16 + 2 * qc;
            float2 v00 = *(const float2*)xr;
            float2 v01 = *(const float2*)(xr + 8);
            float2 v10 = *(const float2*)(xr + 8 * 128);
            float2 v11 = *(const float2*)(xr + 8 * 128 + 8);
            uint32_t aH0,aH1,aH2,aH3,aL0,aL1,aL2,aL3;
            split2(v00.x, v00.y, aH0, aL0);
            split2(v10.x, v10.y, aH1, aL1);
            split2(v01.x, v01.y, aH2, aL2);
            split2(v11.x, v11.y, aH3, aL3);
            #pragma unroll
            for (int nb = 0; nb < 8; nb++) {
                int noff = ((half * 8 + nb) * 8 + qr) * 132 + ks * 8 + qc;
                uint32_t bh0 = Bu1[noff], bh1 = Bu1[noff + 4];
                mma16816(acc[nb], aH0, aH1, aH2, aH3, bh0, bh1);
                mma16816(acc[nb], aL0, aL1, aL2, aL3, bh0, bh1);
                uint32_t bl0 = Bu1[noff + 64], bl1 = Bu1[noff + 68];
                mma16816(acc[nb], aH0, aH1, aH2, aH3, bl0, bl1);
            }
        }
        #pragma unroll
        for (int nb = 0; nb < 8; nb++) {
            int c = (half * 8 + nb) * 8 + 2 * qc;
            int kp = (c >> 1);
            float bx = sb2[c], by = sb2[c + 1];
            uint32_t hh, ll;
            split2(sspf(acc[nb][0] + bx), sspf(acc[nb][1] + by), hh, ll);
            T1[r0 * 132 + kp] = hh; T1[r0 * 132 + 64 + kp] = ll;
            split2(sspf(acc[nb][2] + bx), sspf(acc[nb][3] + by), hh, ll);
            T1[(r0 + 8) * 132 + kp] = hh; T1[(r0 + 8) * 132 + 64 + kp] = ll;
        }
    }
    __syncthreads();

    if (cf1n) {
        for (int i = tid; i < 128 * 64; i += 512) {
            int kp = i >> 7, n = i & 127;
            uint32_t hh, ll;
            split2(cf1n[(2 * kp) * 128 + n], cf1n[(2 * kp + 1) * 128 + n], hh, ll);
            Bu1[n * 132 + kp] = hh; Bu1[n * 132 + 64 + kp] = ll;
        }
    }

    {
        float acc[8][4];
        #pragma unroll
        for (int nb = 0; nb < 8; nb++) { acc[nb][0]=0.f; acc[nb][1]=0.f; acc[nb][2]=0.f; acc[nb][3]=0.f; }
        #pragma unroll
        for (int ks = 0; ks < 8; ks++) {
            int xo0 = r0 * 132 + ks * 8 + qc;
            int xo1 = (r0 + 8) * 132 + ks * 8 + qc;
            uint32_t aH0 = T1[xo0],      aH1 = T1[xo1];
            uint32_t aH2 = T1[xo0 + 4],  aH3 = T1[xo1 + 4];
            uint32_t aL0 = T1[xo0 + 64], aL1 = T1[xo1 + 64];
            uint32_t aL2 = T1[xo0 + 68], aL3 = T1[xo1 + 68];
            #pragma unroll
            for (int nb = 0; nb < 8; nb++) {
                int noff = ((half * 8 + nb) * 8 + qr) * 132 + ks * 8 + qc;
                uint32_t bh0 = Bu2[noff], bh1 = Bu2[noff + 4];
                mma16816(acc[nb], aH0, aH1, aH2, aH3, bh0, bh1);
                mma16816(acc[nb], aL0, aL1, aL2, aL3, bh0, bh1);
                uint32_t bl0 = Bu2[noff + 64], bl1 = Bu2[noff + 68];
                mma16816(acc[nb], aH0, aH1, aH2, aH3, bl0, bl1);
            }
        }
        #pragma unroll
        for (int nb = 0; nb < 8; nb++) {
            int c = (half * 8 + nb) * 8 + 2 * qc;
            float bx = slb[c], by = slb[c + 1];
            float* y0 = h + (base + r0) * 128 + c;
            float* y1 = h + (base + r0 + 8) * 128 + c;
            float2 p0 = *(float2*)y0, p1 = *(float2*)y1;
            float v0 = p0.x + acc[nb][0] + bx, v1 = p0.y + acc[nb][1] + by;
            float v2 = p1.x + acc[nb][2] + bx, v3 = p1.y + acc[nb][3] + by;
            *(float2*)y0 = make_float2(v0, v1);
            *(float2*)y1 = make_float2(v2, v3);
            if (cf1n) {
                int kp = c >> 1;
                uint32_t hh, ll;
                split2(v0, v1, hh, ll);
                T1[r0 * 132 + kp] = hh; T1[r0 * 132 + 64 + kp] = ll;
                split2(v2, v3, hh, ll);
                T1[(r0 + 8) * 132 + kp] = hh; T1[(r0 + 8) * 132 + 64 + kp] = ll;
            }
        }
    }

    if (!cf1n) return;
    __syncthreads();

    {
        float acc[8][4];
        #pragma unroll
        for (int nb = 0; nb < 8; nb++) { acc[nb][0]=0.f; acc[nb][1]=0.f; acc[nb][2]=0.f; acc[nb][3]=0.f; }
        #pragma unroll
        for (int ks = 0; ks < 8; ks++) {
            int xo0 = r0 * 132 + ks * 8 + qc;
            int xo1 = (r0 + 8) * 132 + ks * 8 + qc;
            uint32_t aH0 = T1[xo0],      aH1 = T1[xo1];
            uint32_t aH2 = T1[xo0 + 4],  aH3 = T1[xo1 + 4];
            uint32_t aL0 = T1[xo0 + 64], aL1 = T1[xo1 + 64];
            uint32_t aL2 = T1[xo0 + 68], aL3 = T1[xo1 + 68];
            #pragma unroll
            for (int nb = 0; nb < 8; nb++) {
                int noff = ((half * 8 + nb) * 8 + qr) * 132 + ks * 8 + qc;
                uint32_t bh0 = Bu1[noff], bh1 = Bu1[noff + 4];
                mma16816(acc[nb], aH0, aH1, aH2, aH3, bh0, bh1);
                mma16816(acc[nb], aL0, aL1, aL2, aL3, bh0, bh1);
                uint32_t bl0 = Bu1[noff + 64], bl1 = Bu1[noff + 68];
                mma16816(acc[nb], aH0, aH1, aH2, aH3, bl0, bl1);
            }
        }
        #pragma unroll
        for (int nb = 0; nb < 8; nb++) {
            int c = (half * 8 + nb) * 8 + 2 * qc;
            *(float2*)(hx + (base + r0) * 128 + c)     = make_float2(acc[nb][0], acc[nb][1]);
            *(float2*)(hx + (base + r0 + 8) * 128 + c) = make_float2(acc[nb][2], acc[nb][3]);
        }
    }
}

// ---------------------------------------------------------------------------
// Table builder, N-split: CTA = (layer, 128-point tile, column half).
// Full GEMM1 (all 128 T1 cols), half GEMM2 (64 output cols).
// SMEM u32 layout: B1u@0 (8704) | B2u@8704 (8448) | T1@17152 (16896) |
//                  sb1@34048 (128) | sb2@34176 (128)  -> 34304 u32 = 137216 B
// ---------------------------------------------------------------------------
#define BLD_SMEM (34304 * 4)

__global__ __launch_bounds__(512, 1)
void k_build(const float* __restrict__ w1all, const float* __restrict__ b1all,
             const float* __restrict__ w2all, const float* __restrict__ b2all)
{
    extern __shared__ uint32_t smu[];
    uint32_t* B1u = smu;
    uint32_t* B2u = smu + 8704;
    uint32_t* T1  = smu + 17152;
    float* sb1 = (float*)(smu + 34048);
    float* sb2 = (float*)(smu + 34176);

    const int tpl = TAB_N / 128;
    const int ch = blockIdx.x & 1;
    const int t  = (blockIdx.x >> 1) % tpl;
    const int l  = (blockIdx.x >> 1) / tpl;
    const float* w1 = w1all + (long)l * GDIM * HDIM;
    const float* b1 = b1all + (long)l * HDIM;
    const float* w2 = w2all + (long)l * HDIM * HDIM;
    const float* b2 = b2all + (long)l * HDIM;

    const int tid = threadIdx.x, wid = tid >> 5, lane = tid & 31;
    const int half = wid >> 3, w8 = wid & 7;
    const int qr = lane >> 2, qc = lane & 3;

    for (int i = tid; i < 128 * 32; i += 512) {
        int kp = i >> 7, n = i & 127, k = 2 * kp;
        float v0 = (k < GDIM)     ? w1[k * 128 + n]       : 0.f;
        float v1 = (k + 1 < GDIM) ? w1[(k + 1) * 128 + n] : 0.f;
        uint32_t h, lv; split2(v0, v1, h, lv);
        B1u[n * 68 + kp] = h;
        B1u[n * 68 + 32 + kp] = lv;
    }
    // B2u: only output cols [ch*64, ch*64+64)
    for (int i = tid; i < 64 * 64; i += 512) {
        int kp = i >> 6, nl = i & 63;
        int n = ch * 64 + nl;
        uint32_t h, lv;
        split2(w2[(2 * kp) * 128 + n], w2[(2 * kp + 1) * 128 + n], h, lv);
        B2u[nl * 132 + kp] = h;
        B2u[nl * 132 + 64 + kp] = lv;
    }
    if (tid < 128) { sb1[tid] = b1[tid]; sb2[tid] = b2[tid]; }
    __syncthreads();

    const float step  = CUTOFF / (GDIM - 1);
    const float coeff = -0.5f / (step * step);
    const float PIOC  = 3.14159265358979f / CUTOFF;
    const float DELTA = CUTOFF / (float)TAB_N;
    const int r0 = w8 * 16 + qr;

    float dv0 = (float)(t * 128 + r0) * DELTA;
    float dv1 = (float)(t * 128 + r0 + 8) * DELTA;

    uint32_t aH[4][4], aL[4][4];
    #pragma unroll
    for (int ks = 0; ks < 4; ks++) {
        float g0 = (float)(ks * 16 + 2 * qc) * step;
        eaf(dv0, g0,            step, coeff, aH[ks][0], aL[ks][0]);
        eaf(dv1, g0,            step, coeff, aH[ks][1], aL[ks][1]);
        eaf(dv0, g0 + 8.f*step, step, coeff, aH[ks][2], aL[ks][2]);
        eaf(dv1, g0 + 8.f*step, step, coeff, aH[ks][3], aL[ks][3]);
    }

    // GEMM1: full (all 128 T1 cols across 16 warps)
    #pragma unroll
    for (int nb = 0; nb < 8; nb++) {
        float acc[4] = {0.f, 0.f, 0.f, 0.f};
        #pragma unroll
        for (int ks = 0; ks < 4; ks++) {
            int noff = ((half * 8 + nb) * 8 + qr) * 68 + ks * 8 + qc;
            uint32_t bh0 = B1u[noff], bh1 = B1u[noff + 4];
            mma16816(acc, aH[ks][0], aH[ks][1], aH[ks][2], aH[ks][3], bh0, bh1);
            mma16816(acc, aL[ks][0], aL[ks][1], aL[ks][2], aL[ks][3], bh0, bh1);
            uint32_t bl0 = B1u[noff + 32], bl1 = B1u[noff + 36];
            mma16816(acc, aH[ks][0], aH[ks][1], aH[ks][2], aH[ks][3], bl0, bl1);
        }
        int c = (half * 8 + nb) * 8 + 2 * qc;
        int kp = c >> 1;
        float bx = sb1[c], by = sb1[c + 1];
        uint32_t hh, ll;
        split2(sspf(acc[0] + bx), sspf(acc[1] + by), hh, ll);
        T1[r0 * 132 + kp] = hh; T1[r0 * 132 + 64 + kp] = ll;
        split2(sspf(acc[2] + bx), sspf(acc[3] + by), hh, ll);
        T1[(r0 + 8) * 132 + kp] = hh; T1[(r0 + 8) * 132 + 64 + kp] = ll;
    }
    __syncthreads();

    // GEMM2: half (64 output cols), 4 nb per warp
    float acc2[4][4];
    #pragma unroll
    for (int nb = 0; nb < 4; nb++) { acc2[nb][0]=0.f; acc2[nb][1]=0.f; acc2[nb][2]=0.f; acc2[nb][3]=0.f; }
    #pragma unroll
    for (int ks = 0; ks < 8; ks++) {
        int xo0 = r0 * 132 + ks * 8 + qc;
        int xo1 = (r0 + 8) * 132 + ks * 8 + qc;
        uint32_t aH0 = T1[xo0],      aH1 = T1[xo1];
        uint32_t aH2 = T1[xo0 + 4],  aH3 = T1[xo1 + 4];
        uint32_t aL0 = T1[xo0 + 64], aL1 = T1[xo1 + 64];
        uint32_t aL2 = T1[xo0 + 68], aL3 = T1[xo1 + 68];
        #pragma unroll
        for (int nb = 0; nb < 4; nb++) {
            int cb = half * 4 + nb;                    // 0..7 col-blocks in our 64
            int noff = (cb * 8 + qr) * 132 + ks * 8 + qc;
            uint32_t bh0 = B2u[noff], bh1 = B2u[noff + 4];
            mma16816(acc2[nb], aH0, aH1, aH2, aH3, bh0, bh1);
            mma16816(acc2[nb], aL0, aL1, aL2, aL3, bh0, bh1);
            uint32_t bl0 = B2u[noff + 64], bl1 = B2u[noff + 68];
            mma16816(acc2[nb], aH0, aH1, aH2, aH3, bl0, bl1);
        }
    }

    float cc0 = 0.5f * (cosf(dv0 * PIOC) + 1.f);
    float cc1 = 0.5f * (cosf(dv1 * PIOC) + 1.f);
    float* trow = g_wtab + ((long)l * (TAB_N + 1) + t * 128 + r0) * 128;
    #pragma unroll
    for (int nb = 0; nb < 4; nb++) {
        int c = ch * 64 + (half * 4 + nb) * 8 + 2 * qc;
        float bx = sb2[c], by = sb2[c + 1];
        *(float2*)(trow + c) =
            make_float2((acc2[nb][0] + bx) * cc0, (acc2[nb][1] + by) * cc0);
        *(float2*)(trow + 8 * 128 + c) =
            make_float2((acc2[nb][2] + bx) * cc1, (acc2[nb][3] + by) * cc1);
    }
    // sentinel row (d >= CUTOFF -> 0); once per layer
    if (t == 0 && ch == 0 && tid < 128)
        g_wtab[((long)l * (TAB_N + 1) + TAB_N) * 128 + tid] = 0.f;
}

// ---------------------------------------------------------------------------
// Column-split table-lookup edge kernel (unchanged from R10)
// ---------------------------------------------------------------------------
#define E2_HX 0
#define E2_SB 2176
#define E2_SD 6528
#define E2_IL 6592
#define E2_JL 6656
#define E2_JP 6720
#define E2_IO 6784
#define E2_JO 6817
#define E2_PS 6850
#define E2_W  6946
#define ETAB_SMEM (E2_W * 4)

__global__ __launch_bounds__(256, 6)
void k_edge_tab(const float* __restrict__ pos, const float* __restrict__ wtab)
{
    extern __shared__ float sm[];
    float* hxs  = sm + E2_HX;
    float* sbuf = sm + E2_SB;
    float* sd   = sm + E2_SD;
    int*   sil  = (int*)(sm + E2_IL);
    int*   sjl  = (int*)(sm + E2_JL);
    int*   sjp  = (int*)(sm + E2_JP);
    int*   siof = (int*)(sm + E2_IO);
    int*   sjof = (int*)(sm + E2_JO);
    float* ps   = sm + E2_PS;

    const int tid = threadIdx.x, wid = tid >> 5, lane = tid & 31;
    const int m = blockIdx.x >> 1, ch = blockIdx.x & 1;
    const int cb = ch * 64;
    const int a_own = tid >> 3, c_own = (tid & 7) * 8;
    const float SCALE = (float)TAB_N / CUTOFF;

    int nu = g_ucnt[m];
    int nt = (nu + TS - 1) / TS;

    for (int i = tid; i < APM * 64; i += 256) {
        int a = i >> 6, c = i & 63;
        hxs[a * 68 + c] = g_hx[(long)(m * APM + a) * 128 + cb + c];
    }
    if (tid < 96) ps[tid] = pos[m * 96 + tid];
    float4 agg0 = make_float4(0,0,0,0), agg1 = agg0;
    __syncthreads();

    for (int t = 0; t < nt; t++) {
        if (tid < TS) {
            int k = t * TS + tid;
            float d = 0.f; int il = 0, jl = 0;
            if (k < nu) {
                unsigned pk = g_upak[m * 512 + k];
                il = (int)(pk >> 8); jl = (int)(pk & 255);
                float dx = ps[3*il]   - ps[3*jl];
                float dy = ps[3*il+1] - ps[3*jl+1];
                float dz = ps[3*il+2] - ps[3*jl+2];
                d = sqrtf(dx*dx + dy*dy + dz*dz);
            }
            sd[tid] = d; sil[tid] = il; sjl[tid] = jl;
            sjp[tid] = g_jperm[m * 512 + t * TS + tid];
        }
        if (tid >= 64 && tid < 97)   siof[tid - 64]  = g_ioff[(m * TILES + t) * 33 + tid - 64];
        if (tid >= 128 && tid < 161) sjof[tid - 128] = g_joff[(m * TILES + t) * 33 + tid - 128];
        __syncthreads();

        #pragma unroll
        for (int it = 0; it < 4; it++) {
            int e = wid * 8 + it * 2 + (lane >> 4);
            int col4 = lane & 15;
            float d = sd[e];
            float tt = d * SCALE;
            int i0 = (int)tt;
            i0 = (i0 > TAB_N - 1) ? (TAB_N - 1) : i0;
            float f = tt - (float)i0;
            const float4* T0 = (const float4*)(wtab + (long)i0 * 128 + cb);
            float4 wa = T0[col4];
            float4 wb = T0[32 + col4];
            float4 wv;
            wv.x = wa.x + f * (wb.x - wa.x);
            wv.y = wa.y + f * (wb.y - wa.y);
            wv.z = wa.z + f * (wb.z - wa.z);
            wv.w = wa.w + f * (wb.w - wa.w);
            *(float4*)&sbuf[e * 68 + col4 * 4] = wv;
        }
        __syncthreads();

        for (int r = siof[a_own]; r < siof[a_own + 1]; r++) {
            const float4* wp = (const float4*)&sbuf[r * 68 + c_own];
            const float4* hp = (const float4*)&hxs[sjl[r] * 68 + c_own];
            float4 w0 = wp[0], w1v = wp[1];
            float4 h0 = hp[0], h1 = hp[1];
            agg0.x += w0.x*h0.x; agg0.y += w0.y*h0.y; agg0.z += w0.z*h0.z; agg0.w += w0.w*h0.w;
            agg1.x += w1v.x*h1.x; agg1.y += w1v.y*h1.y; agg1.z += w1v.z*h1.z; agg1.w += w1v.w*h1.w;
        }
        for (int kk = sjof[a_own]; kk < sjof[a_own + 1]; kk++) {
            int r = sjp[kk];
            const float4* wp = (const float4*)&sbuf[r * 68 + c_own];
            const float4* hp = (const float4*)&hxs[sil[r] * 68 + c_own];
            float4 w0 = wp[0], w1v = wp[1];
            float4 h0 = hp[0], h1 = hp[1];
            agg0.x += w0.x*h0.x; agg0.y += w0.y*h0.y; agg0.z += w0.z*h0.z; agg0.w += w0.w*h0.w;
            agg1.x += w1v.x*h1.x; agg1.y += w1v.y*h1.y; agg1.z += w1v.z*h1.z; agg1.w += w1v.w*h1.w;
        }
        __syncthreads();
    }

    float* ap = g_agg + (long)(m * APM + a_own) * 128 + cb + c_own;
    ((float4*)ap)[0] = agg0;
    ((float4*)ap)[1] = agg1;
}

// ---------------------------------------------------------------------------
__global__ __launch_bounds__(256) void k_out(
    const float* __restrict__ out1_w, const float* __restrict__ out1_b,
    const float* __restrict__ out2_w, const float* __restrict__ out2_b,
    const int* __restrict__ batch, float* __restrict__ out)
{
    __shared__ float W1[128 * 64];
    __shared__ float w2s[64];
    __shared__ float xs[8][128];

    int tid = threadIdx.x;
    for (int i = tid; i < 128 * 64; i += 256) W1[i] = out1_w[i];
    if (tid < 64) w2s[tid] = out2_w[tid];
    __syncthreads();

    int warp = tid >> 5, lane = tid & 31;
    float ob0 = out1_b[lane], ob1 = out1_b[lane + 32];
    float b2v = out2_b[0];

    for (int row = blockIdx.x * 8 + warp; row < NATOMS; row += gridDim.x * 8) {
        ((float4*)xs[warp])[lane] = ((const float4*)(g_h + (long)row * 128))[lane];
        __syncwarp();
        float a0 = ob0, a1 = ob1;
        #pragma unroll 8
        for (int k = 0; k < 128; k++) {
            float xv = xs[warp][k];
            a0 += xv * W1[k * 64 + lane];
            a1 += xv * W1[k * 64 + lane + 32];
        }
        float v = sspf(a0) * w2s[lane] + sspf(a1) * w2s[lane + 32];
        #pragma unroll
        for (int off = 16; off; off >>= 1) v += __shfl_down_sync(0xffffffffu, v, off);
        if (lane == 0) atomicAdd(&out[batch[row]], v + b2v);
        __syncwarp();
    }
}

// ---------------------------------------------------------------------------
extern "C" void kernel_launch(void* const* d_in, const int* in_sizes, int n_in,
                              void* d_out, int out_size)
{
    const int*   z       = (const int*)  d_in[0];
    const float* pos     = (const float*)d_in[1];
    const int*   batch   = (const int*)  d_in[2];
    const int*   ei      = (const int*)  d_in[3];
    const float* emb     = (const float*)d_in[4];
    const float* mlp_w1  = (const float*)d_in[5];
    const float* mlp_b1  = (const float*)d_in[6];
    const float* mlp_w2  = (const float*)d_in[7];
    const float* mlp_b2  = (const float*)d_in[8];
    const float* cf1_w   = (const float*)d_in[9];
    const float* cf2_w   = (const float*)d_in[10];
    const float* cf2_b   = (const float*)d_in[11];
    const float* lin_w   = (const float*)d_in[12];
    const float* lin_b   = (const float*)d_in[13];
    const float* out1_w  = (const float*)d_in[14];
    const float* out1_b  = (const float*)d_in[15];
    const float* out2_w  = (const float*)d_in[16];
    const float* out2_b  = (const float*)d_in[17];

    int E = in_sizes[3] / 2;
    const int* src = ei;
    const int* dst = ei + E;

    cudaFuncSetAttribute(k_build, cudaFuncAttributeMaxDynamicSharedMemorySize, BLD_SMEM);
    cudaFuncSetAttribute(k_edge_tab, cudaFuncAttributeMaxDynamicSharedMemorySize, ETAB_SMEM);
    cudaFuncSetAttribute(k_n1e, cudaFuncAttributeMaxDynamicSharedMemorySize, N1_SMEM);
    cudaFuncSetAttribute(k_n2x, cudaFuncAttributeMaxDynamicSharedMemorySize, N2_SMEM);

    float *ph, *phx, *pagg, *ptab;
    cudaGetSymbolAddress((void**)&ph,   g_h);
    cudaGetSymbolAddress((void**)&phx,  g_hx);
    cudaGetSymbolAddress((void**)&pagg, g_agg);
    cudaGetSymbolAddress((void**)&ptab, g_wtab);

    float* out = (float*)d_out;

    k_prep<<<NMOL, 128>>>(src, dst, E);
    k_build<<<LINT * (TAB_N / 128) * 2, 512, BLD_SMEM>>>(mlp_w1, mlp_b1, mlp_w2, mlp_b2);
    k_n1e<<<128, 512, N1_SMEM>>>(z, emb, cf1_w, ph, phx);

    for (int l = 0; l < LINT; l++) {
        k_edge_tab<<<NMOL * 2, 256, ETAB_SMEM>>>(pos, ptab + (long)l * (TAB_N + 1) * HDIM);
        const float* cf1n = (l + 1 < LINT) ? (cf1_w + (long)(l + 1) * HDIM * HDIM) : nullptr;
        k_n2x<<<128, 512, N2_SMEM>>>(
            pagg, cf2_w + (long)l*HDIM*HDIM, cf2_b + (long)l*HDIM,
            lin_w + (long)l*HDIM*HDIM, lin_b + (long)l*HDIM, ph,
            cf1n, phx, out);
    }

    k_out<<<256, 256>>>(out1_w, out1_b, out2_w, out2_b, batch, out);
}

// round 13
// speedup vs baseline: 4.9417x; 1.0905x over previous
#include <cuda_runtime.h>
#include <cuda_bf16.h>
#include <math.h>
#include <stdint.h>

#define NATOMS 16384
#define NMOL   512
#define APM    32
#define HDIM   128
#define GDIM   50
#define LINT   3
#define CUTOFF 6.0f
#define TAB_N  2048
#define TILES  8
#define TS     64

// Scratch (allocation-free)
__device__ float g_h  [NATOMS * HDIM];
__device__ float g_hx [NATOMS * HDIM];
__device__ float g_agg[NATOMS * HDIM];
__device__ int   g_ucnt[NMOL];
__device__ unsigned g_upak[NMOL * 512];
__device__ int   g_ioff[NMOL * TILES * 33];
__device__ int   g_joff[NMOL * TILES * 33];
__device__ int   g_jperm[NMOL * 512];
__device__ float g_wtab[LINT * (TAB_N + 1) * HDIM];

__device__ __forceinline__ float sspf(float x) {
    const float LN2 = 0.6931471805599453f;
    if (x > 20.f) return x - LN2;
    return __logf(1.f + __expf(x)) - LN2;
}
__device__ __forceinline__ void split2(float v0, float v1, uint32_t& hi, uint32_t& lo) {
    __nv_bfloat16 h0 = __float2bfloat16(v0), h1 = __float2bfloat16(v1);
    __nv_bfloat16 l0 = __float2bfloat16(v0 - __bfloat162float(h0));
    __nv_bfloat16 l1 = __float2bfloat16(v1 - __bfloat162float(h1));
    hi = (uint32_t)__bfloat16_as_ushort(h0) | ((uint32_t)__bfloat16_as_ushort(h1) << 16);
    lo = (uint32_t)__bfloat16_as_ushort(l0) | ((uint32_t)__bfloat16_as_ushort(l1) << 16);
}
__device__ __forceinline__ void mma16816(float* d,
    uint32_t a0, uint32_t a1, uint32_t a2, uint32_t a3, uint32_t b0, uint32_t b1) {
    asm volatile(
        "mma.sync.aligned.m16n8k16.row.col.f32.bf16.bf16.f32 "
        "{%0,%1,%2,%3}, {%4,%5,%6,%7}, {%8,%9}, {%0,%1,%2,%3};"
        : "+f"(d[0]), "+f"(d[1]), "+f"(d[2]), "+f"(d[3])
        : "r"(a0), "r"(a1), "r"(a2), "r"(a3), "r"(b0), "r"(b1));
}
__device__ __forceinline__ void eaf(float d, float gofs, float step, float coeff,
                                    uint32_t& hi, uint32_t& lo) {
    float u0 = d - gofs, u1 = d - gofs - step;
    float e0 = __expf(coeff * u0 * u0);
    float e1 = __expf(coeff * u1 * u1);
    split2(e0, e1, hi, lo);
}

// ---------------------------------------------------------------------------
// Prepass with fused moff (unchanged)
// ---------------------------------------------------------------------------
__global__ __launch_bounds__(128) void k_prep(const int* __restrict__ src,
                                              const int* __restrict__ dst, int E) {
    __shared__ unsigned spak[TS];
    __shared__ int scnt2[33];
    __shared__ int snu;
    __shared__ int sbounds[2];
    int m = blockIdx.x;
    int tid = threadIdx.x, lane = tid & 31, wid = tid >> 5;

    if (tid < 2) {
        int target = (m + tid) * APM;
        int lo = 0, hi = E;
        while (lo < hi) { int mid = (lo + hi) >> 1; if (src[mid] < target) lo = mid + 1; else hi = mid; }
        sbounds[tid] = lo;
    }
    __syncthreads();
    int e0 = sbounds[0], e1 = sbounds[1];

    if (wid == 0) {
        int cnt = 0;
        for (int base = e0; base < e1; base += 32) {
            int e = base + lane;
            bool p = false; unsigned pk = 0;
            if (e < e1) {
                int s = src[e] - m * APM, d2 = dst[e] - m * APM;
                if (d2 > s) { p = true; pk = (unsigned)((s << 8) | d2); }
            }
            unsigned msk = __ballot_sync(0xffffffffu, p);
            if (p) g_upak[m * 512 + cnt + __popc(msk & ((1u << lane) - 1))] = pk;
            cnt += __popc(msk);
        }
        if (lane == 0) { g_ucnt[m] = cnt; snu = cnt; }
    }
    __syncthreads();
    int nu = snu;
    int nt = (nu + TS - 1) / TS;

    for (int t = 0; t < nt; t++) {
        int nr = nu - t * TS; if (nr > TS) nr = TS;
        if (tid < TS) spak[tid] = (tid < nr) ? g_upak[m * 512 + t * TS + tid] : 0xffffffffu;
        __syncthreads();
        if (wid == 0) {
            int a = lane, c = 0;
            for (int r = 0; r < nr; r++) c += ((int)(spak[r] >> 8) < a) ? 1 : 0;
            g_ioff[(m * TILES + t) * 33 + a] = c;
            if (lane == 0) g_ioff[(m * TILES + t) * 33 + 32] = nr;
        }
        if (wid == 1) {
            int a = lane, c = 0;
            for (int r = 0; r < nr; r++) c += ((int)(spak[r] & 255) == a) ? 1 : 0;
            int x = c;
            #pragma unroll
            for (int o = 1; o < 32; o <<= 1) {
                int y = __shfl_up_sync(0xffffffffu, x, o);
                if (lane >= o) x += y;
            }
            int excl = x - c;
            g_joff[(m * TILES + t) * 33 + a] = excl;
            scnt2[a] = excl;
            if (lane == 31) g_joff[(m * TILES + t) * 33 + 32] = excl + c;
        }
        __syncthreads();
        if (tid == 0) {
            for (int r = 0; r < nr; r++) {
                int j = (int)(spak[r] & 255);
                g_jperm[m * 512 + t * TS + scnt2[j]] = r;
                scnt2[j]++;
            }
        }
        __syncthreads();
    }
}

// ---------------------------------------------------------------------------
// Fused embed + node GEMM (unchanged)
// ---------------------------------------------------------------------------
#define N1_SMEM (128 * 132 * 4)

__global__ __launch_bounds__(512, 1) void k_n1e(
    const int* __restrict__ z, const float* __restrict__ emb,
    const float* __restrict__ W, float* __restrict__ h, float* __restrict__ hx)
{
    extern __shared__ uint32_t smu[];
    uint32_t* Bu = smu;
    const int tid = threadIdx.x, wid = tid >> 5, lane = tid & 31;
    const int half = wid >> 3, w8 = wid & 7;
    const int qr = lane >> 2, qc = lane & 3;

    for (int i = tid; i < 128 * 64; i += 512) {
        int kp = i >> 7, n = i & 127;
        uint32_t hh, ll;
        split2(W[(2 * kp) * 128 + n], W[(2 * kp + 1) * 128 + n], hh, ll);
        Bu[n * 132 + kp] = hh;
        Bu[n * 132 + 64 + kp] = ll;
    }
    __syncthreads();

    const int r0 = w8 * 16 + qr;
    const long base = (long)blockIdx.x * 128;
    const long za = (long)z[base + r0], zb = (long)z[base + r0 + 8];

    float acc[8][4];
    #pragma unroll
    for (int nb = 0; nb < 8; nb++) { acc[nb][0]=0.f; acc[nb][1]=0.f; acc[nb][2]=0.f; acc[nb][3]=0.f; }

    #pragma unroll
    for (int ks = 0; ks < 8; ks++) {
        const float* xr0 = emb + za * 128 + ks * 16 + 2 * qc;
        const float* xr1 = emb + zb * 128 + ks * 16 + 2 * qc;
        float2 v00 = *(const float2*)xr0;
        float2 v01 = *(const float2*)(xr0 + 8);
        float2 v10 = *(const float2*)xr1;
        float2 v11 = *(const float2*)(xr1 + 8);
        if (half == 0) {
            *(float2*)(h + (base + r0) * 128 + ks * 16 + 2 * qc)         = v00;
            *(float2*)(h + (base + r0) * 128 + ks * 16 + 8 + 2 * qc)     = v01;
            *(float2*)(h + (base + r0 + 8) * 128 + ks * 16 + 2 * qc)     = v10;
            *(float2*)(h + (base + r0 + 8) * 128 + ks * 16 + 8 + 2 * qc) = v11;
        }
        uint32_t aH0,aH1,aH2,aH3,aL0,aL1,aL2,aL3;
        split2(v00.x, v00.y, aH0, aL0);
        split2(v10.x, v10.y, aH1, aL1);
        split2(v01.x, v01.y, aH2, aL2);
        split2(v11.x, v11.y, aH3, aL3);
        #pragma unroll
        for (int nb = 0; nb < 8; nb++) {
            int noff = ((half * 8 + nb) * 8 + qr) * 132 + ks * 8 + qc;
            uint32_t bh0 = Bu[noff], bh1 = Bu[noff + 4];
            mma16816(acc[nb], aH0, aH1, aH2, aH3, bh0, bh1);
            mma16816(acc[nb], aL0, aL1, aL2, aL3, bh0, bh1);
            uint32_t bl0 = Bu[noff + 64], bl1 = Bu[noff + 68];
            mma16816(acc[nb], aH0, aH1, aH2, aH3, bl0, bl1);
        }
    }

    #pragma unroll
    for (int nb = 0; nb < 8; nb++) {
        int c = (half * 8 + nb) * 8 + 2 * qc;
        *(float2*)(hx + (base + r0) * 128 + c)     = make_float2(acc[nb][0], acc[nb][1]);
        *(float2*)(hx + (base + r0 + 8) * 128 + c) = make_float2(acc[nb][2], acc[nb][3]);
    }
}

// ---------------------------------------------------------------------------
// Fused node chain; on the LAST layer also computes the output head:
//   o1 = ssp(h_new @ out1_w + out1_b); atom = o1 @ out2_w + out2_b;
//   out[mol] = sum over its 32 atoms  (CTA = 128 atoms = 4 whole molecules)
// ---------------------------------------------------------------------------
#define N2_OB1 0
#define N2_OB2 16896
#define N2_OT1 33792
#define N2_OS2 50688
#define N2_OSL 50816
#define N2_OSA 50944
#define N2_SMEM ((51072) * 4)

__global__ __launch_bounds__(512, 1) void k_n2x(
    const float* __restrict__ agg,
    const float* __restrict__ W2, const float* __restrict__ b2,
    const float* __restrict__ Wl, const float* __restrict__ lb,
    float* __restrict__ h,
    const float* __restrict__ cf1n, float* __restrict__ hx,
    const float* __restrict__ o1w, const float* __restrict__ o1b,
    const float* __restrict__ o2w, const float* __restrict__ o2b,
    float* __restrict__ out)
{
    extern __shared__ uint32_t smu[];
    uint32_t* Bu1 = smu + N2_OB1;
    uint32_t* Bu2 = smu + N2_OB2;
    uint32_t* T1  = smu + N2_OT1;
    float* sb2 = (float*)(smu + N2_OS2);
    float* slb = (float*)(smu + N2_OSL);
    float* satom = (float*)(smu + N2_OSA);

    const int tid = threadIdx.x, wid = tid >> 5, lane = tid & 31;
    const int half = wid >> 3, w8 = wid & 7;
    const int qr = lane >> 2, qc = lane & 3;

    for (int i = tid; i < 128 * 64; i += 512) {
        int kp = i >> 7, n = i & 127;
        uint32_t hh, ll;
        split2(W2[(2 * kp) * 128 + n], W2[(2 * kp + 1) * 128 + n], hh, ll);
        Bu1[n * 132 + kp] = hh; Bu1[n * 132 + 64 + kp] = ll;
        split2(Wl[(2 * kp) * 128 + n], Wl[(2 * kp + 1) * 128 + n], hh, ll);
        Bu2[n * 132 + kp] = hh; Bu2[n * 132 + 64 + kp] = ll;
    }
    if (tid < 128) { sb2[tid] = b2[tid]; slb[tid] = lb[tid]; }
    __syncthreads();

    const int r0 = w8 * 16 + qr;
    const long base = (long)blockIdx.x * 128;

    // GEMM1: agg @ W2 -> ssp -> T1
    {
        float acc[8][4];
        #pragma unroll
        for (int nb = 0; nb < 8; nb++) { acc[nb][0]=0.f; acc[nb][1]=0.f; acc[nb][2]=0.f; acc[nb][3]=0.f; }
        #pragma unroll
        for (int ks = 0; ks < 8; ks++) {
            const float* xr = agg + (base + r0) * 128 + ks * 16 + 2 * qc;
            float2 v00 = *(const float2*)xr;
            float2 v01 = *(const float2*)(xr + 8);
            float2 v10 = *(const float2*)(xr + 8 * 128);
            float2 v11 = *(const float2*)(xr + 8 * 128 + 8);
            uint32_t aH0,aH1,aH2,aH3,aL0,aL1,aL2,aL3;
            split2(v00.x, v00.y, aH0, aL0);
            split2(v10.x, v10.y, aH1, aL1);
            split2(v01.x, v01.y, aH2, aL2);
            split2(v11.x, v11.y, aH3, aL3);
            #pragma unroll
            for (int nb = 0; nb < 8; nb++) {
                int noff = ((half * 8 + nb) * 8 + qr) * 132 + ks * 8 + qc;
                uint32_t bh0 = Bu1[noff], bh1 = Bu1[noff + 4];
                mma16816(acc[nb], aH0, aH1, aH2, aH3, bh0, bh1);
                mma16816(acc[nb], aL0, aL1, aL2, aL3, bh0, bh1);
                uint32_t bl0 = Bu1[noff + 64], bl1 = Bu1[noff + 68];
                mma16816(acc[nb], aH0, aH1, aH2, aH3, bl0, bl1);
            }
        }
        #pragma unroll
        for (int nb = 0; nb < 8; nb++) {
            int c = (half * 8 + nb) * 8 + 2 * qc;
            int kp = (c >> 1);
            float bx = sb2[c], by = sb2[c + 1];
            uint32_t hh, ll;
            split2(sspf(acc[nb][0] + bx), sspf(acc[nb][1] + by), hh, ll);
            T1[r0 * 132 + kp] = hh; T1[r0 * 132 + 64 + kp] = ll;
            split2(sspf(acc[nb][2] + bx), sspf(acc[nb][3] + by), hh, ll);
            T1[(r0 + 8) * 132 + kp] = hh; T1[(r0 + 8) * 132 + 64 + kp] = ll;
        }
    }
    __syncthreads();

    if (cf1n) {
        for (int i = tid; i < 128 * 64; i += 512) {
            int kp = i >> 7, n = i & 127;
            uint32_t hh, ll;
            split2(cf1n[(2 * kp) * 128 + n], cf1n[(2 * kp + 1) * 128 + n], hh, ll);
            Bu1[n * 132 + kp] = hh; Bu1[n * 132 + 64 + kp] = ll;
        }
    }

    // GEMM2: T1 @ Wl, residual -> h; re-split h_new into T1 (always)
    {
        float acc[8][4];
        #pragma unroll
        for (int nb = 0; nb < 8; nb++) { acc[nb][0]=0.f; acc[nb][1]=0.f; acc[nb][2]=0.f; acc[nb][3]=0.f; }
        #pragma unroll
        for (int ks = 0; ks < 8; ks++) {
            int xo0 = r0 * 132 + ks * 8 + qc;
            int xo1 = (r0 + 8) * 132 + ks * 8 + qc;
            uint32_t aH0 = T1[xo0],      aH1 = T1[xo1];
            uint32_t aH2 = T1[xo0 + 4],  aH3 = T1[xo1 + 4];
            uint32_t aL0 = T1[xo0 + 64], aL1 = T1[xo1 + 64];
            uint32_t aL2 = T1[xo0 + 68], aL3 = T1[xo1 + 68];
            #pragma unroll
            for (int nb = 0; nb < 8; nb++) {
                int noff = ((half * 8 + nb) * 8 + qr) * 132 + ks * 8 + qc;
                uint32_t bh0 = Bu2[noff], bh1 = Bu2[noff + 4];
                mma16816(acc[nb], aH0, aH1, aH2, aH3, bh0, bh1);
                mma16816(acc[nb], aL0, aL1, aL2, aL3, bh0, bh1);
                uint32_t bl0 = Bu2[noff + 64], bl1 = Bu2[noff + 68];
                mma16816(acc[nb], aH0, aH1, aH2, aH3, bl0, bl1);
            }
        }
        #pragma unroll
        for (int nb = 0; nb < 8; nb++) {
            int c = (half * 8 + nb) * 8 + 2 * qc;
            float bx = slb[c], by = slb[c + 1];
            float* y0 = h + (base + r0) * 128 + c;
            float* y1 = h + (base + r0 + 8) * 128 + c;
            float2 p0 = *(float2*)y0, p1 = *(float2*)y1;
            float v0 = p0.x + acc[nb][0] + bx, v1 = p0.y + acc[nb][1] + by;
            float v2 = p1.x + acc[nb][2] + bx, v3 = p1.y + acc[nb][3] + by;
            *(float2*)y0 = make_float2(v0, v1);
            *(float2*)y1 = make_float2(v2, v3);
            int kp = c >> 1;
            uint32_t hh, ll;
            split2(v0, v1, hh, ll);
            T1[r0 * 132 + kp] = hh; T1[r0 * 132 + 64 + kp] = ll;
            split2(v2, v3, hh, ll);
            T1[(r0 + 8) * 132 + kp] = hh; T1[(r0 + 8) * 132 + 64 + kp] = ll;
        }
    }
    __syncthreads();   // T1 (h_new split) complete for all rows

    if (cf1n) {
        // GEMM3: hx = h_new @ cf1n
        float acc[8][4];
        #pragma unroll
        for (int nb = 0; nb < 8; nb++) { acc[nb][0]=0.f; acc[nb][1]=0.f; acc[nb][2]=0.f; acc[nb][3]=0.f; }
        #pragma unroll
        for (int ks = 0; ks < 8; ks++) {
            int xo0 = r0 * 132 + ks * 8 + qc;
            int xo1 = (r0 + 8) * 132 + ks * 8 + qc;
            uint32_t aH0 = T1[xo0],      aH1 = T1[xo1];
            uint32_t aH2 = T1[xo0 + 4],  aH3 = T1[xo1 + 4];
            uint32_t aL0 = T1[xo0 + 64], aL1 = T1[xo1 + 64];
            uint32_t aL2 = T1[xo0 + 68], aL3 = T1[xo1 + 68];
            #pragma unroll
            for (int nb = 0; nb < 8; nb++) {
                int noff = ((half * 8 + nb) * 8 + qr) * 132 + ks * 8 + qc;
                uint32_t bh0 = Bu1[noff], bh1 = Bu1[noff + 4];
                mma16816(acc[nb], aH0, aH1, aH2, aH3, bh0, bh1);
                mma16816(acc[nb], aL0, aL1, aL2, aL3, bh0, bh1);
                uint32_t bl0 = Bu1[noff + 64], bl1 = Bu1[noff + 68];
                mma16816(acc[nb], aH0, aH1, aH2, aH3, bl0, bl1);
            }
        }
        #pragma unroll
        for (int nb = 0; nb < 8; nb++) {
            int c = (half * 8 + nb) * 8 + 2 * qc;
            *(float2*)(hx + (base + r0) * 128 + c)     = make_float2(acc[nb][0], acc[nb][1]);
            *(float2*)(hx + (base + r0 + 8) * 128 + c) = make_float2(acc[nb][2], acc[nb][3]);
        }
        return;
    }

    // ---- Fused output head (last layer) ----
    // Stage out1_w [128,64] split into Bu1; out1_b -> sb2, out2_w -> slb.
    for (int i = tid; i < 64 * 64; i += 512) {
        int kp = i >> 6, n = i & 63;
        uint32_t hh, ll;
        split2(o1w[(2 * kp) * 64 + n], o1w[(2 * kp + 1) * 64 + n], hh, ll);
        Bu1[n * 132 + kp] = hh; Bu1[n * 132 + 64 + kp] = ll;
    }
    if (tid < 64) { sb2[tid] = o1b[tid]; slb[tid] = o2w[tid]; }
    if (tid < 128) satom[tid] = 0.f;
    __syncthreads();

    {
        float acc[4][4];
        #pragma unroll
        for (int nb = 0; nb < 4; nb++) { acc[nb][0]=0.f; acc[nb][1]=0.f; acc[nb][2]=0.f; acc[nb][3]=0.f; }
        #pragma unroll
        for (int ks = 0; ks < 8; ks++) {
            int xo0 = r0 * 132 + ks * 8 + qc;
            int xo1 = (r0 + 8) * 132 + ks * 8 + qc;
            uint32_t aH0 = T1[xo0],      aH1 = T1[xo1];
            uint32_t aH2 = T1[xo0 + 4],  aH3 = T1[xo1 + 4];
            uint32_t aL0 = T1[xo0 + 64], aL1 = T1[xo1 + 64];
            uint32_t aL2 = T1[xo0 + 68], aL3 = T1[xo1 + 68];
            #pragma unroll
            for (int nb = 0; nb < 4; nb++) {
                int cb2 = half * 4 + nb;           // col-blocks 0..7 over 64 cols
                int noff = (cb2 * 8 + qr) * 132 + ks * 8 + qc;
                uint32_t bh0 = Bu1[noff], bh1 = Bu1[noff + 4];
                mma16816(acc[nb], aH0, aH1, aH2, aH3, bh0, bh1);
                mma16816(acc[nb], aL0, aL1, aL2, aL3, bh0, bh1);
                uint32_t bl0 = Bu1[noff + 64], bl1 = Bu1[noff + 68];
                mma16816(acc[nb], aH0, aH1, aH2, aH3, bl0, bl1);
            }
        }
        float P0 = 0.f, P1 = 0.f;
        #pragma unroll
        for (int nb = 0; nb < 4; nb++) {
            int c = (half * 4 + nb) * 8 + 2 * qc;
            float bx = sb2[c], by = sb2[c + 1];
            float wx = slb[c], wy = slb[c + 1];
            P0 += sspf(acc[nb][0] + bx) * wx + sspf(acc[nb][1] + by) * wy;
            P1 += sspf(acc[nb][2] + bx) * wx + sspf(acc[nb][3] + by) * wy;
        }
        atomicAdd(&satom[r0], P0);
        atomicAdd(&satom[r0 + 8], P1);
    }
    __syncthreads();

    if (tid < 4) {
        float s = 0.f;
        #pragma unroll
        for (int a = 0; a < 32; a++) s += satom[tid * 32 + a];
        out[blockIdx.x * 4 + tid] = s + 32.f * o2b[0];
    }
}

// ---------------------------------------------------------------------------
// Table builder, N-split (unchanged)
// ---------------------------------------------------------------------------
#define BLD_SMEM (34304 * 4)

__global__ __launch_bounds__(512, 1)
void k_build(const float* __restrict__ w1all, const float* __restrict__ b1all,
             const float* __restrict__ w2all, const float* __restrict__ b2all)
{
    extern __shared__ uint32_t smu[];
    uint32_t* B1u = smu;
    uint32_t* B2u = smu + 8704;
    uint32_t* T1  = smu + 17152;
    float* sb1 = (float*)(smu + 34048);
    float* sb2 = (float*)(smu + 34176);

    const int tpl = TAB_N / 128;
    const int ch = blockIdx.x & 1;
    const int t  = (blockIdx.x >> 1) % tpl;
    const int l  = (blockIdx.x >> 1) / tpl;
    const float* w1 = w1all + (long)l * GDIM * HDIM;
    const float* b1 = b1all + (long)l * HDIM;
    const float* w2 = w2all + (long)l * HDIM * HDIM;
    const float* b2 = b2all + (long)l * HDIM;

    const int tid = threadIdx.x, wid = tid >> 5, lane = tid & 31;
    const int half = wid >> 3, w8 = wid & 7;
    const int qr = lane >> 2, qc = lane & 3;

    for (int i = tid; i < 128 * 32; i += 512) {
        int kp = i >> 7, n = i & 127, k = 2 * kp;
        float v0 = (k < GDIM)     ? w1[k * 128 + n]       : 0.f;
        float v1 = (k + 1 < GDIM) ? w1[(k + 1) * 128 + n] : 0.f;
        uint32_t h, lv; split2(v0, v1, h, lv);
        B1u[n * 68 + kp] = h;
        B1u[n * 68 + 32 + kp] = lv;
    }
    for (int i = tid; i < 64 * 64; i += 512) {
        int kp = i >> 6, nl = i & 63;
        int n = ch * 64 + nl;
        uint32_t h, lv;
        split2(w2[(2 * kp) * 128 + n], w2[(2 * kp + 1) * 128 + n], h, lv);
        B2u[nl * 132 + kp] = h;
        B2u[nl * 132 + 64 + kp] = lv;
    }
    if (tid < 128) { sb1[tid] = b1[tid]; sb2[tid] = b2[tid]; }
    __syncthreads();

    const float step  = CUTOFF / (GDIM - 1);
    const float coeff = -0.5f / (step * step);
    const float PIOC  = 3.14159265358979f / CUTOFF;
    const float DELTA = CUTOFF / (float)TAB_N;
    const int r0 = w8 * 16 + qr;

    float dv0 = (float)(t * 128 + r0) * DELTA;
    float dv1 = (float)(t * 128 + r0 + 8) * DELTA;

    uint32_t aH[4][4], aL[4][4];
    #pragma unroll
    for (int ks = 0; ks < 4; ks++) {
        float g0 = (float)(ks * 16 + 2 * qc) * step;
        eaf(dv0, g0,            step, coeff, aH[ks][0], aL[ks][0]);
        eaf(dv1, g0,            step, coeff, aH[ks][1], aL[ks][1]);
        eaf(dv0, g0 + 8.f*step, step, coeff, aH[ks][2], aL[ks][2]);
        eaf(dv1, g0 + 8.f*step, step, coeff, aH[ks][3], aL[ks][3]);
    }

    #pragma unroll
    for (int nb = 0; nb < 8; nb++) {
        float acc[4] = {0.f, 0.f, 0.f, 0.f};
        #pragma unroll
        for (int ks = 0; ks < 4; ks++) {
            int noff = ((half * 8 + nb) * 8 + qr) * 68 + ks * 8 + qc;
            uint32_t bh0 = B1u[noff], bh1 = B1u[noff + 4];
            mma16816(acc, aH[ks][0], aH[ks][1], aH[ks][2], aH[ks][3], bh0, bh1);
            mma16816(acc, aL[ks][0], aL[ks][1], aL[ks][2], aL[ks][3], bh0, bh1);
            uint32_t bl0 = B1u[noff + 32], bl1 = B1u[noff + 36];
            mma16816(acc, aH[ks][0], aH[ks][1], aH[ks][2], aH[ks][3], bl0, bl1);
        }
        int c = (half * 8 + nb) * 8 + 2 * qc;
        int kp = c >> 1;
        float bx = sb1[c], by = sb1[c + 1];
        uint32_t hh, ll;
        split2(sspf(acc[0] + bx), sspf(acc[1] + by), hh, ll);
        T1[r0 * 132 + kp] = hh; T1[r0 * 132 + 64 + kp] = ll;
        split2(sspf(acc[2] + bx), sspf(acc[3] + by), hh, ll);
        T1[(r0 + 8) * 132 + kp] = hh; T1[(r0 + 8) * 132 + 64 + kp] = ll;
    }
    __syncthreads();

    float acc2[4][4];
    #pragma unroll
    for (int nb = 0; nb < 4; nb++) { acc2[nb][0]=0.f; acc2[nb][1]=0.f; acc2[nb][2]=0.f; acc2[nb][3]=0.f; }
    #pragma unroll
    for (int ks = 0; ks < 8; ks++) {
        int xo0 = r0 * 132 + ks * 8 + qc;
        int xo1 = (r0 + 8) * 132 + ks * 8 + qc;
        uint32_t aH0 = T1[xo0],      aH1 = T1[xo1];
        uint32_t aH2 = T1[xo0 + 4],  aH3 = T1[xo1 + 4];
        uint32_t aL0 = T1[xo0 + 64], aL1 = T1[xo1 + 64];
        uint32_t aL2 = T1[xo0 + 68], aL3 = T1[xo1 + 68];
        #pragma unroll
        for (int nb = 0; nb < 4; nb++) {
            int cb2 = half * 4 + nb;
            int noff = (cb2 * 8 + qr) * 132 + ks * 8 + qc;
            uint32_t bh0 = B2u[noff], bh1 = B2u[noff + 4];
            mma16816(acc2[nb], aH0, aH1, aH2, aH3, bh0, bh1);
            mma16816(acc2[nb], aL0, aL1, aL2, aL3, bh0, bh1);
            uint32_t bl0 = B2u[noff + 64], bl1 = B2u[noff + 68];
            mma16816(acc2[nb], aH0, aH1, aH2, aH3, bl0, bl1);
        }
    }

    float cc0 = 0.5f * (cosf(dv0 * PIOC) + 1.f);
    float cc1 = 0.5f * (cosf(dv1 * PIOC) + 1.f);
    float* trow = g_wtab + ((long)l * (TAB_N + 1) + t * 128 + r0) * 128;
    #pragma unroll
    for (int nb = 0; nb < 4; nb++) {
        int c = ch * 64 + (half * 4 + nb) * 8 + 2 * qc;
        float bx = sb2[c], by = sb2[c + 1];
        *(float2*)(trow + c) =
            make_float2((acc2[nb][0] + bx) * cc0, (acc2[nb][1] + by) * cc0);
        *(float2*)(trow + 8 * 128 + c) =
            make_float2((acc2[nb][2] + bx) * cc1, (acc2[nb][3] + by) * cc1);
    }
    if (t == 0 && ch == 0 && tid < 128)
        g_wtab[((long)l * (TAB_N + 1) + TAB_N) * 128 + tid] = 0.f;
}

// ---------------------------------------------------------------------------
// Column-split table-lookup edge kernel (byte-exact R11 version, known good)
// ---------------------------------------------------------------------------
#define E2_HX 0
#define E2_SB 2176
#define E2_SD 6528
#define E2_IL 6592
#define E2_JL 6656
#define E2_JP 6720
#define E2_IO 6784
#define E2_JO 6817
#define E2_PS 6850
#define E2_W  6946
#define ETAB_SMEM (E2_W * 4)

__global__ __launch_bounds__(256, 6)
void k_edge_tab(const float* __restrict__ pos, const float* __restrict__ wtab)
{
    extern __shared__ float sm[];
    float* hxs  = sm + E2_HX;
    float* sbuf = sm + E2_SB;
    float* sd   = sm + E2_SD;
    int*   sil  = (int*)(sm + E2_IL);
    int*   sjl  = (int*)(sm + E2_JL);
    int*   sjp  = (int*)(sm + E2_JP);
    int*   siof = (int*)(sm + E2_IO);
    int*   sjof = (int*)(sm + E2_JO);
    float* ps   = sm + E2_PS;

    const int tid = threadIdx.x, wid = tid >> 5, lane = tid & 31;
    const int m = blockIdx.x >> 1, ch = blockIdx.x & 1;
    const int cb = ch * 64;
    const int a_own = tid >> 3, c_own = (tid & 7) * 8;
    const float SCALE = (float)TAB_N / CUTOFF;

    int nu = g_ucnt[m];
    int nt = (nu + TS - 1) / TS;

    for (int i = tid; i < APM * 64; i += 256) {
        int a = i >> 6, c = i & 63;
        hxs[a * 68 + c] = g_hx[(long)(m * APM + a) * 128 + cb + c];
    }
    if (tid < 96) ps[tid] = pos[m * 96 + tid];
    float4 agg0 = make_float4(0,0,0,0), agg1 = agg0;
    __syncthreads();

    for (int t = 0; t < nt; t++) {
        if (tid < TS) {
            int k = t * TS + tid;
            float d = 0.f; int il = 0, jl = 0;
            if (k < nu) {
                unsigned pk = g_upak[m * 512 + k];
                il = (int)(pk >> 8); jl = (int)(pk & 255);
                float dx = ps[3*il]   - ps[3*jl];
                float dy = ps[3*il+1] - ps[3*jl+1];
                float dz = ps[3*il+2] - ps[3*jl+2];
                d = sqrtf(dx*dx + dy*dy + dz*dz);
            }
            sd[tid] = d; sil[tid] = il; sjl[tid] = jl;
            sjp[tid] = g_jperm[m * 512 + t * TS + tid];
        }
        if (tid >= 64 && tid < 97)   siof[tid - 64]  = g_ioff[(m * TILES + t) * 33 + tid - 64];
        if (tid >= 128 && tid < 161) sjof[tid - 128] = g_joff[(m * TILES + t) * 33 + tid - 128];
        __syncthreads();

        #pragma unroll
        for (int it = 0; it < 4; it++) {
            int e = wid * 8 + it * 2 + (lane >> 4);
            int col4 = lane & 15;
            float d = sd[e];
            float tt = d * SCALE;
            int i0 = (int)tt;
            i0 = (i0 > TAB_N - 1) ? (TAB_N - 1) : i0;
            float f = tt - (float)i0;
            const float4* T0 = (const float4*)(wtab + (long)i0 * 128 + cb);
            float4 wa = T0[col4];
            float4 wb = T0[32 + col4];
            float4 wv;
            wv.x = wa.x + f * (wb.x - wa.x);
            wv.y = wa.y + f * (wb.y - wa.y);
            wv.z = wa.z + f * (wb.z - wa.z);
            wv.w = wa.w + f * (wb.w - wa.w);
            *(float4*)&sbuf[e * 68 + col4 * 4] = wv;
        }
        __syncthreads();

        for (int r = siof[a_own]; r < siof[a_own + 1]; r++) {
            const float4* wp = (const float4*)&sbuf[r * 68 + c_own];
            const float4* hp = (const float4*)&hxs[sjl[r] * 68 + c_own];
            float4 w0 = wp[0], w1v = wp[1];
            float4 h0 = hp[0], h1 = hp[1];
            agg0.x += w0.x*h0.x; agg0.y += w0.y*h0.y; agg0.z += w0.z*h0.z; agg0.w += w0.w*h0.w;
            agg1.x += w1v.x*h1.x; agg1.y += w1v.y*h1.y; agg1.z += w1v.z*h1.z; agg1.w += w1v.w*h1.w;
        }
        for (int kk = sjof[a_own]; kk < sjof[a_own + 1]; kk++) {
            int r = sjp[kk];
            const float4* wp = (const float4*)&sbuf[r * 68 + c_own];
            const float4* hp = (const float4*)&hxs[sil[r] * 68 + c_own];
            float4 w0 = wp[0], w1v = wp[1];
            float4 h0 = hp[0], h1 = hp[1];
            agg0.x += w0.x*h0.x; agg0.y += w0.y*h0.y; agg0.z += w0.z*h0.z; agg0.w += w0.w*h0.w;
            agg1.x += w1v.x*h1.x; agg1.y += w1v.y*h1.y; agg1.z += w1v.z*h1.z; agg1.w += w1v.w*h1.w;
        }
        __syncthreads();
    }

    float* ap = g_agg + (long)(m * APM + a_own) * 128 + cb + c_own;
    ((float4*)ap)[0] = agg0;
    ((float4*)ap)[1] = agg1;
}

// ---------------------------------------------------------------------------
extern "C" void kernel_launch(void* const* d_in, const int* in_sizes, int n_in,
                              void* d_out, int out_size)
{
    const int*   z       = (const int*)  d_in[0];
    const float* pos     = (const float*)d_in[1];
    const int*   ei      = (const int*)  d_in[3];
    const float* emb     = (const float*)d_in[4];
    const float* mlp_w1  = (const float*)d_in[5];
    const float* mlp_b1  = (const float*)d_in[6];
    const float* mlp_w2  = (const float*)d_in[7];
    const float* mlp_b2  = (const float*)d_in[8];
    const float* cf1_w   = (const float*)d_in[9];
    const float* cf2_w   = (const float*)d_in[10];
    const float* cf2_b   = (const float*)d_in[11];
    const float* lin_w   = (const float*)d_in[12];
    const float* lin_b   = (const float*)d_in[13];
    const float* out1_w  = (const float*)d_in[14];
    const float* out1_b  = (const float*)d_in[15];
    const float* out2_w  = (const float*)d_in[16];
    const float* out2_b  = (const float*)d_in[17];

    int E = in_sizes[3] / 2;
    const int* src = ei;
    const int* dst = ei + E;

    cudaFuncSetAttribute(k_build, cudaFuncAttributeMaxDynamicSharedMemorySize, BLD_SMEM);
    cudaFuncSetAttribute(k_edge_tab, cudaFuncAttributeMaxDynamicSharedMemorySize, ETAB_SMEM);
    cudaFuncSetAttribute(k_n1e, cudaFuncAttributeMaxDynamicSharedMemorySize, N1_SMEM);
    cudaFuncSetAttribute(k_n2x, cudaFuncAttributeMaxDynamicSharedMemorySize, N2_SMEM);

    float *ph, *phx, *pagg, *ptab;
    cudaGetSymbolAddress((void**)&ph,   g_h);
    cudaGetSymbolAddress((void**)&phx,  g_hx);
    cudaGetSymbolAddress((void**)&pagg, g_agg);
    cudaGetSymbolAddress((void**)&ptab, g_wtab);

    float* out = (float*)d_out;

    k_prep<<<NMOL, 128>>>(src, dst, E);
    k_build<<<LINT * (TAB_N / 128) * 2, 512, BLD_SMEM>>>(mlp_w1, mlp_b1, mlp_w2, mlp_b2);
    k_n1e<<<128, 512, N1_SMEM>>>(z, emb, cf1_w, ph, phx);

    for (int l = 0; l < LINT; l++) {
        k_edge_tab<<<NMOL * 2, 256, ETAB_SMEM>>>(pos, ptab + (long)l * (TAB_N + 1) * HDIM);
        const float* cf1n = (l + 1 < LINT) ? (cf1_w + (long)(l + 1) * HDIM * HDIM) : nullptr;
        k_n2x<<<128, 512, N2_SMEM>>>(
            pagg, cf2_w + (long)l*HDIM*HDIM, cf2_b + (long)l*HDIM,
            lin_w + (long)l*HDIM*HDIM, lin_b + (long)l*HDIM, ph,
            cf1n, phx,
            out1_w, out1_b, out2_w, out2_b, out);
    }
}